// round 7
// baseline (speedup 1.0000x reference)
#include <cuda_runtime.h>
#include <cuda_bf16.h>
#include <math.h>
#include <stdint.h>

// ---------------------------------------------------------------------------
// Problem constants
// ---------------------------------------------------------------------------
static constexpr int B  = 16;
static constexpr int N  = 512;
static constexpr int D  = 512;
static constexpr int H  = 8;
static constexpr int HD = 64;
static constexpr int LW = 64;
static constexpr int NQ = 10000;
static constexpr int BN_ROWS  = B * N;    // 8192
static constexpr int BLW_ROWS = B * LW;   // 1024
static constexpr int DD = D * D;          // 262144 = 2^18

typedef __nv_bfloat16 bf16;
typedef __nv_bfloat162 bf162;

// ---------------------------------------------------------------------------
// Scratch (static device globals)
// ---------------------------------------------------------------------------
// f32
__device__ float g_M     [BN_ROWS * D];
__device__ float g_E     [BN_ROWS * D];
__device__ float g_T1    [BN_ROWS * D];
__device__ float g_T2    [BN_ROWS * D];
__device__ float g_Sbase [BN_ROWS * D];
__device__ float g_Slocal[BN_ROWS * D];
__device__ float g_Sglob [BN_ROWS * D];
__device__ float g_Ssum  [BN_ROWS * D];
__device__ float g_P32   [B * H * LW * LW];    // local probs scratch (f32)
// bf16
__device__ bf16 g_Mb  [BN_ROWS * D];
__device__ bf16 g_Eb  [BN_ROWS * D];
__device__ bf16 g_QK  [BN_ROWS * 1536];        // packed Q/K (and local QKV)
__device__ bf16 g_Vt  [B * H * HD * N];        // V transposed per (b,h): [e][j]
__device__ bf16 g_S16 [B * H * N * N];         // scores
__device__ bf16 g_P16 [B * H * N * N];         // probs
__device__ bf16 g_O16 [BN_ROWS * D];           // attention output (pre out-proj)
__device__ bf16 g_Sb16[BN_ROWS * D];
__device__ bf16 g_Sl16[BN_ROWS * D];
__device__ bf16 g_Ss16[BN_ROWS * D];
__device__ bf16 g_F16 [BN_ROWS * D];
__device__ bf16 g_T2b [BLW_ROWS * D];
__device__ bf16 g_Wb  [18 * DD];               // bf16 weights

// ---------------------------------------------------------------------------
// MMA helpers (bf16 m16n8k16)
// ---------------------------------------------------------------------------
__device__ __forceinline__ void cp_async16(uint32_t dst, const void* src) {
    asm volatile("cp.async.cg.shared.global [%0], [%1], 16;" :: "r"(dst), "l"(src));
}
__device__ __forceinline__ void cp_commit() {
    asm volatile("cp.async.commit_group;");
}
__device__ __forceinline__ void mma_bf16(float c[4], uint32_t a0, uint32_t a1,
                                         uint32_t a2, uint32_t a3,
                                         uint32_t b0, uint32_t b1) {
    asm volatile(
        "mma.sync.aligned.m16n8k16.row.col.f32.bf16.bf16.f32 "
        "{%0,%1,%2,%3}, {%4,%5,%6,%7}, {%8,%9}, {%0,%1,%2,%3};"
        : "+f"(c[0]), "+f"(c[1]), "+f"(c[2]), "+f"(c[3])
        : "r"(a0), "r"(a1), "r"(a2), "r"(a3), "r"(b0), "r"(b1));
}

// v2 GEMM smem geometry: rows of 64 bf16 (BK=64) = 32 u32 + 4 pad
static constexpr int L2STR = 36;                     // u32 per row
static constexpr int L2_STAGE_U32 = 256 * L2STR;     // A(128)+W(128) rows = 9216
static constexpr int L2_SMEM_BYTES = 3 * L2_STAGE_U32 * 4;   // 110592

// scores/pv geometry (BK=32): rows of 32 bf16 = 16 u32 + 4 pad
static constexpr int LSTR = 20;
static constexpr int L_STAGE_U32 = 256 * LSTR;
static constexpr int PV_STAGE_U32 = 192 * LSTR;

// ---------------------------------------------------------------------------
// Weight conversion: 18 slots of DD f32 -> g_Wb bf16
// slots: 0-2 base_in, 3-5 local_in, 6-8 glob_in, 9-11 cross_in,
//        12 base_out, 13 local_out, 14 glob_out, 15 cross_out, 16 w1, 17 w2
// ---------------------------------------------------------------------------
struct WSrc { const float* p[18]; };
__global__ void cvt_weights_kernel(WSrc ws) {
    for (int i = blockIdx.x * blockDim.x + threadIdx.x; i < 18 * DD;
         i += gridDim.x * blockDim.x) {
        int s = i >> 18;
        int off = i & (DD - 1);
        g_Wb[i] = __float2bfloat16(ws.p[s][off]);
    }
}

// ---------------------------------------------------------------------------
// Embedding gather: M = M_emb[q + NQ*r] + P[n],  E = E_emb[qry]  (f32 + bf16)
// ---------------------------------------------------------------------------
__global__ void embed_kernel(const int* __restrict__ q, const int* __restrict__ r,
                             const int* __restrict__ qry,
                             const float* __restrict__ M_emb,
                             const float* __restrict__ E_emb,
                             const float* __restrict__ P) {
    int row = blockIdx.x;
    int n = row & (N - 1);
    int x = q[row] + NQ * r[row];
    int e = qry[row];
    const float* msrc = M_emb + (size_t)x * D;
    const float* esrc = E_emb + (size_t)e * D;
    const float* psrc = P + (size_t)n * D;
    size_t base = (size_t)row * D;
    for (int d = threadIdx.x; d < D; d += blockDim.x) {
        float mv = msrc[d] + psrc[d];
        float ev = esrc[d];
        g_M[base + d] = mv;  g_Mb[base + d] = __float2bfloat16(mv);
        g_E[base + d] = ev;  g_Eb[base + d] = __float2bfloat16(ev);
    }
}

// ---------------------------------------------------------------------------
// BF16 tensor-core GEMM v2: C[m,n] = sum_k A[m,k]*W[n,k] + bias[n] (+res1..3)
// BK=64, 3-stage cp.async pipeline, dynamic smem. 128x128 tile, 8 warps.
// Outputs: optional f32 C32 (ld 512), optional bf16 C16 (ldc16, col offset),
// transposed-V write for cols >= vcol0.
// ---------------------------------------------------------------------------
__global__ __launch_bounds__(256, 2)
void linear_bf16_kernel(const bf16* __restrict__ A, const bf16* __restrict__ W,
                        const float* __restrict__ bias,
                        float* __restrict__ C32,
                        bf16* __restrict__ C16, int ldc16, int coloff,
                        int vcol0, bf16* __restrict__ Vt,
                        const float* __restrict__ res1,
                        const float* __restrict__ res2,
                        const float* __restrict__ res3,
                        int Nout, int relu) {
    extern __shared__ uint32_t sm[];
    const int tid  = threadIdx.x;
    const int lane = tid & 31;
    const int w    = tid >> 5;
    const int g    = lane >> 2;
    const int tg   = lane & 3;
    const int wm0  = (w >> 2) * 64;
    const int wn0  = (w & 3) * 32;
    const int m0   = blockIdx.y * 128;
    const int n0   = blockIdx.x * 128;
    const uint32_t sm_u32 = (uint32_t)__cvta_generic_to_shared(sm);

    auto load_tile = [&](int t, int s) {
        const int k0 = t * 64;
        uint32_t base = sm_u32 + (uint32_t)(s * L2_STAGE_U32) * 4u;
#pragma unroll
        for (int i = 0; i < 4; i++) {               // A: 128 rows x 8 chunks
            int e = tid + i * 256;
            int row = e >> 3, ch = e & 7;
            cp_async16(base + (uint32_t)(row * L2STR + ch * 4) * 4u,
                       &A[(size_t)(m0 + row) * 512 + k0 + ch * 8]);
        }
        base += (uint32_t)(128 * L2STR) * 4u;
#pragma unroll
        for (int i = 0; i < 4; i++) {               // W: 128 rows x 8 chunks
            int e = tid + i * 256;
            int row = e >> 3, ch = e & 7;
            cp_async16(base + (uint32_t)(row * L2STR + ch * 4) * 4u,
                       &W[(size_t)(n0 + row) * 512 + k0 + ch * 8]);
        }
        cp_commit();
    };

    float acc[4][4][4] = {};
    const int NT = 8;    // 512 / 64
    load_tile(0, 0);
    load_tile(1, 1);
    for (int it = 0; it < NT; ++it) {
        if (it + 2 < NT) {
            load_tile(it + 2, (it + 2) % 3);
            asm volatile("cp.async.wait_group 2;");
        } else if (it + 1 < NT) {
            asm volatile("cp.async.wait_group 1;");
        } else {
            asm volatile("cp.async.wait_group 0;");
        }
        __syncthreads();
        const uint32_t* As = sm + (it % 3) * L2_STAGE_U32;
        const uint32_t* Ws = As + 128 * L2STR;
#pragma unroll
        for (int ks = 0; ks < 4; ks++) {            // 4 k-steps of 16
            const int kc = ks * 8;
            uint32_t a[4][4], bq[4][2];
#pragma unroll
            for (int tm = 0; tm < 4; tm++) {
                int mr = wm0 + tm * 16 + g;
                a[tm][0] = As[mr * L2STR + kc + tg];
                a[tm][1] = As[(mr + 8) * L2STR + kc + tg];
                a[tm][2] = As[mr * L2STR + kc + 4 + tg];
                a[tm][3] = As[(mr + 8) * L2STR + kc + 4 + tg];
            }
#pragma unroll
            for (int tn = 0; tn < 4; tn++) {
                int nr = wn0 + tn * 8 + g;
                bq[tn][0] = Ws[nr * L2STR + kc + tg];
                bq[tn][1] = Ws[nr * L2STR + kc + 4 + tg];
            }
#pragma unroll
            for (int tm = 0; tm < 4; tm++)
#pragma unroll
                for (int tn = 0; tn < 4; tn++)
                    mma_bf16(acc[tm][tn], a[tm][0], a[tm][1], a[tm][2], a[tm][3],
                             bq[tn][0], bq[tn][1]);
        }
        __syncthreads();
    }

#pragma unroll
    for (int tm = 0; tm < 4; tm++) {
        int r0 = m0 + wm0 + tm * 16 + g;
        int r1 = r0 + 8;
#pragma unroll
        for (int tn = 0; tn < 4; tn++) {
            int c = n0 + wn0 + tn * 8 + tg * 2;
            float b0 = bias[c], b1 = bias[c + 1];
            float v00 = acc[tm][tn][0] + b0;
            float v01 = acc[tm][tn][1] + b1;
            float v10 = acc[tm][tn][2] + b0;
            float v11 = acc[tm][tn][3] + b1;
            size_t o0 = (size_t)r0 * 512 + c;
            size_t o1 = (size_t)r1 * 512 + c;
            if (res1) { v00 += res1[o0]; v01 += res1[o0 + 1]; v10 += res1[o1]; v11 += res1[o1 + 1]; }
            if (res2) { v00 += res2[o0]; v01 += res2[o0 + 1]; v10 += res2[o1]; v11 += res2[o1 + 1]; }
            if (res3) { v00 += res3[o0]; v01 += res3[o0 + 1]; v10 += res3[o1]; v11 += res3[o1 + 1]; }
            if (relu) { v00 = fmaxf(v00, 0.f); v01 = fmaxf(v01, 0.f);
                        v10 = fmaxf(v10, 0.f); v11 = fmaxf(v11, 0.f); }
            if (C32) {
                *(float2*)&C32[o0] = make_float2(v00, v01);
                *(float2*)&C32[o1] = make_float2(v10, v11);
            }
            if (C16) {
                if (c >= vcol0) {   // transposed V write
                    int ve = c - vcol0;
                    int h = ve >> 6, e0 = ve & 63;
                    int b_ = r0 >> 9;
                    int t0 = r0 & 511, t1 = r1 & 511;
                    bf16* vrow0 = Vt + ((size_t)((b_ * H + h) * HD + e0)) * N;
                    bf16* vrow1 = vrow0 + N;
                    vrow0[t0] = __float2bfloat16(v00);
                    vrow1[t0] = __float2bfloat16(v01);
                    vrow0[t1] = __float2bfloat16(v10);
                    vrow1[t1] = __float2bfloat16(v11);
                } else {
                    *(bf162*)&C16[(size_t)r0 * ldc16 + coloff + c] =
                        __floats2bfloat162_rn(v00, v01);
                    *(bf162*)&C16[(size_t)r1 * ldc16 + coloff + c] =
                        __floats2bfloat162_rn(v10, v11);
                }
            }
        }
    }
}

// ---------------------------------------------------------------------------
// BF16 attention scores: S16[z,i,j] = dot64(Q, K) * 0.125.  Q/K in g_QK
// (ld 1024, Q at col 0, K at col 512). 128x128 tile, grid (4,4,128).
// ---------------------------------------------------------------------------
__global__ __launch_bounds__(256, 2)
void scores_bf16_kernel(const bf16* __restrict__ QK, bf16* __restrict__ S16,
                        int causal) {
    const int z = blockIdx.z, b = z >> 3, h = z & 7;
    const int i0 = blockIdx.y * 128, j0 = blockIdx.x * 128;
    if (causal && j0 > i0 + 127) return;
    const bf16* Qb = QK + (size_t)(b * N) * 1024 + h * HD;
    const bf16* Kb = Qb + 512;
    bf16* Sb = S16 + (size_t)z * N * N;

    __shared__ uint32_t sm[2 * L_STAGE_U32];
    const int tid  = threadIdx.x;
    const int lane = tid & 31;
    const int w    = tid >> 5;
    const int g    = lane >> 2;
    const int tg   = lane & 3;
    const int wm0  = (w >> 2) * 64;
    const int wn0  = (w & 3) * 32;
    const uint32_t sm_u32 = (uint32_t)__cvta_generic_to_shared(sm);

    auto load_tile = [&](int t, int s) {
        const int k0 = t * 32;
        uint32_t base = sm_u32 + (uint32_t)(s * L_STAGE_U32) * 4u;
#pragma unroll
        for (int i = 0; i < 2; i++) {
            int e = tid + i * 256;
            int row = e >> 2, ch = e & 3;
            cp_async16(base + (uint32_t)(row * LSTR + ch * 4) * 4u,
                       &Qb[(size_t)(i0 + row) * 1024 + k0 + ch * 8]);
        }
        base += (uint32_t)(128 * LSTR) * 4u;
#pragma unroll
        for (int i = 0; i < 2; i++) {
            int e = tid + i * 256;
            int row = e >> 2, ch = e & 3;
            cp_async16(base + (uint32_t)(row * LSTR + ch * 4) * 4u,
                       &Kb[(size_t)(j0 + row) * 1024 + k0 + ch * 8]);
        }
        cp_commit();
    };

    float acc[4][4][4] = {};
    load_tile(0, 0);
    for (int it = 0; it < 2; ++it) {    // HD/32
        if (it == 0) { load_tile(1, 1); asm volatile("cp.async.wait_group 1;"); }
        else         { asm volatile("cp.async.wait_group 0;"); }
        __syncthreads();
        const uint32_t* As = sm + (it & 1) * L_STAGE_U32;
        const uint32_t* Ws = As + 128 * LSTR;
#pragma unroll
        for (int kb2 = 0; kb2 < 2; kb2++) {
            const int kc = kb2 * 8;
            uint32_t a[4][4], bq[4][2];
#pragma unroll
            for (int tm = 0; tm < 4; tm++) {
                int mr = wm0 + tm * 16 + g;
                a[tm][0] = As[mr * LSTR + kc + tg];
                a[tm][1] = As[(mr + 8) * LSTR + kc + tg];
                a[tm][2] = As[mr * LSTR + kc + 4 + tg];
                a[tm][3] = As[(mr + 8) * LSTR + kc + 4 + tg];
            }
#pragma unroll
            for (int tn = 0; tn < 4; tn++) {
                int nr = wn0 + tn * 8 + g;
                bq[tn][0] = Ws[nr * LSTR + kc + tg];
                bq[tn][1] = Ws[nr * LSTR + kc + 4 + tg];
            }
#pragma unroll
            for (int tm = 0; tm < 4; tm++)
#pragma unroll
                for (int tn = 0; tn < 4; tn++)
                    mma_bf16(acc[tm][tn], a[tm][0], a[tm][1], a[tm][2], a[tm][3],
                             bq[tn][0], bq[tn][1]);
        }
        __syncthreads();
    }

#pragma unroll
    for (int tm = 0; tm < 4; tm++) {
        int r0 = i0 + wm0 + tm * 16 + g;
        int r1 = r0 + 8;
#pragma unroll
        for (int tn = 0; tn < 4; tn++) {
            int c = j0 + wn0 + tn * 8 + tg * 2;
            *(bf162*)&Sb[(size_t)r0 * N + c] =
                __floats2bfloat162_rn(acc[tm][tn][0] * 0.125f, acc[tm][tn][1] * 0.125f);
            *(bf162*)&Sb[(size_t)r1 * N + c] =
                __floats2bfloat162_rn(acc[tm][tn][2] * 0.125f, acc[tm][tn][3] * 0.125f);
        }
    }
}

// ---------------------------------------------------------------------------
// BF16 PV: O16[b,i,h*64+e] = sum_j P16[z,i,j] * Vt[z,e,j]
// 128x64 tile, grid (1, 4, 128). 8 warps x (32x32).
// ---------------------------------------------------------------------------
__global__ __launch_bounds__(256, 2)
void pv_bf16_kernel(const bf16* __restrict__ P16, const bf16* __restrict__ Vt,
                    bf16* __restrict__ O16, int causal) {
    const int z = blockIdx.z, b = z >> 3, h = z & 7;
    const int i0 = blockIdx.y * 128;
    const bf16* Pb  = P16 + (size_t)z * N * N;
    const bf16* Vtz = Vt + (size_t)z * HD * N;
    bf16* Ob = O16 + (size_t)(b * N) * 512 + h * HD;

    __shared__ uint32_t sm[2 * PV_STAGE_U32];
    const int tid  = threadIdx.x;
    const int lane = tid & 31;
    const int w    = tid >> 5;
    const int g    = lane >> 2;
    const int tg   = lane & 3;
    const int wm0  = (w >> 1) * 32;
    const int wn0  = (w & 1) * 32;
    const uint32_t sm_u32 = (uint32_t)__cvta_generic_to_shared(sm);

    auto load_tile = [&](int t, int s) {
        const int k0 = t * 32;
        uint32_t base = sm_u32 + (uint32_t)(s * PV_STAGE_U32) * 4u;
#pragma unroll
        for (int i = 0; i < 2; i++) {      // P: 128 rows
            int e = tid + i * 256;
            int row = e >> 2, ch = e & 3;
            cp_async16(base + (uint32_t)(row * LSTR + ch * 4) * 4u,
                       &Pb[(size_t)(i0 + row) * N + k0 + ch * 8]);
        }
        base += (uint32_t)(128 * LSTR) * 4u;
        {                                   // Vt: 64 rows
            int row = tid >> 2, ch = tid & 3;
            cp_async16(base + (uint32_t)(row * LSTR + ch * 4) * 4u,
                       &Vtz[(size_t)row * N + k0 + ch * 8]);
        }
        cp_commit();
    };

    float acc[2][4][4] = {};
    const int kend = causal ? (i0 + 128) : N;
    const int NT = kend / 32;
    load_tile(0, 0);
    for (int it = 0; it < NT; ++it) {
        if (it + 1 < NT) { load_tile(it + 1, (it + 1) & 1);
                           asm volatile("cp.async.wait_group 1;"); }
        else             { asm volatile("cp.async.wait_group 0;"); }
        __syncthreads();
        const uint32_t* As = sm + (it & 1) * PV_STAGE_U32;
        const uint32_t* Vs = As + 128 * LSTR;
#pragma unroll
        for (int kb2 = 0; kb2 < 2; kb2++) {
            const int kc = kb2 * 8;
            uint32_t a[2][4], bq[4][2];
#pragma unroll
            for (int tm = 0; tm < 2; tm++) {
                int mr = wm0 + tm * 16 + g;
                a[tm][0] = As[mr * LSTR + kc + tg];
                a[tm][1] = As[(mr + 8) * LSTR + kc + tg];
                a[tm][2] = As[mr * LSTR + kc + 4 + tg];
                a[tm][3] = As[(mr + 8) * LSTR + kc + 4 + tg];
            }
#pragma unroll
            for (int tn = 0; tn < 4; tn++) {
                int nr = wn0 + tn * 8 + g;
                bq[tn][0] = Vs[nr * LSTR + kc + tg];
                bq[tn][1] = Vs[nr * LSTR + kc + 4 + tg];
            }
#pragma unroll
            for (int tm = 0; tm < 2; tm++)
#pragma unroll
                for (int tn = 0; tn < 4; tn++)
                    mma_bf16(acc[tm][tn], a[tm][0], a[tm][1], a[tm][2], a[tm][3],
                             bq[tn][0], bq[tn][1]);
        }
        __syncthreads();
    }

#pragma unroll
    for (int tm = 0; tm < 2; tm++) {
        int r0 = i0 + wm0 + tm * 16 + g;
        int r1 = r0 + 8;
#pragma unroll
        for (int tn = 0; tn < 4; tn++) {
            int c = wn0 + tn * 8 + tg * 2;
            *(bf162*)&Ob[(size_t)r0 * 512 + c] =
                __floats2bfloat162_rn(acc[tm][tn][0], acc[tm][tn][1]);
            *(bf162*)&Ob[(size_t)r1 * 512 + c] =
                __floats2bfloat162_rn(acc[tm][tn][2], acc[tm][tn][3]);
        }
    }
}

// ---------------------------------------------------------------------------
// Fused BASE softmax + head-mean: one block per (b,i), 256 threads.
// Processes all 8 heads: softmax row (causal) -> P16, accumulates head mean
// -> attn_w output. Eliminates f32 probs buffer entirely.
// ---------------------------------------------------------------------------
__global__ void softmax_base_kernel(const bf16* __restrict__ S16,
                                    bf16* __restrict__ P16,
                                    float* __restrict__ outw) {
    int row = blockIdx.x;                 // b*N + i
    int b = row >> 9, i = row & (N - 1);
    int tid = threadIdx.x;
    int lim = i + 1;
    __shared__ float red[256];
    float m0 = 0.f, m1 = 0.f;
    for (int h = 0; h < H; h++) {
        size_t off = ((size_t)((b * H + h) * N) + i) * N;
        const bf16* Sr = S16 + off;
        bf16* Pr = P16 + off;
        float v0 = (tid < lim) ? __bfloat162float(Sr[tid]) : -1e30f;
        float v1 = (tid + 256 < lim) ? __bfloat162float(Sr[tid + 256]) : -1e30f;
        red[tid] = fmaxf(v0, v1);
        __syncthreads();
        for (int s = 128; s > 0; s >>= 1) {
            if (tid < s) red[tid] = fmaxf(red[tid], red[tid + s]);
            __syncthreads();
        }
        float mx = red[0];
        __syncthreads();
        float e0 = (tid < lim) ? __expf(v0 - mx) : 0.f;
        float e1 = (tid + 256 < lim) ? __expf(v1 - mx) : 0.f;
        red[tid] = e0 + e1;
        __syncthreads();
        for (int s = 128; s > 0; s >>= 1) {
            if (tid < s) red[tid] += red[tid + s];
            __syncthreads();
        }
        float inv = 1.f / red[0];
        __syncthreads();
        float p0 = e0 * inv, p1 = e1 * inv;
        Pr[tid] = __float2bfloat16(p0);
        Pr[tid + 256] = __float2bfloat16(p1);
        m0 += p0; m1 += p1;
    }
    size_t orow = (size_t)row * N;
    outw[orow + tid]       = m0 * 0.125f;
    outw[orow + tid + 256] = m1 * 0.125f;
}

// ---------------------------------------------------------------------------
// Softmax over bf16 scores -> bf16 probs (glob/cross). One block per row.
// ---------------------------------------------------------------------------
__global__ void softmax_bf16_kernel(const bf16* __restrict__ S16,
                                    bf16* __restrict__ P16, int causal) {
    int row = blockIdx.x;
    int i = row & (N - 1);
    const bf16* Sr = S16 + (size_t)row * N;
    bf16* Pr = P16 + (size_t)row * N;
    int lim = causal ? (i + 1) : N;
    int tid = threadIdx.x;
    float v[4];
    float mx = -1e30f;
#pragma unroll
    for (int c = 0; c < 4; c++) {
        int j = tid + c * 128;
        v[c] = (j < lim) ? __bfloat162float(Sr[j]) : -1e30f;
        mx = fmaxf(mx, v[c]);
    }
    __shared__ float red[128];
    red[tid] = mx; __syncthreads();
    for (int s = 64; s > 0; s >>= 1) { if (tid < s) red[tid] = fmaxf(red[tid], red[tid + s]); __syncthreads(); }
    mx = red[0]; __syncthreads();
    float sum = 0.f;
#pragma unroll
    for (int c = 0; c < 4; c++) {
        int j = tid + c * 128;
        float e = (j < lim) ? __expf(v[c] - mx) : 0.f;
        v[c] = e; sum += e;
    }
    red[tid] = sum; __syncthreads();
    for (int s = 64; s > 0; s >>= 1) { if (tid < s) red[tid] += red[tid + s]; __syncthreads(); }
    float inv = 1.f / red[0];
#pragma unroll
    for (int c = 0; c < 4; c++) {
        int j = tid + c * 128;
        Pr[j] = __float2bfloat16(v[c] * inv);
    }
}

// f32 softmax (local path, Nk=64)
__global__ void softmax_f32_kernel(float* __restrict__ S, int Nq, int Nk, int causal) {
    int row = blockIdx.x;
    int i = row % Nq;
    float* Sr = S + (size_t)row * Nk;
    int lim = causal ? (i + 1) : Nk;
    int tid = threadIdx.x;
    float v[4];
    float mx = -1e30f;
#pragma unroll
    for (int c = 0; c < 4; c++) {
        int j = tid + c * 128;
        v[c] = (j < lim && j < Nk) ? Sr[j] : -1e30f;
        mx = fmaxf(mx, v[c]);
    }
    __shared__ float red[128];
    red[tid] = mx; __syncthreads();
    for (int s = 64; s > 0; s >>= 1) { if (tid < s) red[tid] = fmaxf(red[tid], red[tid + s]); __syncthreads(); }
    mx = red[0]; __syncthreads();
    float sum = 0.f;
#pragma unroll
    for (int c = 0; c < 4; c++) {
        int j = tid + c * 128;
        float e = (j < lim && j < Nk) ? __expf(v[c] - mx) : 0.f;
        v[c] = e; sum += e;
    }
    red[tid] = sum; __syncthreads();
    for (int s = 64; s > 0; s >>= 1) { if (tid < s) red[tid] += red[tid + s]; __syncthreads(); }
    float inv = 1.f / red[0];
#pragma unroll
    for (int c = 0; c < 4; c++) {
        int j = tid + c * 128;
        if (j < Nk) Sr[j] = v[c] * inv;
    }
}

// ---------------------------------------------------------------------------
// SIMT local attention (LW=64): scores, PV (bf16 inputs from g_QK ld 1536)
// ---------------------------------------------------------------------------
__global__ void local_scores_kernel(const bf16* __restrict__ QK, float* __restrict__ S) {
    int z = blockIdx.z, b = z >> 3, h = z & 7;
    const bf16* Qb = QK + (size_t)(b * LW) * 1536 + h * HD;
    const bf16* Kb = Qb + 512;
    float* Sb = S + (size_t)z * LW * LW;
    __shared__ float Qs[16][64];
    __shared__ float Ks[16][64];
    int tid = threadIdx.x, tx = tid & 15, ty = tid >> 4;
    float acc[4][4] = {};
    for (int k0 = 0; k0 < HD; k0 += 16) {
        for (int idx = tid; idx < 64 * 16; idx += 256) {
            int i = idx >> 4, j = idx & 15;
            Qs[j][i] = __bfloat162float(Qb[(size_t)i * 1536 + k0 + j]);
            Ks[j][i] = __bfloat162float(Kb[(size_t)i * 1536 + k0 + j]);
        }
        __syncthreads();
#pragma unroll
        for (int k = 0; k < 16; k++) {
            float a[4], wv[4];
#pragma unroll
            for (int i = 0; i < 4; i++) a[i] = Qs[k][ty * 4 + i];
#pragma unroll
            for (int j = 0; j < 4; j++) wv[j] = Ks[k][tx * 4 + j];
#pragma unroll
            for (int i = 0; i < 4; i++)
#pragma unroll
                for (int j = 0; j < 4; j++) acc[i][j] += a[i] * wv[j];
        }
        __syncthreads();
    }
#pragma unroll
    for (int i = 0; i < 4; i++)
#pragma unroll
        for (int j = 0; j < 4; j++)
            Sb[(size_t)(ty * 4 + i) * LW + tx * 4 + j] = acc[i][j] * 0.125f;
}

__global__ void local_pv_kernel(const float* __restrict__ Pm, const bf16* __restrict__ QK,
                                bf16* __restrict__ O16) {
    int z = blockIdx.z, b = z >> 3, h = z & 7;
    const float* Pb = Pm + (size_t)z * LW * LW;
    const bf16* Vb = QK + (size_t)(b * LW) * 1536 + 1024 + h * HD;
    bf16* Ob = O16 + (size_t)(b * LW) * 512 + h * HD;
    __shared__ float Ps[64][17];
    __shared__ float Vs[16][64];
    int tid = threadIdx.x, tx = tid & 15, ty = tid >> 4;
    float acc[4][4] = {};
    for (int k0 = 0; k0 < LW; k0 += 16) {
        for (int idx = tid; idx < 64 * 16; idx += 256) {
            int i = idx >> 4, j = idx & 15;
            Ps[i][j] = Pb[(size_t)i * LW + k0 + j];
        }
        for (int idx = tid; idx < 16 * 64; idx += 256) {
            int k = idx >> 6, e = idx & 63;
            Vs[k][e] = __bfloat162float(Vb[(size_t)(k0 + k) * 1536 + e]);
        }
        __syncthreads();
#pragma unroll
        for (int k = 0; k < 16; k++) {
            float a[4], wv[4];
#pragma unroll
            for (int i = 0; i < 4; i++) a[i] = Ps[ty * 4 + i][k];
#pragma unroll
            for (int j = 0; j < 4; j++) wv[j] = Vs[k][tx * 4 + j];
#pragma unroll
            for (int i = 0; i < 4; i++)
#pragma unroll
                for (int j = 0; j < 4; j++) acc[i][j] += a[i] * wv[j];
        }
        __syncthreads();
    }
#pragma unroll
    for (int i = 0; i < 4; i++)
#pragma unroll
        for (int j = 0; j < 4; j++)
            Ob[(size_t)(ty * 4 + i) * 512 + tx * 4 + j] = __float2bfloat16(acc[i][j]);
}

// ---------------------------------------------------------------------------
// LayerNorm: out = LN(X + r1? + r2?) * g + b   (f32 out + optional bf16 out)
// ---------------------------------------------------------------------------
__global__ void ln_kernel(const float* __restrict__ X, const float* __restrict__ r1,
                          const float* __restrict__ r2, const float* __restrict__ g,
                          const float* __restrict__ bvec, float* __restrict__ out,
                          bf16* __restrict__ out16) {
    int row = blockIdx.x;
    size_t base = (size_t)row * D;
    int tid = threadIdx.x;
    float v[4];
    float s = 0.f;
#pragma unroll
    for (int c = 0; c < 4; c++) {
        int d = tid + c * 128;
        float t = X[base + d];
        if (r1) t += r1[base + d];
        if (r2) t += r2[base + d];
        v[c] = t; s += t;
    }
    __shared__ float red[128];
    red[tid] = s; __syncthreads();
    for (int st = 64; st > 0; st >>= 1) { if (tid < st) red[tid] += red[tid + st]; __syncthreads(); }
    float mean = red[0] * (1.f / D);
    __syncthreads();
    float vs = 0.f;
#pragma unroll
    for (int c = 0; c < 4; c++) { float dl = v[c] - mean; vs += dl * dl; }
    red[tid] = vs; __syncthreads();
    for (int st = 64; st > 0; st >>= 1) { if (tid < st) red[tid] += red[tid + st]; __syncthreads(); }
    float inv = rsqrtf(red[0] * (1.f / D) + 1e-5f);
#pragma unroll
    for (int c = 0; c < 4; c++) {
        int d = tid + c * 128;
        float o = (v[c] - mean) * inv * g[d] + bvec[d];
        out[base + d] = o;
        if (out16) out16[base + d] = __float2bfloat16(o);
    }
}

// ---------------------------------------------------------------------------
// Misc elementwise kernels
// ---------------------------------------------------------------------------
__global__ void pack_loc_kernel() {          // Sb16 last LW rows/b -> T2b
    int idx = blockIdx.x * blockDim.x + threadIdx.x;   // over 1024*512
    int d = idx & (D - 1);
    int row = idx >> 9;
    int b = row >> 6;
    int i = row & (LW - 1);
    g_T2b[idx] = g_Sb16[((size_t)(b * N + (N - LW) + i) << 9) + d];
}

__global__ void expand_local_kernel(const float* __restrict__ packed) {
    size_t idx = (size_t)blockIdx.x * blockDim.x + threadIdx.x;  // over B*N*D
    int d = (int)(idx & (D - 1));
    int row = (int)(idx >> 9);
    int b = row >> 9;
    int n = row & (N - 1);
    float v = 0.f;
    if (n >= N - LW)
        v = packed[(((size_t)b * LW + (n - (N - LW))) << 9) + d];
    g_Slocal[idx] = v;
    g_Sl16[idx] = __float2bfloat16(v);
}

__global__ void pred_kernel(const float* __restrict__ F, const float* __restrict__ pw,
                            const float* __restrict__ pb, float* __restrict__ out) {
    int row = blockIdx.x;
    int tid = threadIdx.x;
    const float* x = F + (size_t)row * D;
    float s = 0.f;
    for (int d = tid; d < D; d += 128) s += x[d] * pw[d];
    __shared__ float red[128];
    red[tid] = s; __syncthreads();
    for (int st = 64; st > 0; st >>= 1) { if (tid < st) red[tid] += red[tid + st]; __syncthreads(); }
    if (tid == 0) out[row] = 1.f / (1.f + __expf(-(red[0] + pb[0])));
}

// ---------------------------------------------------------------------------
// Launch
// ---------------------------------------------------------------------------
extern "C" void kernel_launch(void* const* d_in, const int* in_sizes, int n_in,
                              void* d_out, int out_size) {
    (void)in_sizes; (void)n_in; (void)out_size;
    const int*   q     = (const int*)d_in[0];
    const int*   r     = (const int*)d_in[1];
    const int*   qry   = (const int*)d_in[2];
    const float* M_emb = (const float*)d_in[3];
    const float* E_emb = (const float*)d_in[4];
    const float* Pmat  = (const float*)d_in[5];
    const float* biw = (const float*)d_in[6];  const float* bib = (const float*)d_in[7];
    const float* bow = (const float*)d_in[8];  const float* bob = (const float*)d_in[9];
    const float* liw = (const float*)d_in[10]; const float* lib = (const float*)d_in[11];
    const float* low = (const float*)d_in[12]; const float* lob = (const float*)d_in[13];
    const float* giw = (const float*)d_in[14]; const float* gib = (const float*)d_in[15];
    const float* gow = (const float*)d_in[16]; const float* gob = (const float*)d_in[17];
    const float* ciw = (const float*)d_in[18]; const float* cib = (const float*)d_in[19];
    const float* cow = (const float*)d_in[20]; const float* cob = (const float*)d_in[21];
    const float* ln1g = (const float*)d_in[22]; const float* ln1b = (const float*)d_in[23];
    const float* w1 = (const float*)d_in[24];  const float* b1 = (const float*)d_in[25];
    const float* w2 = (const float*)d_in[26];  const float* b2 = (const float*)d_in[27];
    const float* ln2g = (const float*)d_in[28]; const float* ln2b = (const float*)d_in[29];
    const float* pw = (const float*)d_in[30];  const float* pb = (const float*)d_in[31];
    float* out = (float*)d_out;

    float *pM, *pE, *pT1, *pT2, *pSb, *pSl, *pSg, *pSs, *pP32;
    bf16 *pMb, *pEb, *pQK, *pVt, *pS16, *pP16, *pO16, *pSb16, *pSl16, *pSs16, *pF16, *pT2b, *pWb;
    cudaGetSymbolAddress((void**)&pM,   g_M);
    cudaGetSymbolAddress((void**)&pE,   g_E);
    cudaGetSymbolAddress((void**)&pT1,  g_T1);
    cudaGetSymbolAddress((void**)&pT2,  g_T2);
    cudaGetSymbolAddress((void**)&pSb,  g_Sbase);
    cudaGetSymbolAddress((void**)&pSl,  g_Slocal);
    cudaGetSymbolAddress((void**)&pSg,  g_Sglob);
    cudaGetSymbolAddress((void**)&pSs,  g_Ssum);
    cudaGetSymbolAddress((void**)&pP32, g_P32);
    cudaGetSymbolAddress((void**)&pMb,  g_Mb);
    cudaGetSymbolAddress((void**)&pEb,  g_Eb);
    cudaGetSymbolAddress((void**)&pQK,  g_QK);
    cudaGetSymbolAddress((void**)&pVt,  g_Vt);
    cudaGetSymbolAddress((void**)&pS16, g_S16);
    cudaGetSymbolAddress((void**)&pP16, g_P16);
    cudaGetSymbolAddress((void**)&pO16, g_O16);
    cudaGetSymbolAddress((void**)&pSb16, g_Sb16);
    cudaGetSymbolAddress((void**)&pSl16, g_Sl16);
    cudaGetSymbolAddress((void**)&pSs16, g_Ss16);
    cudaGetSymbolAddress((void**)&pF16, g_F16);
    cudaGetSymbolAddress((void**)&pT2b, g_T2b);
    cudaGetSymbolAddress((void**)&pWb,  g_Wb);

    WSrc ws;
    ws.p[0] = biw; ws.p[1] = biw + DD; ws.p[2] = biw + 2 * DD;
    ws.p[3] = liw; ws.p[4] = liw + DD; ws.p[5] = liw + 2 * DD;
    ws.p[6] = giw; ws.p[7] = giw + DD; ws.p[8] = giw + 2 * DD;
    ws.p[9] = ciw; ws.p[10] = ciw + DD; ws.p[11] = ciw + 2 * DD;
    ws.p[12] = bow; ws.p[13] = low; ws.p[14] = gow; ws.p[15] = cow;
    ws.p[16] = w1; ws.p[17] = w2;
    cvt_weights_kernel<<<4608, 256>>>(ws);

    cudaFuncSetAttribute(linear_bf16_kernel,
                         cudaFuncAttributeMaxDynamicSharedMemorySize, L2_SMEM_BYTES);

    const int BIG = 1 << 30;
    auto lin = [&](const bf16* A, const bf16* W, const float* bias,
                   float* C32, bf16* C16, int ldc16, int coloff, int vcol0,
                   const float* r1, const float* r2, const float* r3,
                   int Mrows, int Nout, int relu) {
        dim3 g(Nout / 128, Mrows / 128);
        linear_bf16_kernel<<<g, 256, L2_SMEM_BYTES>>>(A, W, bias, C32, C16, ldc16,
                                                      coloff, vcol0, pVt,
                                                      r1, r2, r3, Nout, relu);
    };

    // 1. embeddings
    embed_kernel<<<BN_ROWS, 128>>>(q, r, qry, M_emb, E_emb, Pmat);

    // 2. base MHA (Q from E, K/V from M, causal) + attn_w output
    lin(pEb, pWb + 0 * DD, bib,     nullptr, pQK, 1024, 0,   BIG, nullptr, nullptr, nullptr, BN_ROWS, 512, 0);   // Q
    lin(pMb, pWb + 1 * DD, bib + D, nullptr, pQK, 1024, 512, 512, nullptr, nullptr, nullptr, BN_ROWS, 1024, 0);  // K + Vt
    scores_bf16_kernel<<<dim3(4, 4, 128), 256>>>(pQK, pS16, 1);
    softmax_base_kernel<<<BN_ROWS, 256>>>(pS16, pP16, out + BN_ROWS);
    pv_bf16_kernel<<<dim3(1, 4, 128), 256>>>(pP16, pVt, pO16, 1);
    lin(pO16, pWb + 12 * DD, bob, pT1, nullptr, 0, 0, BIG, nullptr, nullptr, nullptr, BN_ROWS, 512, 0);
    ln_kernel<<<BN_ROWS, 128>>>(pT1, pM, pE, ln1g, ln1b, pSb, pSb16);

    // 3. local MHA on last LW tokens (causal) -- SIMT path
    pack_loc_kernel<<<(BLW_ROWS * D) / 256, 256>>>();
    lin(pT2b, pWb + 3 * DD, lib, nullptr, pQK, 1536, 0, BIG, nullptr, nullptr, nullptr, BLW_ROWS, 1536, 0);  // fused QKV
    local_scores_kernel<<<dim3(1, 1, 128), 256>>>(pQK, pP32);
    softmax_f32_kernel<<<B * H * LW, 128>>>(pP32, LW, LW, 1);
    local_pv_kernel<<<dim3(1, 1, 128), 256>>>(pP32, pQK, pO16);
    lin(pO16, pWb + 13 * DD, lob, pT1, nullptr, 0, 0, BIG, nullptr, nullptr, nullptr, BLW_ROWS, 512, 0);
    expand_local_kernel<<<(BN_ROWS * D) / 256, 256>>>(pT1);

    // 4. global MHA (self on S_base, causal) -- fused QKV
    lin(pSb16, pWb + 6 * DD, gib, nullptr, pQK, 1024, 0, 1024, nullptr, nullptr, nullptr, BN_ROWS, 1536, 0);
    scores_bf16_kernel<<<dim3(4, 4, 128), 256>>>(pQK, pS16, 1);
    softmax_bf16_kernel<<<B * H * N, 128>>>(pS16, pP16, 1);
    pv_bf16_kernel<<<dim3(1, 4, 128), 256>>>(pP16, pVt, pO16, 1);
    lin(pO16, pWb + 14 * DD, gob, pSg, nullptr, 0, 0, BIG, nullptr, nullptr, nullptr, BN_ROWS, 512, 0);

    // 5. cross MHA (Q from S_base, K/V from S_local, no mask)
    lin(pSb16, pWb + 9 * DD,  cib,     nullptr, pQK, 1024, 0,   BIG, nullptr, nullptr, nullptr, BN_ROWS, 512, 0);
    lin(pSl16, pWb + 10 * DD, cib + D, nullptr, pQK, 1024, 512, 512, nullptr, nullptr, nullptr, BN_ROWS, 1024, 0);
    scores_bf16_kernel<<<dim3(4, 4, 128), 256>>>(pQK, pS16, 0);
    softmax_bf16_kernel<<<B * H * N, 128>>>(pS16, pP16, 0);
    pv_bf16_kernel<<<dim3(1, 4, 128), 256>>>(pP16, pVt, pO16, 0);
    // cross out-proj with fused S = Sbase + Slocal + Sglob + Scross
    lin(pO16, pWb + 15 * DD, cob, pSs, pSs16, 512, 0, BIG, pSb, pSl, pSg, BN_ROWS, 512, 0);

    // 6. FFN + LN2 + head
    lin(pSs16, pWb + 16 * DD, b1, nullptr, pF16, 512, 0, BIG, nullptr, nullptr, nullptr, BN_ROWS, 512, 1);  // relu
    lin(pF16,  pWb + 17 * DD, b2, pT2, nullptr, 0, 0, BIG, nullptr, nullptr, nullptr, BN_ROWS, 512, 0);
    ln_kernel<<<BN_ROWS, 128>>>(pT2, pSs, nullptr, ln2g, ln2b, pT1, nullptr);
    pred_kernel<<<BN_ROWS, 128>>>(pT1, pw, pb, out);
}

// round 8
// speedup vs baseline: 1.0383x; 1.0383x over previous
#include <cuda_runtime.h>
#include <cuda_bf16.h>
#include <math.h>
#include <stdint.h>

// ---------------------------------------------------------------------------
// Problem constants
// ---------------------------------------------------------------------------
static constexpr int B  = 16;
static constexpr int N  = 512;
static constexpr int D  = 512;
static constexpr int H  = 8;
static constexpr int HD = 64;
static constexpr int LW = 64;
static constexpr int NQ = 10000;
static constexpr int BN_ROWS  = B * N;    // 8192
static constexpr int BLW_ROWS = B * LW;   // 1024
static constexpr int DD = D * D;          // 262144 = 2^18

typedef __nv_bfloat16 bf16;
typedef __nv_bfloat162 bf162;

// ---------------------------------------------------------------------------
// Scratch (static device globals)
// ---------------------------------------------------------------------------
__device__ float g_M     [BN_ROWS * D];
__device__ float g_E     [BN_ROWS * D];
__device__ float g_T1    [BN_ROWS * D];
__device__ float g_T2    [BN_ROWS * D];
__device__ float g_Sbase [BN_ROWS * D];
__device__ float g_Slocal[BN_ROWS * D];
__device__ float g_Sglob [BN_ROWS * D];
__device__ float g_Ssum  [BN_ROWS * D];
__device__ float g_P32   [B * H * LW * LW];    // local probs scratch (f32)
__device__ bf16 g_Mb  [BN_ROWS * D];
__device__ bf16 g_Eb  [BN_ROWS * D];
__device__ bf16 g_QK  [BN_ROWS * 1536];        // packed Q/K (and local QKV)
__device__ bf16 g_Vt  [B * H * HD * N];        // V transposed per (b,h): [e][j]
__device__ bf16 g_S16 [B * H * N * N];         // scores
__device__ bf16 g_P16 [B * H * N * N];         // probs
__device__ bf16 g_O16 [BN_ROWS * D];           // attention output (pre out-proj)
__device__ bf16 g_Sb16[BN_ROWS * D];
__device__ bf16 g_Sl16[BN_ROWS * D];
__device__ bf16 g_Ss16[BN_ROWS * D];
__device__ bf16 g_F16 [BN_ROWS * D];
__device__ bf16 g_T2b [BLW_ROWS * D];
__device__ bf16 g_Wb  [18 * DD];               // bf16 weights

// ---------------------------------------------------------------------------
// MMA / ldmatrix helpers
// ---------------------------------------------------------------------------
__device__ __forceinline__ void cp_async16(uint32_t dst, const void* src) {
    asm volatile("cp.async.cg.shared.global [%0], [%1], 16;" :: "r"(dst), "l"(src));
}
__device__ __forceinline__ void cp_commit() {
    asm volatile("cp.async.commit_group;");
}
__device__ __forceinline__ void mma_bf16(float c[4], uint32_t a0, uint32_t a1,
                                         uint32_t a2, uint32_t a3,
                                         uint32_t b0, uint32_t b1) {
    asm volatile(
        "mma.sync.aligned.m16n8k16.row.col.f32.bf16.bf16.f32 "
        "{%0,%1,%2,%3}, {%4,%5,%6,%7}, {%8,%9}, {%0,%1,%2,%3};"
        : "+f"(c[0]), "+f"(c[1]), "+f"(c[2]), "+f"(c[3])
        : "r"(a0), "r"(a1), "r"(a2), "r"(a3), "r"(b0), "r"(b1));
}
__device__ __forceinline__ void ldsm_x4(uint32_t& r0, uint32_t& r1,
                                        uint32_t& r2, uint32_t& r3, uint32_t addr) {
    asm volatile("ldmatrix.sync.aligned.m8n8.x4.shared.b16 {%0,%1,%2,%3}, [%4];"
                 : "=r"(r0), "=r"(r1), "=r"(r2), "=r"(r3) : "r"(addr));
}

// GEMM smem geometry: rows of 64 bf16 (BK=64) = 32 u32 + 4 pad
static constexpr int L2STR = 36;                     // u32 per row
static constexpr int L2_STAGE_U32 = 256 * L2STR;
static constexpr int L2_SMEM_BYTES = 3 * L2_STAGE_U32 * 4;   // 110592

// pv geometry (BK=32): rows of 32 bf16 = 16 u32 + 4 pad
static constexpr int LSTR = 20;
static constexpr int PV_STAGE_U32 = 192 * LSTR;

// ---------------------------------------------------------------------------
// Weight conversion
// ---------------------------------------------------------------------------
struct WSrc { const float* p[18]; };
__global__ void cvt_weights_kernel(WSrc ws) {
    for (int i = blockIdx.x * blockDim.x + threadIdx.x; i < 18 * DD;
         i += gridDim.x * blockDim.x) {
        int s = i >> 18;
        int off = i & (DD - 1);
        g_Wb[i] = __float2bfloat16(ws.p[s][off]);
    }
}

// ---------------------------------------------------------------------------
// Embedding gather
// ---------------------------------------------------------------------------
__global__ void embed_kernel(const int* __restrict__ q, const int* __restrict__ r,
                             const int* __restrict__ qry,
                             const float* __restrict__ M_emb,
                             const float* __restrict__ E_emb,
                             const float* __restrict__ P) {
    int row = blockIdx.x;
    int n = row & (N - 1);
    int x = q[row] + NQ * r[row];
    int e = qry[row];
    const float* msrc = M_emb + (size_t)x * D;
    const float* esrc = E_emb + (size_t)e * D;
    const float* psrc = P + (size_t)n * D;
    size_t base = (size_t)row * D;
    for (int d = threadIdx.x; d < D; d += blockDim.x) {
        float mv = msrc[d] + psrc[d];
        float ev = esrc[d];
        g_M[base + d] = mv;  g_Mb[base + d] = __float2bfloat16(mv);
        g_E[base + d] = ev;  g_Eb[base + d] = __float2bfloat16(ev);
    }
}

// ---------------------------------------------------------------------------
// BF16 tensor-core GEMM: ldmatrix fragment loads, BK=64, 3-stage pipeline.
// ---------------------------------------------------------------------------
__global__ __launch_bounds__(256, 2)
void linear_bf16_kernel(const bf16* __restrict__ A, const bf16* __restrict__ W,
                        const float* __restrict__ bias,
                        float* __restrict__ C32,
                        bf16* __restrict__ C16, int ldc16, int coloff,
                        int vcol0, bf16* __restrict__ Vt,
                        const float* __restrict__ res1,
                        const float* __restrict__ res2,
                        const float* __restrict__ res3,
                        int Nout, int relu) {
    extern __shared__ uint32_t sm[];
    const int tid  = threadIdx.x;
    const int lane = tid & 31;
    const int w    = tid >> 5;
    const int g    = lane >> 2;
    const int tg   = lane & 3;
    const int wm0  = (w >> 2) * 64;
    const int wn0  = (w & 3) * 32;
    const int m0   = blockIdx.y * 128;
    const int n0   = blockIdx.x * 128;
    const uint32_t sm_u32 = (uint32_t)__cvta_generic_to_shared(sm);

    // ldmatrix per-lane offsets (bytes within a stage half)
    const int qr = lane & 7, qm = (lane >> 3) & 1, qk = lane >> 4;
    const int q2 = lane >> 3, rB = lane & 7;
    uint32_t aoff[4], boff[2];
#pragma unroll
    for (int tm = 0; tm < 4; tm++)
        aoff[tm] = (uint32_t)(((wm0 + tm * 16 + qm * 8 + qr) * L2STR + qk * 4) * 4);
#pragma unroll
    for (int p = 0; p < 2; p++)
        boff[p] = (uint32_t)(((wn0 + (p * 2 + (q2 >> 1)) * 8 + rB) * L2STR + (q2 & 1) * 4) * 4);

    auto load_tile = [&](int t, int s) {
        const int k0 = t * 64;
        uint32_t base = sm_u32 + (uint32_t)(s * L2_STAGE_U32) * 4u;
#pragma unroll
        for (int i = 0; i < 4; i++) {
            int e = tid + i * 256;
            int row = e >> 3, ch = e & 7;
            cp_async16(base + (uint32_t)(row * L2STR + ch * 4) * 4u,
                       &A[(size_t)(m0 + row) * 512 + k0 + ch * 8]);
        }
        base += (uint32_t)(128 * L2STR) * 4u;
#pragma unroll
        for (int i = 0; i < 4; i++) {
            int e = tid + i * 256;
            int row = e >> 3, ch = e & 7;
            cp_async16(base + (uint32_t)(row * L2STR + ch * 4) * 4u,
                       &W[(size_t)(n0 + row) * 512 + k0 + ch * 8]);
        }
        cp_commit();
    };

    float acc[4][4][4] = {};
    const int NT = 8;    // 512 / 64
    load_tile(0, 0);
    load_tile(1, 1);
    for (int it = 0; it < NT; ++it) {
        if (it + 2 < NT) {
            load_tile(it + 2, (it + 2) % 3);
            asm volatile("cp.async.wait_group 2;");
        } else if (it + 1 < NT) {
            asm volatile("cp.async.wait_group 1;");
        } else {
            asm volatile("cp.async.wait_group 0;");
        }
        __syncthreads();
        const uint32_t baseA = sm_u32 + (uint32_t)((it % 3) * L2_STAGE_U32) * 4u;
        const uint32_t baseW = baseA + (uint32_t)(128 * L2STR) * 4u;
#pragma unroll
        for (int ks = 0; ks < 4; ks++) {
            const uint32_t kb = (uint32_t)(ks * 32);   // 8 u32 = 32 bytes
            uint32_t a[4][4], bq[4][2];
#pragma unroll
            for (int tm = 0; tm < 4; tm++)
                ldsm_x4(a[tm][0], a[tm][1], a[tm][2], a[tm][3], baseA + aoff[tm] + kb);
#pragma unroll
            for (int p = 0; p < 2; p++)
                ldsm_x4(bq[p * 2][0], bq[p * 2][1], bq[p * 2 + 1][0], bq[p * 2 + 1][1],
                        baseW + boff[p] + kb);
#pragma unroll
            for (int tm = 0; tm < 4; tm++)
#pragma unroll
                for (int tn = 0; tn < 4; tn++)
                    mma_bf16(acc[tm][tn], a[tm][0], a[tm][1], a[tm][2], a[tm][3],
                             bq[tn][0], bq[tn][1]);
        }
        __syncthreads();
    }

#pragma unroll
    for (int tm = 0; tm < 4; tm++) {
        int r0 = m0 + wm0 + tm * 16 + g;
        int r1 = r0 + 8;
#pragma unroll
        for (int tn = 0; tn < 4; tn++) {
            int c = n0 + wn0 + tn * 8 + tg * 2;
            float b0 = bias[c], b1 = bias[c + 1];
            float v00 = acc[tm][tn][0] + b0;
            float v01 = acc[tm][tn][1] + b1;
            float v10 = acc[tm][tn][2] + b0;
            float v11 = acc[tm][tn][3] + b1;
            size_t o0 = (size_t)r0 * 512 + c;
            size_t o1 = (size_t)r1 * 512 + c;
            if (res1) { v00 += res1[o0]; v01 += res1[o0 + 1]; v10 += res1[o1]; v11 += res1[o1 + 1]; }
            if (res2) { v00 += res2[o0]; v01 += res2[o0 + 1]; v10 += res2[o1]; v11 += res2[o1 + 1]; }
            if (res3) { v00 += res3[o0]; v01 += res3[o0 + 1]; v10 += res3[o1]; v11 += res3[o1 + 1]; }
            if (relu) { v00 = fmaxf(v00, 0.f); v01 = fmaxf(v01, 0.f);
                        v10 = fmaxf(v10, 0.f); v11 = fmaxf(v11, 0.f); }
            if (C32) {
                *(float2*)&C32[o0] = make_float2(v00, v01);
                *(float2*)&C32[o1] = make_float2(v10, v11);
            }
            if (C16) {
                if (c >= vcol0) {
                    int ve = c - vcol0;
                    int h = ve >> 6, e0 = ve & 63;
                    int b_ = r0 >> 9;
                    int t0 = r0 & 511, t1 = r1 & 511;
                    bf16* vrow0 = Vt + ((size_t)((b_ * H + h) * HD + e0)) * N;
                    bf16* vrow1 = vrow0 + N;
                    vrow0[t0] = __float2bfloat16(v00);
                    vrow1[t0] = __float2bfloat16(v01);
                    vrow0[t1] = __float2bfloat16(v10);
                    vrow1[t1] = __float2bfloat16(v11);
                } else {
                    *(bf162*)&C16[(size_t)r0 * ldc16 + coloff + c] =
                        __floats2bfloat162_rn(v00, v01);
                    *(bf162*)&C16[(size_t)r1 * ldc16 + coloff + c] =
                        __floats2bfloat162_rn(v10, v11);
                }
            }
        }
    }
}

// ---------------------------------------------------------------------------
// BF16 attention scores, single-stage K=64, ldmatrix fragments.
// S16[z,i,j] = dot64(Q,K) * 0.125; Q/K packed in g_QK (ld 1024).
// ---------------------------------------------------------------------------
__global__ __launch_bounds__(256, 2)
void scores_bf16_kernel(const bf16* __restrict__ QK, bf16* __restrict__ S16,
                        int causal) {
    const int z = blockIdx.z, b = z >> 3, h = z & 7;
    const int i0 = blockIdx.y * 128, j0 = blockIdx.x * 128;
    if (causal && j0 > i0 + 127) return;
    const bf16* Qb = QK + (size_t)(b * N) * 1024 + h * HD;
    const bf16* Kb = Qb + 512;
    bf16* Sb = S16 + (size_t)z * N * N;

    __shared__ uint32_t sm[256 * L2STR];   // Q(128 rows) + K(128 rows), 36 KB
    const int tid  = threadIdx.x;
    const int lane = tid & 31;
    const int w    = tid >> 5;
    const int g    = lane >> 2;
    const int tg   = lane & 3;
    const int wm0  = (w >> 2) * 64;
    const int wn0  = (w & 3) * 32;
    const uint32_t sm_u32 = (uint32_t)__cvta_generic_to_shared(sm);
    const uint32_t baseQ = sm_u32;
    const uint32_t baseK = sm_u32 + (uint32_t)(128 * L2STR) * 4u;

    // load both tiles (each 128 rows x 32 u32)
#pragma unroll
    for (int i = 0; i < 4; i++) {
        int e = tid + i * 256;
        int row = e >> 3, ch = e & 7;
        cp_async16(baseQ + (uint32_t)(row * L2STR + ch * 4) * 4u,
                   &Qb[(size_t)(i0 + row) * 1024 + ch * 8]);
    }
#pragma unroll
    for (int i = 0; i < 4; i++) {
        int e = tid + i * 256;
        int row = e >> 3, ch = e & 7;
        cp_async16(baseK + (uint32_t)(row * L2STR + ch * 4) * 4u,
                   &Kb[(size_t)(j0 + row) * 1024 + ch * 8]);
    }
    cp_commit();
    asm volatile("cp.async.wait_group 0;");
    __syncthreads();

    const int qr = lane & 7, qm = (lane >> 3) & 1, qk = lane >> 4;
    const int q2 = lane >> 3, rB = lane & 7;
    uint32_t aoff[4], boff[2];
#pragma unroll
    for (int tm = 0; tm < 4; tm++)
        aoff[tm] = (uint32_t)(((wm0 + tm * 16 + qm * 8 + qr) * L2STR + qk * 4) * 4);
#pragma unroll
    for (int p = 0; p < 2; p++)
        boff[p] = (uint32_t)(((wn0 + (p * 2 + (q2 >> 1)) * 8 + rB) * L2STR + (q2 & 1) * 4) * 4);

    float acc[4][4][4] = {};
#pragma unroll
    for (int ks = 0; ks < 4; ks++) {       // 4 x k16 = K=64
        const uint32_t kb = (uint32_t)(ks * 32);
        uint32_t a[4][4], bq[4][2];
#pragma unroll
        for (int tm = 0; tm < 4; tm++)
            ldsm_x4(a[tm][0], a[tm][1], a[tm][2], a[tm][3], baseQ + aoff[tm] + kb);
#pragma unroll
        for (int p = 0; p < 2; p++)
            ldsm_x4(bq[p * 2][0], bq[p * 2][1], bq[p * 2 + 1][0], bq[p * 2 + 1][1],
                    baseK + boff[p] + kb);
#pragma unroll
        for (int tm = 0; tm < 4; tm++)
#pragma unroll
            for (int tn = 0; tn < 4; tn++)
                mma_bf16(acc[tm][tn], a[tm][0], a[tm][1], a[tm][2], a[tm][3],
                         bq[tn][0], bq[tn][1]);
    }

#pragma unroll
    for (int tm = 0; tm < 4; tm++) {
        int r0 = i0 + wm0 + tm * 16 + g;
        int r1 = r0 + 8;
#pragma unroll
        for (int tn = 0; tn < 4; tn++) {
            int c = j0 + wn0 + tn * 8 + tg * 2;
            *(bf162*)&Sb[(size_t)r0 * N + c] =
                __floats2bfloat162_rn(acc[tm][tn][0] * 0.125f, acc[tm][tn][1] * 0.125f);
            *(bf162*)&Sb[(size_t)r1 * N + c] =
                __floats2bfloat162_rn(acc[tm][tn][2] * 0.125f, acc[tm][tn][3] * 0.125f);
        }
    }
}

// ---------------------------------------------------------------------------
// BF16 PV: O16 = P16 @ Vt^T, 128x64 tile, BK=32, ldmatrix fragments.
// ---------------------------------------------------------------------------
__global__ __launch_bounds__(256, 2)
void pv_bf16_kernel(const bf16* __restrict__ P16, const bf16* __restrict__ Vt,
                    bf16* __restrict__ O16, int causal) {
    const int z = blockIdx.z, b = z >> 3, h = z & 7;
    const int i0 = blockIdx.y * 128;
    const bf16* Pb  = P16 + (size_t)z * N * N;
    const bf16* Vtz = Vt + (size_t)z * HD * N;
    bf16* Ob = O16 + (size_t)(b * N) * 512 + h * HD;

    __shared__ uint32_t sm[2 * PV_STAGE_U32];
    const int tid  = threadIdx.x;
    const int lane = tid & 31;
    const int w    = tid >> 5;
    const int g    = lane >> 2;
    const int tg   = lane & 3;
    const int wm0  = (w >> 1) * 32;
    const int wn0  = (w & 1) * 32;
    const uint32_t sm_u32 = (uint32_t)__cvta_generic_to_shared(sm);

    const int qr = lane & 7, qm = (lane >> 3) & 1, qk = lane >> 4;
    const int q2 = lane >> 3, rB = lane & 7;
    uint32_t aoff[2], boff[2];
#pragma unroll
    for (int tm = 0; tm < 2; tm++)
        aoff[tm] = (uint32_t)(((wm0 + tm * 16 + qm * 8 + qr) * LSTR + qk * 4) * 4);
#pragma unroll
    for (int p = 0; p < 2; p++)
        boff[p] = (uint32_t)(((wn0 + (p * 2 + (q2 >> 1)) * 8 + rB) * LSTR + (q2 & 1) * 4) * 4);

    auto load_tile = [&](int t, int s) {
        const int k0 = t * 32;
        uint32_t base = sm_u32 + (uint32_t)(s * PV_STAGE_U32) * 4u;
#pragma unroll
        for (int i = 0; i < 2; i++) {      // P: 128 rows x 4 chunks
            int e = tid + i * 256;
            int row = e >> 2, ch = e & 3;
            cp_async16(base + (uint32_t)(row * LSTR + ch * 4) * 4u,
                       &Pb[(size_t)(i0 + row) * N + k0 + ch * 8]);
        }
        base += (uint32_t)(128 * LSTR) * 4u;
        {                                   // Vt: 64 rows x 4 chunks
            int row = tid >> 2, ch = tid & 3;
            cp_async16(base + (uint32_t)(row * LSTR + ch * 4) * 4u,
                       &Vtz[(size_t)row * N + k0 + ch * 8]);
        }
        cp_commit();
    };

    float acc[2][4][4] = {};
    const int kend = causal ? (i0 + 128) : N;
    const int NT = kend / 32;
    load_tile(0, 0);
    for (int it = 0; it < NT; ++it) {
        if (it + 1 < NT) { load_tile(it + 1, (it + 1) & 1);
                           asm volatile("cp.async.wait_group 1;"); }
        else             { asm volatile("cp.async.wait_group 0;"); }
        __syncthreads();
        const uint32_t baseP = sm_u32 + (uint32_t)((it & 1) * PV_STAGE_U32) * 4u;
        const uint32_t baseV = baseP + (uint32_t)(128 * LSTR) * 4u;
#pragma unroll
        for (int ks = 0; ks < 2; ks++) {
            const uint32_t kb = (uint32_t)(ks * 32);
            uint32_t a[2][4], bq[4][2];
#pragma unroll
            for (int tm = 0; tm < 2; tm++)
                ldsm_x4(a[tm][0], a[tm][1], a[tm][2], a[tm][3], baseP + aoff[tm] + kb);
#pragma unroll
            for (int p = 0; p < 2; p++)
                ldsm_x4(bq[p * 2][0], bq[p * 2][1], bq[p * 2 + 1][0], bq[p * 2 + 1][1],
                        baseV + boff[p] + kb);
#pragma unroll
            for (int tm = 0; tm < 2; tm++)
#pragma unroll
                for (int tn = 0; tn < 4; tn++)
                    mma_bf16(acc[tm][tn], a[tm][0], a[tm][1], a[tm][2], a[tm][3],
                             bq[tn][0], bq[tn][1]);
        }
        __syncthreads();
    }

#pragma unroll
    for (int tm = 0; tm < 2; tm++) {
        int r0 = i0 + wm0 + tm * 16 + g;
        int r1 = r0 + 8;
#pragma unroll
        for (int tn = 0; tn < 4; tn++) {
            int c = wn0 + tn * 8 + tg * 2;
            *(bf162*)&Ob[(size_t)r0 * 512 + c] =
                __floats2bfloat162_rn(acc[tm][tn][0], acc[tm][tn][1]);
            *(bf162*)&Ob[(size_t)r1 * 512 + c] =
                __floats2bfloat162_rn(acc[tm][tn][2], acc[tm][tn][3]);
        }
    }
}

// ---------------------------------------------------------------------------
// Fused BASE softmax + head-mean: one block per (b,i), 256 threads.
// ---------------------------------------------------------------------------
__global__ void softmax_base_kernel(const bf16* __restrict__ S16,
                                    bf16* __restrict__ P16,
                                    float* __restrict__ outw) {
    int row = blockIdx.x;
    int b = row >> 9, i = row & (N - 1);
    int tid = threadIdx.x;
    int lim = i + 1;
    __shared__ float red[256];
    float m0 = 0.f, m1 = 0.f;
    for (int h = 0; h < H; h++) {
        size_t off = ((size_t)((b * H + h) * N) + i) * N;
        const bf16* Sr = S16 + off;
        bf16* Pr = P16 + off;
        float v0 = (tid < lim) ? __bfloat162float(Sr[tid]) : -1e30f;
        float v1 = (tid + 256 < lim) ? __bfloat162float(Sr[tid + 256]) : -1e30f;
        red[tid] = fmaxf(v0, v1);
        __syncthreads();
        for (int s = 128; s > 0; s >>= 1) {
            if (tid < s) red[tid] = fmaxf(red[tid], red[tid + s]);
            __syncthreads();
        }
        float mx = red[0];
        __syncthreads();
        float e0 = (tid < lim) ? __expf(v0 - mx) : 0.f;
        float e1 = (tid + 256 < lim) ? __expf(v1 - mx) : 0.f;
        red[tid] = e0 + e1;
        __syncthreads();
        for (int s = 128; s > 0; s >>= 1) {
            if (tid < s) red[tid] += red[tid + s];
            __syncthreads();
        }
        float inv = 1.f / red[0];
        __syncthreads();
        float p0 = e0 * inv, p1 = e1 * inv;
        Pr[tid] = __float2bfloat16(p0);
        Pr[tid + 256] = __float2bfloat16(p1);
        m0 += p0; m1 += p1;
    }
    size_t orow = (size_t)row * N;
    outw[orow + tid]       = m0 * 0.125f;
    outw[orow + tid + 256] = m1 * 0.125f;
}

// ---------------------------------------------------------------------------
// Softmax over bf16 scores -> bf16 probs (glob/cross).
// ---------------------------------------------------------------------------
__global__ void softmax_bf16_kernel(const bf16* __restrict__ S16,
                                    bf16* __restrict__ P16, int causal) {
    int row = blockIdx.x;
    int i = row & (N - 1);
    const bf16* Sr = S16 + (size_t)row * N;
    bf16* Pr = P16 + (size_t)row * N;
    int lim = causal ? (i + 1) : N;
    int tid = threadIdx.x;
    float v[4];
    float mx = -1e30f;
#pragma unroll
    for (int c = 0; c < 4; c++) {
        int j = tid + c * 128;
        v[c] = (j < lim) ? __bfloat162float(Sr[j]) : -1e30f;
        mx = fmaxf(mx, v[c]);
    }
    __shared__ float red[128];
    red[tid] = mx; __syncthreads();
    for (int s = 64; s > 0; s >>= 1) { if (tid < s) red[tid] = fmaxf(red[tid], red[tid + s]); __syncthreads(); }
    mx = red[0]; __syncthreads();
    float sum = 0.f;
#pragma unroll
    for (int c = 0; c < 4; c++) {
        int j = tid + c * 128;
        float e = (j < lim) ? __expf(v[c] - mx) : 0.f;
        v[c] = e; sum += e;
    }
    red[tid] = sum; __syncthreads();
    for (int s = 64; s > 0; s >>= 1) { if (tid < s) red[tid] += red[tid + s]; __syncthreads(); }
    float inv = 1.f / red[0];
#pragma unroll
    for (int c = 0; c < 4; c++) {
        int j = tid + c * 128;
        Pr[j] = __float2bfloat16(v[c] * inv);
    }
}

// f32 softmax (local path, Nk=64)
__global__ void softmax_f32_kernel(float* __restrict__ S, int Nq, int Nk, int causal) {
    int row = blockIdx.x;
    int i = row % Nq;
    float* Sr = S + (size_t)row * Nk;
    int lim = causal ? (i + 1) : Nk;
    int tid = threadIdx.x;
    float v[4];
    float mx = -1e30f;
#pragma unroll
    for (int c = 0; c < 4; c++) {
        int j = tid + c * 128;
        v[c] = (j < lim && j < Nk) ? Sr[j] : -1e30f;
        mx = fmaxf(mx, v[c]);
    }
    __shared__ float red[128];
    red[tid] = mx; __syncthreads();
    for (int s = 64; s > 0; s >>= 1) { if (tid < s) red[tid] = fmaxf(red[tid], red[tid + s]); __syncthreads(); }
    mx = red[0]; __syncthreads();
    float sum = 0.f;
#pragma unroll
    for (int c = 0; c < 4; c++) {
        int j = tid + c * 128;
        float e = (j < lim && j < Nk) ? __expf(v[c] - mx) : 0.f;
        v[c] = e; sum += e;
    }
    red[tid] = sum; __syncthreads();
    for (int s = 64; s > 0; s >>= 1) { if (tid < s) red[tid] += red[tid + s]; __syncthreads(); }
    float inv = 1.f / red[0];
#pragma unroll
    for (int c = 0; c < 4; c++) {
        int j = tid + c * 128;
        if (j < Nk) Sr[j] = v[c] * inv;
    }
}

// ---------------------------------------------------------------------------
// SIMT local attention (LW=64)
// ---------------------------------------------------------------------------
__global__ void local_scores_kernel(const bf16* __restrict__ QK, float* __restrict__ S) {
    int z = blockIdx.z, b = z >> 3, h = z & 7;
    const bf16* Qb = QK + (size_t)(b * LW) * 1536 + h * HD;
    const bf16* Kb = Qb + 512;
    float* Sb = S + (size_t)z * LW * LW;
    __shared__ float Qs[16][64];
    __shared__ float Ks[16][64];
    int tid = threadIdx.x, tx = tid & 15, ty = tid >> 4;
    float acc[4][4] = {};
    for (int k0 = 0; k0 < HD; k0 += 16) {
        for (int idx = tid; idx < 64 * 16; idx += 256) {
            int i = idx >> 4, j = idx & 15;
            Qs[j][i] = __bfloat162float(Qb[(size_t)i * 1536 + k0 + j]);
            Ks[j][i] = __bfloat162float(Kb[(size_t)i * 1536 + k0 + j]);
        }
        __syncthreads();
#pragma unroll
        for (int k = 0; k < 16; k++) {
            float a[4], wv[4];
#pragma unroll
            for (int i = 0; i < 4; i++) a[i] = Qs[k][ty * 4 + i];
#pragma unroll
            for (int j = 0; j < 4; j++) wv[j] = Ks[k][tx * 4 + j];
#pragma unroll
            for (int i = 0; i < 4; i++)
#pragma unroll
                for (int j = 0; j < 4; j++) acc[i][j] += a[i] * wv[j];
        }
        __syncthreads();
    }
#pragma unroll
    for (int i = 0; i < 4; i++)
#pragma unroll
        for (int j = 0; j < 4; j++)
            Sb[(size_t)(ty * 4 + i) * LW + tx * 4 + j] = acc[i][j] * 0.125f;
}

__global__ void local_pv_kernel(const float* __restrict__ Pm, const bf16* __restrict__ QK,
                                bf16* __restrict__ O16) {
    int z = blockIdx.z, b = z >> 3, h = z & 7;
    const float* Pb = Pm + (size_t)z * LW * LW;
    const bf16* Vb = QK + (size_t)(b * LW) * 1536 + 1024 + h * HD;
    bf16* Ob = O16 + (size_t)(b * LW) * 512 + h * HD;
    __shared__ float Ps[64][17];
    __shared__ float Vs[16][64];
    int tid = threadIdx.x, tx = tid & 15, ty = tid >> 4;
    float acc[4][4] = {};
    for (int k0 = 0; k0 < LW; k0 += 16) {
        for (int idx = tid; idx < 64 * 16; idx += 256) {
            int i = idx >> 4, j = idx & 15;
            Ps[i][j] = Pb[(size_t)i * LW + k0 + j];
        }
        for (int idx = tid; idx < 16 * 64; idx += 256) {
            int k = idx >> 6, e = idx & 63;
            Vs[k][e] = __bfloat162float(Vb[(size_t)(k0 + k) * 1536 + e]);
        }
        __syncthreads();
#pragma unroll
        for (int k = 0; k < 16; k++) {
            float a[4], wv[4];
#pragma unroll
            for (int i = 0; i < 4; i++) a[i] = Ps[ty * 4 + i][k];
#pragma unroll
            for (int j = 0; j < 4; j++) wv[j] = Vs[k][tx * 4 + j];
#pragma unroll
            for (int i = 0; i < 4; i++)
#pragma unroll
                for (int j = 0; j < 4; j++) acc[i][j] += a[i] * wv[j];
        }
        __syncthreads();
    }
#pragma unroll
    for (int i = 0; i < 4; i++)
#pragma unroll
        for (int j = 0; j < 4; j++)
            Ob[(size_t)(ty * 4 + i) * 512 + tx * 4 + j] = __float2bfloat16(acc[i][j]);
}

// ---------------------------------------------------------------------------
// LayerNorm: out = LN(X + r1? + r2?) * g + b
// ---------------------------------------------------------------------------
__global__ void ln_kernel(const float* __restrict__ X, const float* __restrict__ r1,
                          const float* __restrict__ r2, const float* __restrict__ g,
                          const float* __restrict__ bvec, float* __restrict__ out,
                          bf16* __restrict__ out16) {
    int row = blockIdx.x;
    size_t base = (size_t)row * D;
    int tid = threadIdx.x;
    float v[4];
    float s = 0.f;
#pragma unroll
    for (int c = 0; c < 4; c++) {
        int d = tid + c * 128;
        float t = X[base + d];
        if (r1) t += r1[base + d];
        if (r2) t += r2[base + d];
        v[c] = t; s += t;
    }
    __shared__ float red[128];
    red[tid] = s; __syncthreads();
    for (int st = 64; st > 0; st >>= 1) { if (tid < st) red[tid] += red[tid + st]; __syncthreads(); }
    float mean = red[0] * (1.f / D);
    __syncthreads();
    float vs = 0.f;
#pragma unroll
    for (int c = 0; c < 4; c++) { float dl = v[c] - mean; vs += dl * dl; }
    red[tid] = vs; __syncthreads();
    for (int st = 64; st > 0; st >>= 1) { if (tid < st) red[tid] += red[tid + st]; __syncthreads(); }
    float inv = rsqrtf(red[0] * (1.f / D) + 1e-5f);
#pragma unroll
    for (int c = 0; c < 4; c++) {
        int d = tid + c * 128;
        float o = (v[c] - mean) * inv * g[d] + bvec[d];
        out[base + d] = o;
        if (out16) out16[base + d] = __float2bfloat16(o);
    }
}

// ---------------------------------------------------------------------------
// Misc elementwise kernels
// ---------------------------------------------------------------------------
__global__ void pack_loc_kernel() {
    int idx = blockIdx.x * blockDim.x + threadIdx.x;
    int d = idx & (D - 1);
    int row = idx >> 9;
    int b = row >> 6;
    int i = row & (LW - 1);
    g_T2b[idx] = g_Sb16[((size_t)(b * N + (N - LW) + i) << 9) + d];
}

__global__ void expand_local_kernel(const float* __restrict__ packed) {
    size_t idx = (size_t)blockIdx.x * blockDim.x + threadIdx.x;
    int d = (int)(idx & (D - 1));
    int row = (int)(idx >> 9);
    int b = row >> 9;
    int n = row & (N - 1);
    float v = 0.f;
    if (n >= N - LW)
        v = packed[(((size_t)b * LW + (n - (N - LW))) << 9) + d];
    g_Slocal[idx] = v;
    g_Sl16[idx] = __float2bfloat16(v);
}

__global__ void pred_kernel(const float* __restrict__ F, const float* __restrict__ pw,
                            const float* __restrict__ pb, float* __restrict__ out) {
    int row = blockIdx.x;
    int tid = threadIdx.x;
    const float* x = F + (size_t)row * D;
    float s = 0.f;
    for (int d = tid; d < D; d += 128) s += x[d] * pw[d];
    __shared__ float red[128];
    red[tid] = s; __syncthreads();
    for (int st = 64; st > 0; st >>= 1) { if (tid < st) red[tid] += red[tid + st]; __syncthreads(); }
    if (tid == 0) out[row] = 1.f / (1.f + __expf(-(red[0] + pb[0])));
}

// ---------------------------------------------------------------------------
// Launch
// ---------------------------------------------------------------------------
extern "C" void kernel_launch(void* const* d_in, const int* in_sizes, int n_in,
                              void* d_out, int out_size) {
    (void)in_sizes; (void)n_in; (void)out_size;
    const int*   q     = (const int*)d_in[0];
    const int*   r     = (const int*)d_in[1];
    const int*   qry   = (const int*)d_in[2];
    const float* M_emb = (const float*)d_in[3];
    const float* E_emb = (const float*)d_in[4];
    const float* Pmat  = (const float*)d_in[5];
    const float* biw = (const float*)d_in[6];  const float* bib = (const float*)d_in[7];
    const float* bow = (const float*)d_in[8];  const float* bob = (const float*)d_in[9];
    const float* liw = (const float*)d_in[10]; const float* lib = (const float*)d_in[11];
    const float* low = (const float*)d_in[12]; const float* lob = (const float*)d_in[13];
    const float* giw = (const float*)d_in[14]; const float* gib = (const float*)d_in[15];
    const float* gow = (const float*)d_in[16]; const float* gob = (const float*)d_in[17];
    const float* ciw = (const float*)d_in[18]; const float* cib = (const float*)d_in[19];
    const float* cow = (const float*)d_in[20]; const float* cob = (const float*)d_in[21];
    const float* ln1g = (const float*)d_in[22]; const float* ln1b = (const float*)d_in[23];
    const float* w1 = (const float*)d_in[24];  const float* b1 = (const float*)d_in[25];
    const float* w2 = (const float*)d_in[26];  const float* b2 = (const float*)d_in[27];
    const float* ln2g = (const float*)d_in[28]; const float* ln2b = (const float*)d_in[29];
    const float* pw = (const float*)d_in[30];  const float* pb = (const float*)d_in[31];
    float* out = (float*)d_out;

    float *pM, *pE, *pT1, *pT2, *pSb, *pSl, *pSg, *pSs, *pP32;
    bf16 *pMb, *pEb, *pQK, *pVt, *pS16, *pP16, *pO16, *pSb16, *pSl16, *pSs16, *pF16, *pT2b, *pWb;
    cudaGetSymbolAddress((void**)&pM,   g_M);
    cudaGetSymbolAddress((void**)&pE,   g_E);
    cudaGetSymbolAddress((void**)&pT1,  g_T1);
    cudaGetSymbolAddress((void**)&pT2,  g_T2);
    cudaGetSymbolAddress((void**)&pSb,  g_Sbase);
    cudaGetSymbolAddress((void**)&pSl,  g_Slocal);
    cudaGetSymbolAddress((void**)&pSg,  g_Sglob);
    cudaGetSymbolAddress((void**)&pSs,  g_Ssum);
    cudaGetSymbolAddress((void**)&pP32, g_P32);
    cudaGetSymbolAddress((void**)&pMb,  g_Mb);
    cudaGetSymbolAddress((void**)&pEb,  g_Eb);
    cudaGetSymbolAddress((void**)&pQK,  g_QK);
    cudaGetSymbolAddress((void**)&pVt,  g_Vt);
    cudaGetSymbolAddress((void**)&pS16, g_S16);
    cudaGetSymbolAddress((void**)&pP16, g_P16);
    cudaGetSymbolAddress((void**)&pO16, g_O16);
    cudaGetSymbolAddress((void**)&pSb16, g_Sb16);
    cudaGetSymbolAddress((void**)&pSl16, g_Sl16);
    cudaGetSymbolAddress((void**)&pSs16, g_Ss16);
    cudaGetSymbolAddress((void**)&pF16, g_F16);
    cudaGetSymbolAddress((void**)&pT2b, g_T2b);
    cudaGetSymbolAddress((void**)&pWb,  g_Wb);

    WSrc ws;
    ws.p[0] = biw; ws.p[1] = biw + DD; ws.p[2] = biw + 2 * DD;
    ws.p[3] = liw; ws.p[4] = liw + DD; ws.p[5] = liw + 2 * DD;
    ws.p[6] = giw; ws.p[7] = giw + DD; ws.p[8] = giw + 2 * DD;
    ws.p[9] = ciw; ws.p[10] = ciw + DD; ws.p[11] = ciw + 2 * DD;
    ws.p[12] = bow; ws.p[13] = low; ws.p[14] = gow; ws.p[15] = cow;
    ws.p[16] = w1; ws.p[17] = w2;
    cvt_weights_kernel<<<4608, 256>>>(ws);

    cudaFuncSetAttribute(linear_bf16_kernel,
                         cudaFuncAttributeMaxDynamicSharedMemorySize, L2_SMEM_BYTES);

    const int BIG = 1 << 30;
    auto lin = [&](const bf16* A, const bf16* W, const float* bias,
                   float* C32, bf16* C16, int ldc16, int coloff, int vcol0,
                   const float* r1, const float* r2, const float* r3,
                   int Mrows, int Nout, int relu) {
        dim3 g(Nout / 128, Mrows / 128);
        linear_bf16_kernel<<<g, 256, L2_SMEM_BYTES>>>(A, W, bias, C32, C16, ldc16,
                                                      coloff, vcol0, pVt,
                                                      r1, r2, r3, Nout, relu);
    };

    // 1. embeddings
    embed_kernel<<<BN_ROWS, 128>>>(q, r, qry, M_emb, E_emb, Pmat);

    // 2. base MHA (Q from E, K/V from M, causal) + attn_w output
    lin(pEb, pWb + 0 * DD, bib,     nullptr, pQK, 1024, 0,   BIG, nullptr, nullptr, nullptr, BN_ROWS, 512, 0);   // Q
    lin(pMb, pWb + 1 * DD, bib + D, nullptr, pQK, 1024, 512, 512, nullptr, nullptr, nullptr, BN_ROWS, 1024, 0);  // K + Vt
    scores_bf16_kernel<<<dim3(4, 4, 128), 256>>>(pQK, pS16, 1);
    softmax_base_kernel<<<BN_ROWS, 256>>>(pS16, pP16, out + BN_ROWS);
    pv_bf16_kernel<<<dim3(1, 4, 128), 256>>>(pP16, pVt, pO16, 1);
    lin(pO16, pWb + 12 * DD, bob, pT1, nullptr, 0, 0, BIG, nullptr, nullptr, nullptr, BN_ROWS, 512, 0);
    ln_kernel<<<BN_ROWS, 128>>>(pT1, pM, pE, ln1g, ln1b, pSb, pSb16);

    // 3. local MHA on last LW tokens (causal) -- SIMT path
    pack_loc_kernel<<<(BLW_ROWS * D) / 256, 256>>>();
    lin(pT2b, pWb + 3 * DD, lib, nullptr, pQK, 1536, 0, BIG, nullptr, nullptr, nullptr, BLW_ROWS, 1536, 0);  // fused QKV
    local_scores_kernel<<<dim3(1, 1, 128), 256>>>(pQK, pP32);
    softmax_f32_kernel<<<B * H * LW, 128>>>(pP32, LW, LW, 1);
    local_pv_kernel<<<dim3(1, 1, 128), 256>>>(pP32, pQK, pO16);
    lin(pO16, pWb + 13 * DD, lob, pT1, nullptr, 0, 0, BIG, nullptr, nullptr, nullptr, BLW_ROWS, 512, 0);
    expand_local_kernel<<<(BN_ROWS * D) / 256, 256>>>(pT1);

    // 4. global MHA (self on S_base, causal) -- fused QKV
    lin(pSb16, pWb + 6 * DD, gib, nullptr, pQK, 1024, 0, 1024, nullptr, nullptr, nullptr, BN_ROWS, 1536, 0);
    scores_bf16_kernel<<<dim3(4, 4, 128), 256>>>(pQK, pS16, 1);
    softmax_bf16_kernel<<<B * H * N, 128>>>(pS16, pP16, 1);
    pv_bf16_kernel<<<dim3(1, 4, 128), 256>>>(pP16, pVt, pO16, 1);
    lin(pO16, pWb + 14 * DD, gob, pSg, nullptr, 0, 0, BIG, nullptr, nullptr, nullptr, BN_ROWS, 512, 0);

    // 5. cross MHA (Q from S_base, K/V from S_local, no mask)
    lin(pSb16, pWb + 9 * DD,  cib,     nullptr, pQK, 1024, 0,   BIG, nullptr, nullptr, nullptr, BN_ROWS, 512, 0);
    lin(pSl16, pWb + 10 * DD, cib + D, nullptr, pQK, 1024, 512, 512, nullptr, nullptr, nullptr, BN_ROWS, 1024, 0);
    scores_bf16_kernel<<<dim3(4, 4, 128), 256>>>(pQK, pS16, 0);
    softmax_bf16_kernel<<<B * H * N, 128>>>(pS16, pP16, 0);
    pv_bf16_kernel<<<dim3(1, 4, 128), 256>>>(pP16, pVt, pO16, 0);
    // cross out-proj with fused S = Sbase + Slocal + Sglob + Scross
    lin(pO16, pWb + 15 * DD, cob, pSs, pSs16, 512, 0, BIG, pSb, pSl, pSg, BN_ROWS, 512, 0);

    // 6. FFN + LN2 + head
    lin(pSs16, pWb + 16 * DD, b1, nullptr, pF16, 512, 0, BIG, nullptr, nullptr, nullptr, BN_ROWS, 512, 1);  // relu
    lin(pF16,  pWb + 17 * DD, b2, pT2, nullptr, 0, 0, BIG, nullptr, nullptr, nullptr, BN_ROWS, 512, 0);
    ln_kernel<<<BN_ROWS, 128>>>(pT2, pSs, nullptr, ln2g, ln2b, pT1, nullptr);
    pred_kernel<<<BN_ROWS, 128>>>(pT1, pw, pb, out);
}

// round 11
// speedup vs baseline: 1.4173x; 1.3650x over previous
#include <cuda_runtime.h>
#include <cuda_bf16.h>
#include <math.h>
#include <stdint.h>

// ---------------------------------------------------------------------------
// Problem constants
// ---------------------------------------------------------------------------
static constexpr int B  = 16;
static constexpr int N  = 512;
static constexpr int D  = 512;
static constexpr int H  = 8;
static constexpr int HD = 64;
static constexpr int LW = 64;
static constexpr int NQ = 10000;
static constexpr int BN_ROWS  = B * N;    // 8192
static constexpr int BLW_ROWS = B * LW;   // 1024
static constexpr int DD = D * D;          // 262144 = 2^18

typedef __nv_bfloat16 bf16;
typedef __nv_bfloat162 bf162;

// ---------------------------------------------------------------------------
// Scratch (static device globals)
// ---------------------------------------------------------------------------
__device__ float g_M     [BN_ROWS * D];
__device__ float g_E     [BN_ROWS * D];
__device__ float g_T1    [BN_ROWS * D];
__device__ float g_T2    [BN_ROWS * D];
__device__ float g_Sbase [BN_ROWS * D];
__device__ float g_Slocal[BN_ROWS * D];
__device__ float g_Sglob [BN_ROWS * D];
__device__ float g_Ssum  [BN_ROWS * D];
__device__ float g_P32   [B * H * LW * LW];    // local probs scratch (f32)
__device__ bf16 g_Mb    [BN_ROWS * D];
__device__ bf16 g_Eb    [BN_ROWS * D];
__device__ bf16 g_QK    [BN_ROWS * 1024];      // base/glob packed Q|K
__device__ bf16 g_QKx   [BN_ROWS * 1024];      // cross packed Q|K
__device__ bf16 g_QKloc [BLW_ROWS * 1536];     // local packed QKV
__device__ bf16 g_Vt    [B * H * HD * N];      // V transposed per (b,h): [e][j]
__device__ bf16 g_S16   [B * H * N * N];       // scores
__device__ bf16 g_P16   [B * H * N * N];       // probs
__device__ bf16 g_O16   [BN_ROWS * D];         // attention output (pre out-proj)
__device__ bf16 g_O16loc[BLW_ROWS * D];
__device__ bf16 g_Sb16  [BN_ROWS * D];
__device__ bf16 g_Sl16  [BN_ROWS * D];
__device__ bf16 g_Ss16  [BN_ROWS * D];
__device__ bf16 g_F16   [BN_ROWS * D];
__device__ bf16 g_T2b   [BLW_ROWS * D];
__device__ bf16 g_Wb    [18 * DD];             // bf16 weights

// ---------------------------------------------------------------------------
// MMA / ldmatrix helpers
// ---------------------------------------------------------------------------
__device__ __forceinline__ void cp_async16(uint32_t dst, const void* src) {
    asm volatile("cp.async.cg.shared.global [%0], [%1], 16;" :: "r"(dst), "l"(src));
}
__device__ __forceinline__ void cp_commit() {
    asm volatile("cp.async.commit_group;");
}
__device__ __forceinline__ void mma_bf16(float c[4], uint32_t a0, uint32_t a1,
                                         uint32_t a2, uint32_t a3,
                                         uint32_t b0, uint32_t b1) {
    asm volatile(
        "mma.sync.aligned.m16n8k16.row.col.f32.bf16.bf16.f32 "
        "{%0,%1,%2,%3}, {%4,%5,%6,%7}, {%8,%9}, {%0,%1,%2,%3};"
        : "+f"(c[0]), "+f"(c[1]), "+f"(c[2]), "+f"(c[3])
        : "r"(a0), "r"(a1), "r"(a2), "r"(a3), "r"(b0), "r"(b1));
}
__device__ __forceinline__ void ldsm_x4(uint32_t& r0, uint32_t& r1,
                                        uint32_t& r2, uint32_t& r3, uint32_t addr) {
    asm volatile("ldmatrix.sync.aligned.m8n8.x4.shared.b16 {%0,%1,%2,%3}, [%4];"
                 : "=r"(r0), "=r"(r1), "=r"(r2), "=r"(r3) : "r"(addr));
}

static constexpr int L2STR = 36;                     // u32 per row (64 bf16 + pad)
static constexpr int L2_STAGE_U32 = 256 * L2STR;
static constexpr int L2_SMEM_BYTES = 3 * L2_STAGE_U32 * 4;   // 110592
static constexpr int LSTR = 20;                      // u32 per row (32 bf16 + pad)
static constexpr int PV_STAGE_U32 = 192 * LSTR;

// ---------------------------------------------------------------------------
// Weight conversion
// ---------------------------------------------------------------------------
struct WSrc { const float* p[18]; };
__global__ void cvt_weights_kernel(WSrc ws) {
    for (int i = blockIdx.x * blockDim.x + threadIdx.x; i < 18 * DD;
         i += gridDim.x * blockDim.x) {
        int s = i >> 18;
        int off = i & (DD - 1);
        g_Wb[i] = __float2bfloat16(ws.p[s][off]);
    }
}

// ---------------------------------------------------------------------------
// Embedding gather
// ---------------------------------------------------------------------------
__global__ void embed_kernel(const int* __restrict__ q, const int* __restrict__ r,
                             const int* __restrict__ qry,
                             const float* __restrict__ M_emb,
                             const float* __restrict__ E_emb,
                             const float* __restrict__ P) {
    int row = blockIdx.x;
    int n = row & (N - 1);
    int x = q[row] + NQ * r[row];
    int e = qry[row];
    const float* msrc = M_emb + (size_t)x * D;
    const float* esrc = E_emb + (size_t)e * D;
    const float* psrc = P + (size_t)n * D;
    size_t base = (size_t)row * D;
    for (int d = threadIdx.x; d < D; d += blockDim.x) {
        float mv = msrc[d] + psrc[d];
        float ev = esrc[d];
        g_M[base + d] = mv;  g_Mb[base + d] = __float2bfloat16(mv);
        g_E[base + d] = ev;  g_Eb[base + d] = __float2bfloat16(ev);
    }
}

// ---------------------------------------------------------------------------
// BF16 tensor-core GEMM: ldmatrix fragments, BK=64, 3-stage pipeline.
// ---------------------------------------------------------------------------
__global__ __launch_bounds__(256, 2)
void linear_bf16_kernel(const bf16* __restrict__ A, const bf16* __restrict__ W,
                        const float* __restrict__ bias,
                        float* __restrict__ C32,
                        bf16* __restrict__ C16, int ldc16, int coloff,
                        int vcol0, bf16* __restrict__ Vt,
                        const float* __restrict__ res1,
                        const float* __restrict__ res2,
                        const float* __restrict__ res3,
                        int Nout, int relu) {
    extern __shared__ uint32_t sm[];
    const int tid  = threadIdx.x;
    const int lane = tid & 31;
    const int w    = tid >> 5;
    const int g    = lane >> 2;
    const int tg   = lane & 3;
    const int wm0  = (w >> 2) * 64;
    const int wn0  = (w & 3) * 32;
    const int m0   = blockIdx.y * 128;
    const int n0   = blockIdx.x * 128;
    const uint32_t sm_u32 = (uint32_t)__cvta_generic_to_shared(sm);

    const int qr = lane & 7, qm = (lane >> 3) & 1, qk = lane >> 4;
    const int q2 = lane >> 3, rB = lane & 7;
    uint32_t aoff[4], boff[2];
#pragma unroll
    for (int tm = 0; tm < 4; tm++)
        aoff[tm] = (uint32_t)(((wm0 + tm * 16 + qm * 8 + qr) * L2STR + qk * 4) * 4);
#pragma unroll
    for (int p = 0; p < 2; p++)
        boff[p] = (uint32_t)(((wn0 + (p * 2 + (q2 >> 1)) * 8 + rB) * L2STR + (q2 & 1) * 4) * 4);

    auto load_tile = [&](int t, int s) {
        const int k0 = t * 64;
        uint32_t base = sm_u32 + (uint32_t)(s * L2_STAGE_U32) * 4u;
#pragma unroll
        for (int i = 0; i < 4; i++) {
            int e = tid + i * 256;
            int row = e >> 3, ch = e & 7;
            cp_async16(base + (uint32_t)(row * L2STR + ch * 4) * 4u,
                       &A[(size_t)(m0 + row) * 512 + k0 + ch * 8]);
        }
        base += (uint32_t)(128 * L2STR) * 4u;
#pragma unroll
        for (int i = 0; i < 4; i++) {
            int e = tid + i * 256;
            int row = e >> 3, ch = e & 7;
            cp_async16(base + (uint32_t)(row * L2STR + ch * 4) * 4u,
                       &W[(size_t)(n0 + row) * 512 + k0 + ch * 8]);
        }
        cp_commit();
    };

    float acc[4][4][4] = {};
    const int NT = 8;    // 512 / 64
    load_tile(0, 0);
    load_tile(1, 1);
    for (int it = 0; it < NT; ++it) {
        if (it + 2 < NT) {
            load_tile(it + 2, (it + 2) % 3);
            asm volatile("cp.async.wait_group 2;");
        } else if (it + 1 < NT) {
            asm volatile("cp.async.wait_group 1;");
        } else {
            asm volatile("cp.async.wait_group 0;");
        }
        __syncthreads();
        const uint32_t baseA = sm_u32 + (uint32_t)((it % 3) * L2_STAGE_U32) * 4u;
        const uint32_t baseW = baseA + (uint32_t)(128 * L2STR) * 4u;
#pragma unroll
        for (int ks = 0; ks < 4; ks++) {
            const uint32_t kb = (uint32_t)(ks * 32);
            uint32_t a[4][4], bq[4][2];
#pragma unroll
            for (int tm = 0; tm < 4; tm++)
                ldsm_x4(a[tm][0], a[tm][1], a[tm][2], a[tm][3], baseA + aoff[tm] + kb);
#pragma unroll
            for (int p = 0; p < 2; p++)
                ldsm_x4(bq[p * 2][0], bq[p * 2][1], bq[p * 2 + 1][0], bq[p * 2 + 1][1],
                        baseW + boff[p] + kb);
#pragma unroll
            for (int tm = 0; tm < 4; tm++)
#pragma unroll
                for (int tn = 0; tn < 4; tn++)
                    mma_bf16(acc[tm][tn], a[tm][0], a[tm][1], a[tm][2], a[tm][3],
                             bq[tn][0], bq[tn][1]);
        }
        __syncthreads();
    }

#pragma unroll
    for (int tm = 0; tm < 4; tm++) {
        int r0 = m0 + wm0 + tm * 16 + g;
        int r1 = r0 + 8;
#pragma unroll
        for (int tn = 0; tn < 4; tn++) {
            int c = n0 + wn0 + tn * 8 + tg * 2;
            float b0 = bias[c], b1 = bias[c + 1];
            float v00 = acc[tm][tn][0] + b0;
            float v01 = acc[tm][tn][1] + b1;
            float v10 = acc[tm][tn][2] + b0;
            float v11 = acc[tm][tn][3] + b1;
            size_t o0 = (size_t)r0 * 512 + c;
            size_t o1 = (size_t)r1 * 512 + c;
            if (res1) { v00 += res1[o0]; v01 += res1[o0 + 1]; v10 += res1[o1]; v11 += res1[o1 + 1]; }
            if (res2) { v00 += res2[o0]; v01 += res2[o0 + 1]; v10 += res2[o1]; v11 += res2[o1 + 1]; }
            if (res3) { v00 += res3[o0]; v01 += res3[o0 + 1]; v10 += res3[o1]; v11 += res3[o1 + 1]; }
            if (relu) { v00 = fmaxf(v00, 0.f); v01 = fmaxf(v01, 0.f);
                        v10 = fmaxf(v10, 0.f); v11 = fmaxf(v11, 0.f); }
            if (C32) {
                *(float2*)&C32[o0] = make_float2(v00, v01);
                *(float2*)&C32[o1] = make_float2(v10, v11);
            }
            if (C16) {
                if (c >= vcol0) {
                    int ve = c - vcol0;
                    int h = ve >> 6, e0 = ve & 63;
                    int b_ = r0 >> 9;
                    int t0 = r0 & 511, t1 = r1 & 511;
                    bf16* vrow0 = Vt + ((size_t)((b_ * H + h) * HD + e0)) * N;
                    bf16* vrow1 = vrow0 + N;
                    vrow0[t0] = __float2bfloat16(v00);
                    vrow1[t0] = __float2bfloat16(v01);
                    vrow0[t1] = __float2bfloat16(v10);
                    vrow1[t1] = __float2bfloat16(v11);
                } else {
                    *(bf162*)&C16[(size_t)r0 * ldc16 + coloff + c] =
                        __floats2bfloat162_rn(v00, v01);
                    *(bf162*)&C16[(size_t)r1 * ldc16 + coloff + c] =
                        __floats2bfloat162_rn(v10, v11);
                }
            }
        }
    }
}

// ---------------------------------------------------------------------------
// BF16 attention scores, single-stage K=64, ldmatrix fragments.
// ---------------------------------------------------------------------------
__global__ __launch_bounds__(256, 2)
void scores_bf16_kernel(const bf16* __restrict__ QK, bf16* __restrict__ S16,
                        int causal) {
    const int z = blockIdx.z, b = z >> 3, h = z & 7;
    const int i0 = blockIdx.y * 128, j0 = blockIdx.x * 128;
    if (causal && j0 > i0 + 127) return;
    const bf16* Qb = QK + (size_t)(b * N) * 1024 + h * HD;
    const bf16* Kb = Qb + 512;
    bf16* Sb = S16 + (size_t)z * N * N;

    __shared__ uint32_t sm[256 * L2STR];
    const int tid  = threadIdx.x;
    const int lane = tid & 31;
    const int w    = tid >> 5;
    const int g    = lane >> 2;
    const int tg   = lane & 3;
    const int wm0  = (w >> 2) * 64;
    const int wn0  = (w & 3) * 32;
    const uint32_t sm_u32 = (uint32_t)__cvta_generic_to_shared(sm);
    const uint32_t baseQ = sm_u32;
    const uint32_t baseK = sm_u32 + (uint32_t)(128 * L2STR) * 4u;

#pragma unroll
    for (int i = 0; i < 4; i++) {
        int e = tid + i * 256;
        int row = e >> 3, ch = e & 7;
        cp_async16(baseQ + (uint32_t)(row * L2STR + ch * 4) * 4u,
                   &Qb[(size_t)(i0 + row) * 1024 + ch * 8]);
    }
#pragma unroll
    for (int i = 0; i < 4; i++) {
        int e = tid + i * 256;
        int row = e >> 3, ch = e & 7;
        cp_async16(baseK + (uint32_t)(row * L2STR + ch * 4) * 4u,
                   &Kb[(size_t)(j0 + row) * 1024 + ch * 8]);
    }
    cp_commit();
    asm volatile("cp.async.wait_group 0;");
    __syncthreads();

    const int qr = lane & 7, qm = (lane >> 3) & 1, qk = lane >> 4;
    const int q2 = lane >> 3, rB = lane & 7;
    uint32_t aoff[4], boff[2];
#pragma unroll
    for (int tm = 0; tm < 4; tm++)
        aoff[tm] = (uint32_t)(((wm0 + tm * 16 + qm * 8 + qr) * L2STR + qk * 4) * 4);
#pragma unroll
    for (int p = 0; p < 2; p++)
        boff[p] = (uint32_t)(((wn0 + (p * 2 + (q2 >> 1)) * 8 + rB) * L2STR + (q2 & 1) * 4) * 4);

    float acc[4][4][4] = {};
#pragma unroll
    for (int ks = 0; ks < 4; ks++) {
        const uint32_t kb = (uint32_t)(ks * 32);
        uint32_t a[4][4], bq[4][2];
#pragma unroll
        for (int tm = 0; tm < 4; tm++)
            ldsm_x4(a[tm][0], a[tm][1], a[tm][2], a[tm][3], baseQ + aoff[tm] + kb);
#pragma unroll
        for (int p = 0; p < 2; p++)
            ldsm_x4(bq[p * 2][0], bq[p * 2][1], bq[p * 2 + 1][0], bq[p * 2 + 1][1],
                    baseK + boff[p] + kb);
#pragma unroll
        for (int tm = 0; tm < 4; tm++)
#pragma unroll
            for (int tn = 0; tn < 4; tn++)
                mma_bf16(acc[tm][tn], a[tm][0], a[tm][1], a[tm][2], a[tm][3],
                         bq[tn][0], bq[tn][1]);
    }

#pragma unroll
    for (int tm = 0; tm < 4; tm++) {
        int r0 = i0 + wm0 + tm * 16 + g;
        int r1 = r0 + 8;
#pragma unroll
        for (int tn = 0; tn < 4; tn++) {
            int c = j0 + wn0 + tn * 8 + tg * 2;
            *(bf162*)&Sb[(size_t)r0 * N + c] =
                __floats2bfloat162_rn(acc[tm][tn][0] * 0.125f, acc[tm][tn][1] * 0.125f);
            *(bf162*)&Sb[(size_t)r1 * N + c] =
                __floats2bfloat162_rn(acc[tm][tn][2] * 0.125f, acc[tm][tn][3] * 0.125f);
        }
    }
}

// ---------------------------------------------------------------------------
// BF16 PV: O16 = P16 @ Vt^T, 128x64 tile, BK=32, ldmatrix fragments.
// ---------------------------------------------------------------------------
__global__ __launch_bounds__(256, 2)
void pv_bf16_kernel(const bf16* __restrict__ P16, const bf16* __restrict__ Vt,
                    bf16* __restrict__ O16, int causal) {
    const int z = blockIdx.z, b = z >> 3, h = z & 7;
    const int i0 = blockIdx.y * 128;
    const bf16* Pb  = P16 + (size_t)z * N * N;
    const bf16* Vtz = Vt + (size_t)z * HD * N;
    bf16* Ob = O16 + (size_t)(b * N) * 512 + h * HD;

    __shared__ uint32_t sm[2 * PV_STAGE_U32];
    const int tid  = threadIdx.x;
    const int lane = tid & 31;
    const int w    = tid >> 5;
    const int g    = lane >> 2;
    const int tg   = lane & 3;
    const int wm0  = (w >> 1) * 32;
    const int wn0  = (w & 1) * 32;
    const uint32_t sm_u32 = (uint32_t)__cvta_generic_to_shared(sm);

    const int qr = lane & 7, qm = (lane >> 3) & 1, qk = lane >> 4;
    const int q2 = lane >> 3, rB = lane & 7;
    uint32_t aoff[2], boff[2];
#pragma unroll
    for (int tm = 0; tm < 2; tm++)
        aoff[tm] = (uint32_t)(((wm0 + tm * 16 + qm * 8 + qr) * LSTR + qk * 4) * 4);
#pragma unroll
    for (int p = 0; p < 2; p++)
        boff[p] = (uint32_t)(((wn0 + (p * 2 + (q2 >> 1)) * 8 + rB) * LSTR + (q2 & 1) * 4) * 4);

    auto load_tile = [&](int t, int s) {
        const int k0 = t * 32;
        uint32_t base = sm_u32 + (uint32_t)(s * PV_STAGE_U32) * 4u;
#pragma unroll
        for (int i = 0; i < 2; i++) {
            int e = tid + i * 256;
            int row = e >> 2, ch = e & 3;
            cp_async16(base + (uint32_t)(row * LSTR + ch * 4) * 4u,
                       &Pb[(size_t)(i0 + row) * N + k0 + ch * 8]);
        }
        base += (uint32_t)(128 * LSTR) * 4u;
        {
            int row = tid >> 2, ch = tid & 3;
            cp_async16(base + (uint32_t)(row * LSTR + ch * 4) * 4u,
                       &Vtz[(size_t)row * N + k0 + ch * 8]);
        }
        cp_commit();
    };

    float acc[2][4][4] = {};
    const int kend = causal ? (i0 + 128) : N;
    const int NT = kend / 32;
    load_tile(0, 0);
    for (int it = 0; it < NT; ++it) {
        if (it + 1 < NT) { load_tile(it + 1, (it + 1) & 1);
                           asm volatile("cp.async.wait_group 1;"); }
        else             { asm volatile("cp.async.wait_group 0;"); }
        __syncthreads();
        const uint32_t baseP = sm_u32 + (uint32_t)((it & 1) * PV_STAGE_U32) * 4u;
        const uint32_t baseV = baseP + (uint32_t)(128 * LSTR) * 4u;
#pragma unroll
        for (int ks = 0; ks < 2; ks++) {
            const uint32_t kb = (uint32_t)(ks * 32);
            uint32_t a[2][4], bq[4][2];
#pragma unroll
            for (int tm = 0; tm < 2; tm++)
                ldsm_x4(a[tm][0], a[tm][1], a[tm][2], a[tm][3], baseP + aoff[tm] + kb);
#pragma unroll
            for (int p = 0; p < 2; p++)
                ldsm_x4(bq[p * 2][0], bq[p * 2][1], bq[p * 2 + 1][0], bq[p * 2 + 1][1],
                        baseV + boff[p] + kb);
#pragma unroll
            for (int tm = 0; tm < 2; tm++)
#pragma unroll
                for (int tn = 0; tn < 4; tn++)
                    mma_bf16(acc[tm][tn], a[tm][0], a[tm][1], a[tm][2], a[tm][3],
                             bq[tn][0], bq[tn][1]);
        }
        __syncthreads();
    }

#pragma unroll
    for (int tm = 0; tm < 2; tm++) {
        int r0 = i0 + wm0 + tm * 16 + g;
        int r1 = r0 + 8;
#pragma unroll
        for (int tn = 0; tn < 4; tn++) {
            int c = wn0 + tn * 8 + tg * 2;
            *(bf162*)&Ob[(size_t)r0 * 512 + c] =
                __floats2bfloat162_rn(acc[tm][tn][0], acc[tm][tn][1]);
            *(bf162*)&Ob[(size_t)r1 * 512 + c] =
                __floats2bfloat162_rn(acc[tm][tn][2], acc[tm][tn][3]);
        }
    }
}

// ---------------------------------------------------------------------------
// Fused BASE softmax + head-mean, warp-per-head. One block per (b,i).
// ---------------------------------------------------------------------------
__global__ void softmax_base_warp(const bf16* __restrict__ S16,
                                  bf16* __restrict__ P16,
                                  float* __restrict__ outw) {
    int row = blockIdx.x;                 // b*N + i
    int b = row >> 9, i = row & (N - 1);
    int wid = threadIdx.x >> 5, lane = threadIdx.x & 31;
    int lim = i + 1;
    __shared__ float pm[8][512];
    size_t off = ((size_t)((b * H + wid) * N) + i) * N;
    const bf16* Sr = S16 + off;
    bf16* Pr = P16 + off;
    float v[16];
    float mx = -1e30f;
#pragma unroll
    for (int c = 0; c < 16; c++) {
        int j = lane + c * 32;
        v[c] = (j < lim) ? __bfloat162float(Sr[j]) : -1e30f;
        mx = fmaxf(mx, v[c]);
    }
#pragma unroll
    for (int s = 16; s > 0; s >>= 1) mx = fmaxf(mx, __shfl_xor_sync(~0u, mx, s));
    float sum = 0.f;
#pragma unroll
    for (int c = 0; c < 16; c++) {
        int j = lane + c * 32;
        float e = (j < lim) ? __expf(v[c] - mx) : 0.f;
        v[c] = e; sum += e;
    }
#pragma unroll
    for (int s = 16; s > 0; s >>= 1) sum += __shfl_xor_sync(~0u, sum, s);
    float inv = 1.f / sum;
#pragma unroll
    for (int c = 0; c < 16; c++) {
        int j = lane + c * 32;
        float p = v[c] * inv;
        Pr[j] = __float2bfloat16(p);
        pm[wid][j] = p;
    }
    __syncthreads();
    size_t orow = (size_t)row * N;
    for (int t = threadIdx.x; t < N; t += 256) {
        float s = 0.f;
#pragma unroll
        for (int h = 0; h < H; h++) s += pm[h][t];
        outw[orow + t] = s * 0.125f;
    }
}

// ---------------------------------------------------------------------------
// Warp-per-row softmax (glob/cross). 8 rows per block.
// ---------------------------------------------------------------------------
__global__ void softmax_warp_kernel(const bf16* __restrict__ S16,
                                    bf16* __restrict__ P16, int causal) {
    int row = blockIdx.x * 8 + (threadIdx.x >> 5);
    int lane = threadIdx.x & 31;
    int i = row & (N - 1);
    int lim = causal ? (i + 1) : N;
    const bf16* Sr = S16 + (size_t)row * N;
    bf16* Pr = P16 + (size_t)row * N;
    float v[16];
    float mx = -1e30f;
#pragma unroll
    for (int c = 0; c < 16; c++) {
        int j = lane + c * 32;
        v[c] = (j < lim) ? __bfloat162float(Sr[j]) : -1e30f;
        mx = fmaxf(mx, v[c]);
    }
#pragma unroll
    for (int s = 16; s > 0; s >>= 1) mx = fmaxf(mx, __shfl_xor_sync(~0u, mx, s));
    float sum = 0.f;
#pragma unroll
    for (int c = 0; c < 16; c++) {
        int j = lane + c * 32;
        float e = (j < lim) ? __expf(v[c] - mx) : 0.f;
        v[c] = e; sum += e;
    }
#pragma unroll
    for (int s = 16; s > 0; s >>= 1) sum += __shfl_xor_sync(~0u, sum, s);
    float inv = 1.f / sum;
#pragma unroll
    for (int c = 0; c < 16; c++) {
        int j = lane + c * 32;
        Pr[j] = __float2bfloat16(v[c] * inv);
    }
}

// f32 softmax (local path, Nk=64)
__global__ void softmax_f32_kernel(float* __restrict__ S, int Nq, int Nk, int causal) {
    int row = blockIdx.x;
    int i = row % Nq;
    float* Sr = S + (size_t)row * Nk;
    int lim = causal ? (i + 1) : Nk;
    int tid = threadIdx.x;
    float v[4];
    float mx = -1e30f;
#pragma unroll
    for (int c = 0; c < 4; c++) {
        int j = tid + c * 128;
        v[c] = (j < lim && j < Nk) ? Sr[j] : -1e30f;
        mx = fmaxf(mx, v[c]);
    }
    __shared__ float red[128];
    red[tid] = mx; __syncthreads();
    for (int s = 64; s > 0; s >>= 1) { if (tid < s) red[tid] = fmaxf(red[tid], red[tid + s]); __syncthreads(); }
    mx = red[0]; __syncthreads();
    float sum = 0.f;
#pragma unroll
    for (int c = 0; c < 4; c++) {
        int j = tid + c * 128;
        float e = (j < lim && j < Nk) ? __expf(v[c] - mx) : 0.f;
        v[c] = e; sum += e;
    }
    red[tid] = sum; __syncthreads();
    for (int s = 64; s > 0; s >>= 1) { if (tid < s) red[tid] += red[tid + s]; __syncthreads(); }
    float inv = 1.f / red[0];
#pragma unroll
    for (int c = 0; c < 4; c++) {
        int j = tid + c * 128;
        if (j < Nk) Sr[j] = v[c] * inv;
    }
}

// ---------------------------------------------------------------------------
// SIMT local attention (LW=64)
// ---------------------------------------------------------------------------
__global__ void local_scores_kernel(const bf16* __restrict__ QK, float* __restrict__ S) {
    int z = blockIdx.z, b = z >> 3, h = z & 7;
    const bf16* Qb = QK + (size_t)(b * LW) * 1536 + h * HD;
    const bf16* Kb = Qb + 512;
    float* Sb = S + (size_t)z * LW * LW;
    __shared__ float Qs[16][64];
    __shared__ float Ks[16][64];
    int tid = threadIdx.x, tx = tid & 15, ty = tid >> 4;
    float acc[4][4] = {};
    for (int k0 = 0; k0 < HD; k0 += 16) {
        for (int idx = tid; idx < 64 * 16; idx += 256) {
            int i = idx >> 4, j = idx & 15;
            Qs[j][i] = __bfloat162float(Qb[(size_t)i * 1536 + k0 + j]);
            Ks[j][i] = __bfloat162float(Kb[(size_t)i * 1536 + k0 + j]);
        }
        __syncthreads();
#pragma unroll
        for (int k = 0; k < 16; k++) {
            float a[4], wv[4];
#pragma unroll
            for (int i = 0; i < 4; i++) a[i] = Qs[k][ty * 4 + i];
#pragma unroll
            for (int j = 0; j < 4; j++) wv[j] = Ks[k][tx * 4 + j];
#pragma unroll
            for (int i = 0; i < 4; i++)
#pragma unroll
                for (int j = 0; j < 4; j++) acc[i][j] += a[i] * wv[j];
        }
        __syncthreads();
    }
#pragma unroll
    for (int i = 0; i < 4; i++)
#pragma unroll
        for (int j = 0; j < 4; j++)
            Sb[(size_t)(ty * 4 + i) * LW + tx * 4 + j] = acc[i][j] * 0.125f;
}

__global__ void local_pv_kernel(const float* __restrict__ Pm, const bf16* __restrict__ QK,
                                bf16* __restrict__ O16) {
    int z = blockIdx.z, b = z >> 3, h = z & 7;
    const float* Pb = Pm + (size_t)z * LW * LW;
    const bf16* Vb = QK + (size_t)(b * LW) * 1536 + 1024 + h * HD;
    bf16* Ob = O16 + (size_t)(b * LW) * 512 + h * HD;
    __shared__ float Ps[64][17];
    __shared__ float Vs[16][64];
    int tid = threadIdx.x, tx = tid & 15, ty = tid >> 4;
    float acc[4][4] = {};
    for (int k0 = 0; k0 < LW; k0 += 16) {
        for (int idx = tid; idx < 64 * 16; idx += 256) {
            int i = idx >> 4, j = idx & 15;
            Ps[i][j] = Pb[(size_t)i * LW + k0 + j];
        }
        for (int idx = tid; idx < 16 * 64; idx += 256) {
            int k = idx >> 6, e = idx & 63;
            Vs[k][e] = __bfloat162float(Vb[(size_t)(k0 + k) * 1536 + e]);
        }
        __syncthreads();
#pragma unroll
        for (int k = 0; k < 16; k++) {
            float a[4], wv[4];
#pragma unroll
            for (int i = 0; i < 4; i++) a[i] = Ps[ty * 4 + i][k];
#pragma unroll
            for (int j = 0; j < 4; j++) wv[j] = Vs[k][tx * 4 + j];
#pragma unroll
            for (int i = 0; i < 4; i++)
#pragma unroll
                for (int j = 0; j < 4; j++) acc[i][j] += a[i] * wv[j];
        }
        __syncthreads();
    }
#pragma unroll
    for (int i = 0; i < 4; i++)
#pragma unroll
        for (int j = 0; j < 4; j++)
            Ob[(size_t)(ty * 4 + i) * 512 + tx * 4 + j] = __float2bfloat16(acc[i][j]);
}

// ---------------------------------------------------------------------------
// LayerNorm: out = LN(X + r1? + r2?) * g + b ; optional bf16 out + packed copy
// ---------------------------------------------------------------------------
__global__ void ln_kernel(const float* __restrict__ X, const float* __restrict__ r1,
                          const float* __restrict__ r2, const float* __restrict__ g,
                          const float* __restrict__ bvec, float* __restrict__ out,
                          bf16* __restrict__ out16, bf16* __restrict__ pack16) {
    int row = blockIdx.x;
    size_t base = (size_t)row * D;
    int tid = threadIdx.x;
    int n = row & (N - 1);
    int b = row >> 9;
    float v[4];
    float s = 0.f;
#pragma unroll
    for (int c = 0; c < 4; c++) {
        int d = tid + c * 128;
        float t = X[base + d];
        if (r1) t += r1[base + d];
        if (r2) t += r2[base + d];
        v[c] = t; s += t;
    }
    __shared__ float red[128];
    red[tid] = s; __syncthreads();
    for (int st = 64; st > 0; st >>= 1) { if (tid < st) red[tid] += red[tid + st]; __syncthreads(); }
    float mean = red[0] * (1.f / D);
    __syncthreads();
    float vs = 0.f;
#pragma unroll
    for (int c = 0; c < 4; c++) { float dl = v[c] - mean; vs += dl * dl; }
    red[tid] = vs; __syncthreads();
    for (int st = 64; st > 0; st >>= 1) { if (tid < st) red[tid] += red[tid + st]; __syncthreads(); }
    float inv = rsqrtf(red[0] * (1.f / D) + 1e-5f);
    bf16* prow = (pack16 && n >= N - LW)
               ? pack16 + ((size_t)(b * LW + (n - (N - LW)))) * D : nullptr;
#pragma unroll
    for (int c = 0; c < 4; c++) {
        int d = tid + c * 128;
        float o = (v[c] - mean) * inv * g[d] + bvec[d];
        out[base + d] = o;
        bf16 ob = __float2bfloat16(o);
        if (out16) out16[base + d] = ob;
        if (prow) prow[d] = ob;
    }
}

// ---------------------------------------------------------------------------
// Misc elementwise kernels
// ---------------------------------------------------------------------------
__global__ void expand_local_kernel(const float* __restrict__ packed) {
    size_t idx = (size_t)blockIdx.x * blockDim.x + threadIdx.x;
    int d = (int)(idx & (D - 1));
    int row = (int)(idx >> 9);
    int b = row >> 9;
    int n = row & (N - 1);
    float v = 0.f;
    if (n >= N - LW)
        v = packed[(((size_t)b * LW + (n - (N - LW))) << 9) + d];
    g_Slocal[idx] = v;
    g_Sl16[idx] = __float2bfloat16(v);
}

__global__ void pred_kernel(const float* __restrict__ F, const float* __restrict__ pw,
                            const float* __restrict__ pb, float* __restrict__ out) {
    int row = blockIdx.x;
    int tid = threadIdx.x;
    const float* x = F + (size_t)row * D;
    float s = 0.f;
    for (int d = tid; d < D; d += 128) s += x[d] * pw[d];
    __shared__ float red[128];
    red[tid] = s; __syncthreads();
    for (int st = 64; st > 0; st >>= 1) { if (tid < st) red[tid] += red[tid + st]; __syncthreads(); }
    if (tid == 0) out[row] = 1.f / (1.f + __expf(-(red[0] + pb[0])));
}

// ---------------------------------------------------------------------------
// Launch (multi-stream fork/join for graph-captured overlap)
// ---------------------------------------------------------------------------
extern "C" void kernel_launch(void* const* d_in, const int* in_sizes, int n_in,
                              void* d_out, int out_size) {
    (void)in_sizes; (void)n_in; (void)out_size;
    const int*   q     = (const int*)d_in[0];
    const int*   r     = (const int*)d_in[1];
    const int*   qry   = (const int*)d_in[2];
    const float* M_emb = (const float*)d_in[3];
    const float* E_emb = (const float*)d_in[4];
    const float* Pmat  = (const float*)d_in[5];
    const float* biw = (const float*)d_in[6];  const float* bib = (const float*)d_in[7];
    const float* bow = (const float*)d_in[8];  const float* bob = (const float*)d_in[9];
    const float* liw = (const float*)d_in[10]; const float* lib = (const float*)d_in[11];
    const float* low = (const float*)d_in[12]; const float* lob = (const float*)d_in[13];
    const float* giw = (const float*)d_in[14]; const float* gib = (const float*)d_in[15];
    const float* gow = (const float*)d_in[16]; const float* gob = (const float*)d_in[17];
    const float* ciw = (const float*)d_in[18]; const float* cib = (const float*)d_in[19];
    const float* cow = (const float*)d_in[20]; const float* cob = (const float*)d_in[21];
    const float* ln1g = (const float*)d_in[22]; const float* ln1b = (const float*)d_in[23];
    const float* w1 = (const float*)d_in[24];  const float* b1 = (const float*)d_in[25];
    const float* w2 = (const float*)d_in[26];  const float* b2 = (const float*)d_in[27];
    const float* ln2g = (const float*)d_in[28]; const float* ln2b = (const float*)d_in[29];
    const float* pw = (const float*)d_in[30];  const float* pb = (const float*)d_in[31];
    float* out = (float*)d_out;

    float *pM, *pE, *pT1, *pT2, *pSb, *pSl, *pSg, *pSs, *pP32;
    bf16 *pMb, *pEb, *pQK, *pQKx, *pQKloc, *pVt, *pS16, *pP16, *pO16, *pO16loc;
    bf16 *pSb16, *pSl16, *pSs16, *pF16, *pT2b, *pWb;
    cudaGetSymbolAddress((void**)&pM,   g_M);
    cudaGetSymbolAddress((void**)&pE,   g_E);
    cudaGetSymbolAddress((void**)&pT1,  g_T1);
    cudaGetSymbolAddress((void**)&pT2,  g_T2);
    cudaGetSymbolAddress((void**)&pSb,  g_Sbase);
    cudaGetSymbolAddress((void**)&pSl,  g_Slocal);
    cudaGetSymbolAddress((void**)&pSg,  g_Sglob);
    cudaGetSymbolAddress((void**)&pSs,  g_Ssum);
    cudaGetSymbolAddress((void**)&pP32, g_P32);
    cudaGetSymbolAddress((void**)&pMb,  g_Mb);
    cudaGetSymbolAddress((void**)&pEb,  g_Eb);
    cudaGetSymbolAddress((void**)&pQK,  g_QK);
    cudaGetSymbolAddress((void**)&pQKx, g_QKx);
    cudaGetSymbolAddress((void**)&pQKloc, g_QKloc);
    cudaGetSymbolAddress((void**)&pVt,  g_Vt);
    cudaGetSymbolAddress((void**)&pS16, g_S16);
    cudaGetSymbolAddress((void**)&pP16, g_P16);
    cudaGetSymbolAddress((void**)&pO16, g_O16);
    cudaGetSymbolAddress((void**)&pO16loc, g_O16loc);
    cudaGetSymbolAddress((void**)&pSb16, g_Sb16);
    cudaGetSymbolAddress((void**)&pSl16, g_Sl16);
    cudaGetSymbolAddress((void**)&pSs16, g_Ss16);
    cudaGetSymbolAddress((void**)&pF16, g_F16);
    cudaGetSymbolAddress((void**)&pT2b, g_T2b);
    cudaGetSymbolAddress((void**)&pWb,  g_Wb);

    static cudaStream_t s1 = nullptr, s2 = nullptr;
    static cudaEvent_t evFork, evCvt, evEmb, evBQ, evLn, evLoc, evXq;
    if (!s1) {
        cudaStreamCreateWithFlags(&s1, cudaStreamNonBlocking);
        cudaStreamCreateWithFlags(&s2, cudaStreamNonBlocking);
        cudaEventCreateWithFlags(&evFork, cudaEventDisableTiming);
        cudaEventCreateWithFlags(&evCvt, cudaEventDisableTiming);
        cudaEventCreateWithFlags(&evEmb, cudaEventDisableTiming);
        cudaEventCreateWithFlags(&evBQ, cudaEventDisableTiming);
        cudaEventCreateWithFlags(&evLn, cudaEventDisableTiming);
        cudaEventCreateWithFlags(&evLoc, cudaEventDisableTiming);
        cudaEventCreateWithFlags(&evXq, cudaEventDisableTiming);
        cudaFuncSetAttribute(linear_bf16_kernel,
                             cudaFuncAttributeMaxDynamicSharedMemorySize, L2_SMEM_BYTES);
    }

    WSrc ws;
    ws.p[0] = biw; ws.p[1] = biw + DD; ws.p[2] = biw + 2 * DD;
    ws.p[3] = liw; ws.p[4] = liw + DD; ws.p[5] = liw + 2 * DD;
    ws.p[6] = giw; ws.p[7] = giw + DD; ws.p[8] = giw + 2 * DD;
    ws.p[9] = ciw; ws.p[10] = ciw + DD; ws.p[11] = ciw + 2 * DD;
    ws.p[12] = bow; ws.p[13] = low; ws.p[14] = gow; ws.p[15] = cow;
    ws.p[16] = w1; ws.p[17] = w2;

    const int BIG = 1 << 30;
    auto lin = [&](cudaStream_t st, const bf16* A, const bf16* W, const float* bias,
                   float* C32, bf16* C16, int ldc16, int coloff, int vcol0,
                   const float* r1, const float* r2, const float* r3,
                   int Mrows, int Nout, int relu) {
        dim3 gdim(Nout / 128, Mrows / 128);
        linear_bf16_kernel<<<gdim, 256, L2_SMEM_BYTES, st>>>(A, W, bias, C32, C16, ldc16,
                                                             coloff, vcol0, pVt,
                                                             r1, r2, r3, Nout, relu);
    };

    // ---- fork: s1 joins capture ----
    cudaEventRecord(evFork, 0);
    cudaStreamWaitEvent(s1, evFork, 0);

    // s1: weight conversion    |  s0: embeddings
    cvt_weights_kernel<<<4608, 256, 0, s1>>>(ws);
    cudaEventRecord(evCvt, s1);
    embed_kernel<<<BN_ROWS, 128>>>(q, r, qry, M_emb, E_emb, Pmat);
    cudaEventRecord(evEmb, 0);

    // s1: base Q projection (needs embed + weights)
    cudaStreamWaitEvent(s1, evEmb, 0);
    lin(s1, pEb, pWb + 0 * DD, bib, nullptr, pQK, 1024, 0, BIG,
        nullptr, nullptr, nullptr, BN_ROWS, 512, 0);
    cudaEventRecord(evBQ, s1);

    // s0: base K + Vt (needs weights)
    cudaStreamWaitEvent(0, evCvt, 0);
    lin(0, pMb, pWb + 1 * DD, bib + D, nullptr, pQK, 1024, 512, 512,
        nullptr, nullptr, nullptr, BN_ROWS, 1024, 0);
    cudaStreamWaitEvent(0, evBQ, 0);

    // s0: base attention + out-proj + LN1 (LN also packs last LW rows -> T2b)
    scores_bf16_kernel<<<dim3(4, 4, 128), 256>>>(pQK, pS16, 1);
    softmax_base_warp<<<BN_ROWS, 256>>>(pS16, pP16, out + BN_ROWS);
    pv_bf16_kernel<<<dim3(1, 4, 128), 256>>>(pP16, pVt, pO16, 1);
    lin(0, pO16, pWb + 12 * DD, bob, pT1, nullptr, 0, 0, BIG,
        nullptr, nullptr, nullptr, BN_ROWS, 512, 0);
    ln_kernel<<<BN_ROWS, 128>>>(pT1, pM, pE, ln1g, ln1b, pSb, pSb16, pT2b);
    cudaEventRecord(evLn, 0);

    // s1: local MHA path (hidden under global path)
    cudaStreamWaitEvent(s1, evLn, 0);
    lin(s1, pT2b, pWb + 3 * DD, lib, nullptr, pQKloc, 1536, 0, BIG,
        nullptr, nullptr, nullptr, BLW_ROWS, 1536, 0);
    local_scores_kernel<<<dim3(1, 1, 128), 256, 0, s1>>>(pQKloc, pP32);
    softmax_f32_kernel<<<B * H * LW, 128, 0, s1>>>(pP32, LW, LW, 1);
    local_pv_kernel<<<dim3(1, 1, 128), 256, 0, s1>>>(pP32, pQKloc, pO16loc);
    lin(s1, pO16loc, pWb + 13 * DD, lob, pT1, nullptr, 0, 0, BIG,
        nullptr, nullptr, nullptr, BLW_ROWS, 512, 0);
    expand_local_kernel<<<(BN_ROWS * D) / 256, 256, 0, s1>>>(pT1);
    cudaEventRecord(evLoc, s1);

    // s2: cross Q projection (hidden under global path)
    cudaStreamWaitEvent(s2, evLn, 0);
    lin(s2, pSb16, pWb + 9 * DD, cib, nullptr, pQKx, 1024, 0, BIG,
        nullptr, nullptr, nullptr, BN_ROWS, 512, 0);
    cudaEventRecord(evXq, s2);

    // s0: global MHA (fused QKV)
    lin(0, pSb16, pWb + 6 * DD, gib, nullptr, pQK, 1024, 0, 1024,
        nullptr, nullptr, nullptr, BN_ROWS, 1536, 0);
    scores_bf16_kernel<<<dim3(4, 4, 128), 256>>>(pQK, pS16, 1);
    softmax_warp_kernel<<<(B * H * N) / 8, 256>>>(pS16, pP16, 1);
    pv_bf16_kernel<<<dim3(1, 4, 128), 256>>>(pP16, pVt, pO16, 1);
    lin(0, pO16, pWb + 14 * DD, gob, pSg, nullptr, 0, 0, BIG,
        nullptr, nullptr, nullptr, BN_ROWS, 512, 0);

    // s0: join local + crossQ, then cross MHA
    cudaStreamWaitEvent(0, evLoc, 0);
    cudaStreamWaitEvent(0, evXq, 0);
    lin(0, pSl16, pWb + 10 * DD, cib + D, nullptr, pQKx, 1024, 512, 512,
        nullptr, nullptr, nullptr, BN_ROWS, 1024, 0);
    scores_bf16_kernel<<<dim3(4, 4, 128), 256>>>(pQKx, pS16, 0);
    softmax_warp_kernel<<<(B * H * N) / 8, 256>>>(pS16, pP16, 0);
    pv_bf16_kernel<<<dim3(1, 4, 128), 256>>>(pP16, pVt, pO16, 0);
    // cross out-proj with fused S = Sbase + Slocal + Sglob + Scross
    lin(0, pO16, pWb + 15 * DD, cob, pSs, pSs16, 512, 0, BIG,
        pSb, pSl, pSg, BN_ROWS, 512, 0);

    // s0: FFN + LN2 + head
    lin(0, pSs16, pWb + 16 * DD, b1, nullptr, pF16, 512, 0, BIG,
        nullptr, nullptr, nullptr, BN_ROWS, 512, 1);
    lin(0, pF16, pWb + 17 * DD, b2, pT2, nullptr, 0, 0, BIG,
        nullptr, nullptr, nullptr, BN_ROWS, 512, 0);
    ln_kernel<<<BN_ROWS, 128>>>(pT2, pSs, nullptr, ln2g, ln2b, pT1, nullptr, nullptr);
    pred_kernel<<<BN_ROWS, 128>>>(pT1, pw, pb, out);
}

// round 14
// speedup vs baseline: 1.4270x; 1.0068x over previous
#include <cuda_runtime.h>
#include <cuda_bf16.h>
#include <math.h>
#include <stdint.h>

// ---------------------------------------------------------------------------
// Problem constants
// ---------------------------------------------------------------------------
static constexpr int B  = 16;
static constexpr int N  = 512;
static constexpr int D  = 512;
static constexpr int H  = 8;
static constexpr int HD = 64;
static constexpr int LW = 64;
static constexpr int NQ = 10000;
static constexpr int BN_ROWS  = B * N;    // 8192
static constexpr int BLW_ROWS = B * LW;   // 1024
static constexpr int DD = D * D;          // 262144 = 2^18

typedef __nv_bfloat16 bf16;
typedef __nv_bfloat162 bf162;

// ---------------------------------------------------------------------------
// Scratch (static device globals)
// ---------------------------------------------------------------------------
__device__ float g_M     [BN_ROWS * D];
__device__ float g_E     [BN_ROWS * D];
__device__ float g_T1    [BN_ROWS * D];
__device__ float g_T2    [BN_ROWS * D];
__device__ float g_Sbase [BN_ROWS * D];
__device__ float g_Slocal[BN_ROWS * D];
__device__ float g_Sglob [BN_ROWS * D];
__device__ float g_Ssum  [BN_ROWS * D];
__device__ float g_P32   [B * H * LW * LW];    // local probs scratch (f32)
__device__ bf16 g_Mb    [BN_ROWS * D];
__device__ bf16 g_Eb    [BN_ROWS * D];
__device__ bf16 g_QK    [BN_ROWS * 1024];      // base/glob packed Q|K
__device__ bf16 g_QKx   [BN_ROWS * 1024];      // cross packed Q|K
__device__ bf16 g_QKloc [BLW_ROWS * 1536];     // local packed QKV
__device__ bf16 g_Vt    [B * H * HD * N];      // V^T per (b,h) (base/glob)
__device__ bf16 g_Vtx   [B * H * HD * N];      // V^T per (b,h) (cross)
__device__ bf16 g_S16   [B * H * N * N];       // scores (base/glob)
__device__ bf16 g_P16   [B * H * N * N];       // probs (base/glob)
__device__ bf16 g_S16x  [B * H * N * N];       // scores (cross)
__device__ bf16 g_P16x  [B * H * N * N];       // probs (cross)
__device__ bf16 g_O16   [BN_ROWS * D];         // attn out (base/glob)
__device__ bf16 g_O16x  [BN_ROWS * D];         // attn out (cross)
__device__ bf16 g_O16loc[BLW_ROWS * D];
__device__ bf16 g_Sb16  [BN_ROWS * D];
__device__ bf16 g_Sl16  [BN_ROWS * D];
__device__ bf16 g_Ss16  [BN_ROWS * D];
__device__ bf16 g_F16   [BN_ROWS * D];
__device__ bf16 g_T2b   [BLW_ROWS * D];
__device__ bf16 g_Wb    [18 * DD];             // bf16 weights

// ---------------------------------------------------------------------------
// MMA / ldmatrix helpers
// ---------------------------------------------------------------------------
__device__ __forceinline__ void cp_async16(uint32_t dst, const void* src) {
    asm volatile("cp.async.cg.shared.global [%0], [%1], 16;" :: "r"(dst), "l"(src));
}
__device__ __forceinline__ void cp_commit() {
    asm volatile("cp.async.commit_group;");
}
__device__ __forceinline__ void mma_bf16(float c[4], uint32_t a0, uint32_t a1,
                                         uint32_t a2, uint32_t a3,
                                         uint32_t b0, uint32_t b1) {
    asm volatile(
        "mma.sync.aligned.m16n8k16.row.col.f32.bf16.bf16.f32 "
        "{%0,%1,%2,%3}, {%4,%5,%6,%7}, {%8,%9}, {%0,%1,%2,%3};"
        : "+f"(c[0]), "+f"(c[1]), "+f"(c[2]), "+f"(c[3])
        : "r"(a0), "r"(a1), "r"(a2), "r"(a3), "r"(b0), "r"(b1));
}
__device__ __forceinline__ void ldsm_x4(uint32_t& r0, uint32_t& r1,
                                        uint32_t& r2, uint32_t& r3, uint32_t addr) {
    asm volatile("ldmatrix.sync.aligned.m8n8.x4.shared.b16 {%0,%1,%2,%3}, [%4];"
                 : "=r"(r0), "=r"(r1), "=r"(r2), "=r"(r3) : "r"(addr));
}

static constexpr int L2STR = 36;
static constexpr int L2_STAGE_U32 = 256 * L2STR;
static constexpr int L2_SMEM_BYTES = 3 * L2_STAGE_U32 * 4;   // 110592
static constexpr int LSTR = 20;
static constexpr int PV_STAGE_U32 = 192 * LSTR;

// ---------------------------------------------------------------------------
// Weight conversion
// ---------------------------------------------------------------------------
struct WSrc { const float* p[18]; };
__global__ void cvt_weights_kernel(WSrc ws) {
    for (int i = blockIdx.x * blockDim.x + threadIdx.x; i < 18 * DD;
         i += gridDim.x * blockDim.x) {
        int s = i >> 18;
        int off = i & (DD - 1);
        g_Wb[i] = __float2bfloat16(ws.p[s][off]);
    }
}

// ---------------------------------------------------------------------------
// Embedding gather
// ---------------------------------------------------------------------------
__global__ void embed_kernel(const int* __restrict__ q, const int* __restrict__ r,
                             const int* __restrict__ qry,
                             const float* __restrict__ M_emb,
                             const float* __restrict__ E_emb,
                             const float* __restrict__ P) {
    int row = blockIdx.x;
    int n = row & (N - 1);
    int x = q[row] + NQ * r[row];
    int e = qry[row];
    const float* msrc = M_emb + (size_t)x * D;
    const float* esrc = E_emb + (size_t)e * D;
    const float* psrc = P + (size_t)n * D;
    size_t base = (size_t)row * D;
    for (int d = threadIdx.x; d < D; d += blockDim.x) {
        float mv = msrc[d] + psrc[d];
        float ev = esrc[d];
        g_M[base + d] = mv;  g_Mb[base + d] = __float2bfloat16(mv);
        g_E[base + d] = ev;  g_Eb[base + d] = __float2bfloat16(ev);
    }
}

// ---------------------------------------------------------------------------
// BF16 tensor-core GEMM: ldmatrix fragments, BK=64, 3-stage pipeline.
// ---------------------------------------------------------------------------
__global__ __launch_bounds__(256, 2)
void linear_bf16_kernel(const bf16* __restrict__ A, const bf16* __restrict__ W,
                        const float* __restrict__ bias,
                        float* __restrict__ C32,
                        bf16* __restrict__ C16, int ldc16, int coloff,
                        int vcol0, bf16* __restrict__ Vt,
                        const float* __restrict__ res1,
                        const float* __restrict__ res2,
                        const float* __restrict__ res3,
                        int Nout, int relu) {
    extern __shared__ uint32_t sm[];
    const int tid  = threadIdx.x;
    const int lane = tid & 31;
    const int w    = tid >> 5;
    const int g    = lane >> 2;
    const int tg   = lane & 3;
    const int wm0  = (w >> 2) * 64;
    const int wn0  = (w & 3) * 32;
    const int m0   = blockIdx.y * 128;
    const int n0   = blockIdx.x * 128;
    const uint32_t sm_u32 = (uint32_t)__cvta_generic_to_shared(sm);

    const int qr = lane & 7, qm = (lane >> 3) & 1, qk = lane >> 4;
    const int q2 = lane >> 3, rB = lane & 7;
    uint32_t aoff[4], boff[2];
#pragma unroll
    for (int tm = 0; tm < 4; tm++)
        aoff[tm] = (uint32_t)(((wm0 + tm * 16 + qm * 8 + qr) * L2STR + qk * 4) * 4);
#pragma unroll
    for (int p = 0; p < 2; p++)
        boff[p] = (uint32_t)(((wn0 + (p * 2 + (q2 >> 1)) * 8 + rB) * L2STR + (q2 & 1) * 4) * 4);

    auto load_tile = [&](int t, int s) {
        const int k0 = t * 64;
        uint32_t base = sm_u32 + (uint32_t)(s * L2_STAGE_U32) * 4u;
#pragma unroll
        for (int i = 0; i < 4; i++) {
            int e = tid + i * 256;
            int row = e >> 3, ch = e & 7;
            cp_async16(base + (uint32_t)(row * L2STR + ch * 4) * 4u,
                       &A[(size_t)(m0 + row) * 512 + k0 + ch * 8]);
        }
        base += (uint32_t)(128 * L2STR) * 4u;
#pragma unroll
        for (int i = 0; i < 4; i++) {
            int e = tid + i * 256;
            int row = e >> 3, ch = e & 7;
            cp_async16(base + (uint32_t)(row * L2STR + ch * 4) * 4u,
                       &W[(size_t)(n0 + row) * 512 + k0 + ch * 8]);
        }
        cp_commit();
    };

    float acc[4][4][4] = {};
    const int NT = 8;
    load_tile(0, 0);
    load_tile(1, 1);
    for (int it = 0; it < NT; ++it) {
        if (it + 2 < NT) {
            load_tile(it + 2, (it + 2) % 3);
            asm volatile("cp.async.wait_group 2;");
        } else if (it + 1 < NT) {
            asm volatile("cp.async.wait_group 1;");
        } else {
            asm volatile("cp.async.wait_group 0;");
        }
        __syncthreads();
        const uint32_t baseA = sm_u32 + (uint32_t)((it % 3) * L2_STAGE_U32) * 4u;
        const uint32_t baseW = baseA + (uint32_t)(128 * L2STR) * 4u;
#pragma unroll
        for (int ks = 0; ks < 4; ks++) {
            const uint32_t kb = (uint32_t)(ks * 32);
            uint32_t a[4][4], bq[4][2];
#pragma unroll
            for (int tm = 0; tm < 4; tm++)
                ldsm_x4(a[tm][0], a[tm][1], a[tm][2], a[tm][3], baseA + aoff[tm] + kb);
#pragma unroll
            for (int p = 0; p < 2; p++)
                ldsm_x4(bq[p * 2][0], bq[p * 2][1], bq[p * 2 + 1][0], bq[p * 2 + 1][1],
                        baseW + boff[p] + kb);
#pragma unroll
            for (int tm = 0; tm < 4; tm++)
#pragma unroll
                for (int tn = 0; tn < 4; tn++)
                    mma_bf16(acc[tm][tn], a[tm][0], a[tm][1], a[tm][2], a[tm][3],
                             bq[tn][0], bq[tn][1]);
        }
        __syncthreads();
    }

#pragma unroll
    for (int tm = 0; tm < 4; tm++) {
        int r0 = m0 + wm0 + tm * 16 + g;
        int r1 = r0 + 8;
#pragma unroll
        for (int tn = 0; tn < 4; tn++) {
            int c = n0 + wn0 + tn * 8 + tg * 2;
            float b0 = bias[c], b1 = bias[c + 1];
            float v00 = acc[tm][tn][0] + b0;
            float v01 = acc[tm][tn][1] + b1;
            float v10 = acc[tm][tn][2] + b0;
            float v11 = acc[tm][tn][3] + b1;
            size_t o0 = (size_t)r0 * 512 + c;
            size_t o1 = (size_t)r1 * 512 + c;
            if (res1) { v00 += res1[o0]; v01 += res1[o0 + 1]; v10 += res1[o1]; v11 += res1[o1 + 1]; }
            if (res2) { v00 += res2[o0]; v01 += res2[o0 + 1]; v10 += res2[o1]; v11 += res2[o1 + 1]; }
            if (res3) { v00 += res3[o0]; v01 += res3[o0 + 1]; v10 += res3[o1]; v11 += res3[o1 + 1]; }
            if (relu) { v00 = fmaxf(v00, 0.f); v01 = fmaxf(v01, 0.f);
                        v10 = fmaxf(v10, 0.f); v11 = fmaxf(v11, 0.f); }
            if (C32) {
                *(float2*)&C32[o0] = make_float2(v00, v01);
                *(float2*)&C32[o1] = make_float2(v10, v11);
            }
            if (C16) {
                if (c >= vcol0) {
                    int ve = c - vcol0;
                    int h = ve >> 6, e0 = ve & 63;
                    int b_ = r0 >> 9;
                    int t0 = r0 & 511, t1 = r1 & 511;
                    bf16* vrow0 = Vt + ((size_t)((b_ * H + h) * HD + e0)) * N;
                    bf16* vrow1 = vrow0 + N;
                    vrow0[t0] = __float2bfloat16(v00);
                    vrow1[t0] = __float2bfloat16(v01);
                    vrow0[t1] = __float2bfloat16(v10);
                    vrow1[t1] = __float2bfloat16(v11);
                } else {
                    *(bf162*)&C16[(size_t)r0 * ldc16 + coloff + c] =
                        __floats2bfloat162_rn(v00, v01);
                    *(bf162*)&C16[(size_t)r1 * ldc16 + coloff + c] =
                        __floats2bfloat162_rn(v10, v11);
                }
            }
        }
    }
}

// ---------------------------------------------------------------------------
// BF16 attention scores, single-stage K=64, ldmatrix fragments.
// ---------------------------------------------------------------------------
__global__ __launch_bounds__(256, 2)
void scores_bf16_kernel(const bf16* __restrict__ QK, bf16* __restrict__ S16,
                        int causal) {
    const int z = blockIdx.z, b = z >> 3, h = z & 7;
    const int i0 = blockIdx.y * 128, j0 = blockIdx.x * 128;
    if (causal && j0 > i0 + 127) return;
    const bf16* Qb = QK + (size_t)(b * N) * 1024 + h * HD;
    const bf16* Kb = Qb + 512;
    bf16* Sb = S16 + (size_t)z * N * N;

    __shared__ uint32_t sm[256 * L2STR];
    const int tid  = threadIdx.x;
    const int lane = tid & 31;
    const int w    = tid >> 5;
    const int g    = lane >> 2;
    const int tg   = lane & 3;
    const int wm0  = (w >> 2) * 64;
    const int wn0  = (w & 3) * 32;
    const uint32_t sm_u32 = (uint32_t)__cvta_generic_to_shared(sm);
    const uint32_t baseQ = sm_u32;
    const uint32_t baseK = sm_u32 + (uint32_t)(128 * L2STR) * 4u;

#pragma unroll
    for (int i = 0; i < 4; i++) {
        int e = tid + i * 256;
        int row = e >> 3, ch = e & 7;
        cp_async16(baseQ + (uint32_t)(row * L2STR + ch * 4) * 4u,
                   &Qb[(size_t)(i0 + row) * 1024 + ch * 8]);
    }
#pragma unroll
    for (int i = 0; i < 4; i++) {
        int e = tid + i * 256;
        int row = e >> 3, ch = e & 7;
        cp_async16(baseK + (uint32_t)(row * L2STR + ch * 4) * 4u,
                   &Kb[(size_t)(j0 + row) * 1024 + ch * 8]);
    }
    cp_commit();
    asm volatile("cp.async.wait_group 0;");
    __syncthreads();

    const int qr = lane & 7, qm = (lane >> 3) & 1, qk = lane >> 4;
    const int q2 = lane >> 3, rB = lane & 7;
    uint32_t aoff[4], boff[2];
#pragma unroll
    for (int tm = 0; tm < 4; tm++)
        aoff[tm] = (uint32_t)(((wm0 + tm * 16 + qm * 8 + qr) * L2STR + qk * 4) * 4);
#pragma unroll
    for (int p = 0; p < 2; p++)
        boff[p] = (uint32_t)(((wn0 + (p * 2 + (q2 >> 1)) * 8 + rB) * L2STR + (q2 & 1) * 4) * 4);

    float acc[4][4][4] = {};
#pragma unroll
    for (int ks = 0; ks < 4; ks++) {
        const uint32_t kb = (uint32_t)(ks * 32);
        uint32_t a[4][4], bq[4][2];
#pragma unroll
        for (int tm = 0; tm < 4; tm++)
            ldsm_x4(a[tm][0], a[tm][1], a[tm][2], a[tm][3], baseQ + aoff[tm] + kb);
#pragma unroll
        for (int p = 0; p < 2; p++)
            ldsm_x4(bq[p * 2][0], bq[p * 2][1], bq[p * 2 + 1][0], bq[p * 2 + 1][1],
                    baseK + boff[p] + kb);
#pragma unroll
        for (int tm = 0; tm < 4; tm++)
#pragma unroll
            for (int tn = 0; tn < 4; tn++)
                mma_bf16(acc[tm][tn], a[tm][0], a[tm][1], a[tm][2], a[tm][3],
                         bq[tn][0], bq[tn][1]);
    }

#pragma unroll
    for (int tm = 0; tm < 4; tm++) {
        int r0 = i0 + wm0 + tm * 16 + g;
        int r1 = r0 + 8;
#pragma unroll
        for (int tn = 0; tn < 4; tn++) {
            int c = j0 + wn0 + tn * 8 + tg * 2;
            *(bf162*)&Sb[(size_t)r0 * N + c] =
                __floats2bfloat162_rn(acc[tm][tn][0] * 0.125f, acc[tm][tn][1] * 0.125f);
            *(bf162*)&Sb[(size_t)r1 * N + c] =
                __floats2bfloat162_rn(acc[tm][tn][2] * 0.125f, acc[tm][tn][3] * 0.125f);
        }
    }
}

// ---------------------------------------------------------------------------
// BF16 PV: O16 = P16 @ Vt^T, 128x64 tile, BK=32, ldmatrix fragments.
// ---------------------------------------------------------------------------
__global__ __launch_bounds__(256, 2)
void pv_bf16_kernel(const bf16* __restrict__ P16, const bf16* __restrict__ Vt,
                    bf16* __restrict__ O16, int causal) {
    const int z = blockIdx.z, b = z >> 3, h = z & 7;
    const int i0 = blockIdx.y * 128;
    const bf16* Pb  = P16 + (size_t)z * N * N;
    const bf16* Vtz = Vt + (size_t)z * HD * N;
    bf16* Ob = O16 + (size_t)(b * N) * 512 + h * HD;

    __shared__ uint32_t sm[2 * PV_STAGE_U32];
    const int tid  = threadIdx.x;
    const int lane = tid & 31;
    const int w    = tid >> 5;
    const int g    = lane >> 2;
    const int tg   = lane & 3;
    const int wm0  = (w >> 1) * 32;
    const int wn0  = (w & 1) * 32;
    const uint32_t sm_u32 = (uint32_t)__cvta_generic_to_shared(sm);

    const int qr = lane & 7, qm = (lane >> 3) & 1, qk = lane >> 4;
    const int q2 = lane >> 3, rB = lane & 7;
    uint32_t aoff[2], boff[2];
#pragma unroll
    for (int tm = 0; tm < 2; tm++)
        aoff[tm] = (uint32_t)(((wm0 + tm * 16 + qm * 8 + qr) * LSTR + qk * 4) * 4);
#pragma unroll
    for (int p = 0; p < 2; p++)
        boff[p] = (uint32_t)(((wn0 + (p * 2 + (q2 >> 1)) * 8 + rB) * LSTR + (q2 & 1) * 4) * 4);

    auto load_tile = [&](int t, int s) {
        const int k0 = t * 32;
        uint32_t base = sm_u32 + (uint32_t)(s * PV_STAGE_U32) * 4u;
#pragma unroll
        for (int i = 0; i < 2; i++) {
            int e = tid + i * 256;
            int row = e >> 2, ch = e & 3;
            cp_async16(base + (uint32_t)(row * LSTR + ch * 4) * 4u,
                       &Pb[(size_t)(i0 + row) * N + k0 + ch * 8]);
        }
        base += (uint32_t)(128 * LSTR) * 4u;
        {
            int row = tid >> 2, ch = tid & 3;
            cp_async16(base + (uint32_t)(row * LSTR + ch * 4) * 4u,
                       &Vtz[(size_t)row * N + k0 + ch * 8]);
        }
        cp_commit();
    };

    float acc[2][4][4] = {};
    const int kend = causal ? (i0 + 128) : N;
    const int NT = kend / 32;
    load_tile(0, 0);
    for (int it = 0; it < NT; ++it) {
        if (it + 1 < NT) { load_tile(it + 1, (it + 1) & 1);
                           asm volatile("cp.async.wait_group 1;"); }
        else             { asm volatile("cp.async.wait_group 0;"); }
        __syncthreads();
        const uint32_t baseP = sm_u32 + (uint32_t)((it & 1) * PV_STAGE_U32) * 4u;
        const uint32_t baseV = baseP + (uint32_t)(128 * LSTR) * 4u;
#pragma unroll
        for (int ks = 0; ks < 2; ks++) {
            const uint32_t kb = (uint32_t)(ks * 32);
            uint32_t a[2][4], bq[4][2];
#pragma unroll
            for (int tm = 0; tm < 2; tm++)
                ldsm_x4(a[tm][0], a[tm][1], a[tm][2], a[tm][3], baseP + aoff[tm] + kb);
#pragma unroll
            for (int p = 0; p < 2; p++)
                ldsm_x4(bq[p * 2][0], bq[p * 2][1], bq[p * 2 + 1][0], bq[p * 2 + 1][1],
                        baseV + boff[p] + kb);
#pragma unroll
            for (int tm = 0; tm < 2; tm++)
#pragma unroll
                for (int tn = 0; tn < 4; tn++)
                    mma_bf16(acc[tm][tn], a[tm][0], a[tm][1], a[tm][2], a[tm][3],
                             bq[tn][0], bq[tn][1]);
        }
        __syncthreads();
    }

#pragma unroll
    for (int tm = 0; tm < 2; tm++) {
        int r0 = i0 + wm0 + tm * 16 + g;
        int r1 = r0 + 8;
#pragma unroll
        for (int tn = 0; tn < 4; tn++) {
            int c = wn0 + tn * 8 + tg * 2;
            *(bf162*)&Ob[(size_t)r0 * 512 + c] =
                __floats2bfloat162_rn(acc[tm][tn][0], acc[tm][tn][1]);
            *(bf162*)&Ob[(size_t)r1 * 512 + c] =
                __floats2bfloat162_rn(acc[tm][tn][2], acc[tm][tn][3]);
        }
    }
}

// ---------------------------------------------------------------------------
// Fused BASE softmax + head-mean, warp-per-head. One block per (b,i).
// ---------------------------------------------------------------------------
__global__ void softmax_base_warp(const bf16* __restrict__ S16,
                                  bf16* __restrict__ P16,
                                  float* __restrict__ outw) {
    int row = blockIdx.x;
    int b = row >> 9, i = row & (N - 1);
    int wid = threadIdx.x >> 5, lane = threadIdx.x & 31;
    int lim = i + 1;
    __shared__ float pm[8][512];
    size_t off = ((size_t)((b * H + wid) * N) + i) * N;
    const bf16* Sr = S16 + off;
    bf16* Pr = P16 + off;
    float v[16];
    float mx = -1e30f;
#pragma unroll
    for (int c = 0; c < 16; c++) {
        int j = lane + c * 32;
        v[c] = (j < lim) ? __bfloat162float(Sr[j]) : -1e30f;
        mx = fmaxf(mx, v[c]);
    }
#pragma unroll
    for (int s = 16; s > 0; s >>= 1) mx = fmaxf(mx, __shfl_xor_sync(~0u, mx, s));
    float sum = 0.f;
#pragma unroll
    for (int c = 0; c < 16; c++) {
        int j = lane + c * 32;
        float e = (j < lim) ? __expf(v[c] - mx) : 0.f;
        v[c] = e; sum += e;
    }
#pragma unroll
    for (int s = 16; s > 0; s >>= 1) sum += __shfl_xor_sync(~0u, sum, s);
    float inv = 1.f / sum;
#pragma unroll
    for (int c = 0; c < 16; c++) {
        int j = lane + c * 32;
        float p = v[c] * inv;
        Pr[j] = __float2bfloat16(p);
        pm[wid][j] = p;
    }
    __syncthreads();
    size_t orow = (size_t)row * N;
    for (int t = threadIdx.x; t < N; t += 256) {
        float s = 0.f;
#pragma unroll
        for (int h = 0; h < H; h++) s += pm[h][t];
        outw[orow + t] = s * 0.125f;
    }
}

// ---------------------------------------------------------------------------
// Warp-per-row softmax (glob/cross). 8 rows per block.
// ---------------------------------------------------------------------------
__global__ void softmax_warp_kernel(const bf16* __restrict__ S16,
                                    bf16* __restrict__ P16, int causal) {
    int row = blockIdx.x * 8 + (threadIdx.x >> 5);
    int lane = threadIdx.x & 31;
    int i = row & (N - 1);
    int lim = causal ? (i + 1) : N;
    const bf16* Sr = S16 + (size_t)row * N;
    bf16* Pr = P16 + (size_t)row * N;
    float v[16];
    float mx = -1e30f;
#pragma unroll
    for (int c = 0; c < 16; c++) {
        int j = lane + c * 32;
        v[c] = (j < lim) ? __bfloat162float(Sr[j]) : -1e30f;
        mx = fmaxf(mx, v[c]);
    }
#pragma unroll
    for (int s = 16; s > 0; s >>= 1) mx = fmaxf(mx, __shfl_xor_sync(~0u, mx, s));
    float sum = 0.f;
#pragma unroll
    for (int c = 0; c < 16; c++) {
        int j = lane + c * 32;
        float e = (j < lim) ? __expf(v[c] - mx) : 0.f;
        v[c] = e; sum += e;
    }
#pragma unroll
    for (int s = 16; s > 0; s >>= 1) sum += __shfl_xor_sync(~0u, sum, s);
    float inv = 1.f / sum;
#pragma unroll
    for (int c = 0; c < 16; c++) {
        int j = lane + c * 32;
        Pr[j] = __float2bfloat16(v[c] * inv);
    }
}

// f32 softmax (local path, Nk=64)
__global__ void softmax_f32_kernel(float* __restrict__ S, int Nq, int Nk, int causal) {
    int row = blockIdx.x;
    int i = row % Nq;
    float* Sr = S + (size_t)row * Nk;
    int lim = causal ? (i + 1) : Nk;
    int tid = threadIdx.x;
    float v[4];
    float mx = -1e30f;
#pragma unroll
    for (int c = 0; c < 4; c++) {
        int j = tid + c * 128;
        v[c] = (j < lim && j < Nk) ? Sr[j] : -1e30f;
        mx = fmaxf(mx, v[c]);
    }
    __shared__ float red[128];
    red[tid] = mx; __syncthreads();
    for (int s = 64; s > 0; s >>= 1) { if (tid < s) red[tid] = fmaxf(red[tid], red[tid + s]); __syncthreads(); }
    mx = red[0]; __syncthreads();
    float sum = 0.f;
#pragma unroll
    for (int c = 0; c < 4; c++) {
        int j = tid + c * 128;
        float e = (j < lim && j < Nk) ? __expf(v[c] - mx) : 0.f;
        v[c] = e; sum += e;
    }
    red[tid] = sum; __syncthreads();
    for (int s = 64; s > 0; s >>= 1) { if (tid < s) red[tid] += red[tid + s]; __syncthreads(); }
    float inv = 1.f / red[0];
#pragma unroll
    for (int c = 0; c < 4; c++) {
        int j = tid + c * 128;
        if (j < Nk) Sr[j] = v[c] * inv;
    }
}

// ---------------------------------------------------------------------------
// SIMT local attention (LW=64)
// ---------------------------------------------------------------------------
__global__ void local_scores_kernel(const bf16* __restrict__ QK, float* __restrict__ S) {
    int z = blockIdx.z, b = z >> 3, h = z & 7;
    const bf16* Qb = QK + (size_t)(b * LW) * 1536 + h * HD;
    const bf16* Kb = Qb + 512;
    float* Sb = S + (size_t)z * LW * LW;
    __shared__ float Qs[16][64];
    __shared__ float Ks[16][64];
    int tid = threadIdx.x, tx = tid & 15, ty = tid >> 4;
    float acc[4][4] = {};
    for (int k0 = 0; k0 < HD; k0 += 16) {
        for (int idx = tid; idx < 64 * 16; idx += 256) {
            int i = idx >> 4, j = idx & 15;
            Qs[j][i] = __bfloat162float(Qb[(size_t)i * 1536 + k0 + j]);
            Ks[j][i] = __bfloat162float(Kb[(size_t)i * 1536 + k0 + j]);
        }
        __syncthreads();
#pragma unroll
        for (int k = 0; k < 16; k++) {
            float a[4], wv[4];
#pragma unroll
            for (int i = 0; i < 4; i++) a[i] = Qs[k][ty * 4 + i];
#pragma unroll
            for (int j = 0; j < 4; j++) wv[j] = Ks[k][tx * 4 + j];
#pragma unroll
            for (int i = 0; i < 4; i++)
#pragma unroll
                for (int j = 0; j < 4; j++) acc[i][j] += a[i] * wv[j];
        }
        __syncthreads();
    }
#pragma unroll
    for (int i = 0; i < 4; i++)
#pragma unroll
        for (int j = 0; j < 4; j++)
            Sb[(size_t)(ty * 4 + i) * LW + tx * 4 + j] = acc[i][j] * 0.125f;
}

__global__ void local_pv_kernel(const float* __restrict__ Pm, const bf16* __restrict__ QK,
                                bf16* __restrict__ O16) {
    int z = blockIdx.z, b = z >> 3, h = z & 7;
    const float* Pb = Pm + (size_t)z * LW * LW;
    const bf16* Vb = QK + (size_t)(b * LW) * 1536 + 1024 + h * HD;
    bf16* Ob = O16 + (size_t)(b * LW) * 512 + h * HD;
    __shared__ float Ps[64][17];
    __shared__ float Vs[16][64];
    int tid = threadIdx.x, tx = tid & 15, ty = tid >> 4;
    float acc[4][4] = {};
    for (int k0 = 0; k0 < LW; k0 += 16) {
        for (int idx = tid; idx < 64 * 16; idx += 256) {
            int i = idx >> 4, j = idx & 15;
            Ps[i][j] = Pb[(size_t)i * LW + k0 + j];
        }
        for (int idx = tid; idx < 16 * 64; idx += 256) {
            int k = idx >> 6, e = idx & 63;
            Vs[k][e] = __bfloat162float(Vb[(size_t)(k0 + k) * 1536 + e]);
        }
        __syncthreads();
#pragma unroll
        for (int k = 0; k < 16; k++) {
            float a[4], wv[4];
#pragma unroll
            for (int i = 0; i < 4; i++) a[i] = Ps[ty * 4 + i][k];
#pragma unroll
            for (int j = 0; j < 4; j++) wv[j] = Vs[k][tx * 4 + j];
#pragma unroll
            for (int i = 0; i < 4; i++)
#pragma unroll
                for (int j = 0; j < 4; j++) acc[i][j] += a[i] * wv[j];
        }
        __syncthreads();
    }
#pragma unroll
    for (int i = 0; i < 4; i++)
#pragma unroll
        for (int j = 0; j < 4; j++)
            Ob[(size_t)(ty * 4 + i) * 512 + tx * 4 + j] = __float2bfloat16(acc[i][j]);
}

// ---------------------------------------------------------------------------
// LayerNorm: out = LN(X + r1? + r2?) * g + b ; optional bf16 out + packed copy
// ---------------------------------------------------------------------------
__global__ void ln_kernel(const float* __restrict__ X, const float* __restrict__ r1,
                          const float* __restrict__ r2, const float* __restrict__ g,
                          const float* __restrict__ bvec, float* __restrict__ out,
                          bf16* __restrict__ out16, bf16* __restrict__ pack16) {
    int row = blockIdx.x;
    size_t base = (size_t)row * D;
    int tid = threadIdx.x;
    int n = row & (N - 1);
    int b = row >> 9;
    float v[4];
    float s = 0.f;
#pragma unroll
    for (int c = 0; c < 4; c++) {
        int d = tid + c * 128;
        float t = X[base + d];
        if (r1) t += r1[base + d];
        if (r2) t += r2[base + d];
        v[c] = t; s += t;
    }
    __shared__ float red[128];
    red[tid] = s; __syncthreads();
    for (int st = 64; st > 0; st >>= 1) { if (tid < st) red[tid] += red[tid + st]; __syncthreads(); }
    float mean = red[0] * (1.f / D);
    __syncthreads();
    float vs = 0.f;
#pragma unroll
    for (int c = 0; c < 4; c++) { float dl = v[c] - mean; vs += dl * dl; }
    red[tid] = vs; __syncthreads();
    for (int st = 64; st > 0; st >>= 1) { if (tid < st) red[tid] += red[tid + st]; __syncthreads(); }
    float inv = rsqrtf(red[0] * (1.f / D) + 1e-5f);
    bf16* prow = (pack16 && n >= N - LW)
               ? pack16 + ((size_t)(b * LW + (n - (N - LW)))) * D : nullptr;
#pragma unroll
    for (int c = 0; c < 4; c++) {
        int d = tid + c * 128;
        float o = (v[c] - mean) * inv * g[d] + bvec[d];
        out[base + d] = o;
        bf16 ob = __float2bfloat16(o);
        if (out16) out16[base + d] = ob;
        if (prow) prow[d] = ob;
    }
}

// ---------------------------------------------------------------------------
// Misc elementwise kernels
// ---------------------------------------------------------------------------
__global__ void expand_local_kernel(const float* __restrict__ packed) {
    size_t idx = (size_t)blockIdx.x * blockDim.x + threadIdx.x;
    int d = (int)(idx & (D - 1));
    int row = (int)(idx >> 9);
    int b = row >> 9;
    int n = row & (N - 1);
    float v = 0.f;
    if (n >= N - LW)
        v = packed[(((size_t)b * LW + (n - (N - LW))) << 9) + d];
    g_Slocal[idx] = v;
    g_Sl16[idx] = __float2bfloat16(v);
}

__global__ void pred_kernel(const float* __restrict__ F, const float* __restrict__ pw,
                            const float* __restrict__ pb, float* __restrict__ out) {
    int row = blockIdx.x;
    int tid = threadIdx.x;
    const float* x = F + (size_t)row * D;
    float s = 0.f;
    for (int d = tid; d < D; d += 128) s += x[d] * pw[d];
    __shared__ float red[128];
    red[tid] = s; __syncthreads();
    for (int st = 64; st > 0; st >>= 1) { if (tid < st) red[tid] += red[tid + st]; __syncthreads(); }
    if (tid == 0) out[row] = 1.f / (1.f + __expf(-(red[0] + pb[0])));
}

// ---------------------------------------------------------------------------
// Launch (multi-stream fork/join; global MHA on s0 ∥ cross MHA on s2)
// ---------------------------------------------------------------------------
extern "C" void kernel_launch(void* const* d_in, const int* in_sizes, int n_in,
                              void* d_out, int out_size) {
    (void)in_sizes; (void)n_in; (void)out_size;
    const int*   q     = (const int*)d_in[0];
    const int*   r     = (const int*)d_in[1];
    const int*   qry   = (const int*)d_in[2];
    const float* M_emb = (const float*)d_in[3];
    const float* E_emb = (const float*)d_in[4];
    const float* Pmat  = (const float*)d_in[5];
    const float* biw = (const float*)d_in[6];  const float* bib = (const float*)d_in[7];
    const float* bow = (const float*)d_in[8];  const float* bob = (const float*)d_in[9];
    const float* liw = (const float*)d_in[10]; const float* lib = (const float*)d_in[11];
    const float* low = (const float*)d_in[12]; const float* lob = (const float*)d_in[13];
    const float* giw = (const float*)d_in[14]; const float* gib = (const float*)d_in[15];
    const float* gow = (const float*)d_in[16]; const float* gob = (const float*)d_in[17];
    const float* ciw = (const float*)d_in[18]; const float* cib = (const float*)d_in[19];
    const float* cow = (const float*)d_in[20]; const float* cob = (const float*)d_in[21];
    const float* ln1g = (const float*)d_in[22]; const float* ln1b = (const float*)d_in[23];
    const float* w1 = (const float*)d_in[24];  const float* b1 = (const float*)d_in[25];
    const float* w2 = (const float*)d_in[26];  const float* b2 = (const float*)d_in[27];
    const float* ln2g = (const float*)d_in[28]; const float* ln2b = (const float*)d_in[29];
    const float* pw = (const float*)d_in[30];  const float* pb = (const float*)d_in[31];
    float* out = (float*)d_out;

    float *pM, *pE, *pT1, *pT2, *pSb, *pSl, *pSg, *pSs, *pP32;
    bf16 *pMb, *pEb, *pQK, *pQKx, *pQKloc, *pVt, *pVtx, *pS16, *pP16, *pS16x, *pP16x;
    bf16 *pO16, *pO16x, *pO16loc, *pSb16, *pSl16, *pSs16, *pF16, *pT2b, *pWb;
    cudaGetSymbolAddress((void**)&pM,   g_M);
    cudaGetSymbolAddress((void**)&pE,   g_E);
    cudaGetSymbolAddress((void**)&pT1,  g_T1);
    cudaGetSymbolAddress((void**)&pT2,  g_T2);
    cudaGetSymbolAddress((void**)&pSb,  g_Sbase);
    cudaGetSymbolAddress((void**)&pSl,  g_Slocal);
    cudaGetSymbolAddress((void**)&pSg,  g_Sglob);
    cudaGetSymbolAddress((void**)&pSs,  g_Ssum);
    cudaGetSymbolAddress((void**)&pP32, g_P32);
    cudaGetSymbolAddress((void**)&pMb,  g_Mb);
    cudaGetSymbolAddress((void**)&pEb,  g_Eb);
    cudaGetSymbolAddress((void**)&pQK,  g_QK);
    cudaGetSymbolAddress((void**)&pQKx, g_QKx);
    cudaGetSymbolAddress((void**)&pQKloc, g_QKloc);
    cudaGetSymbolAddress((void**)&pVt,  g_Vt);
    cudaGetSymbolAddress((void**)&pVtx, g_Vtx);
    cudaGetSymbolAddress((void**)&pS16, g_S16);
    cudaGetSymbolAddress((void**)&pP16, g_P16);
    cudaGetSymbolAddress((void**)&pS16x, g_S16x);
    cudaGetSymbolAddress((void**)&pP16x, g_P16x);
    cudaGetSymbolAddress((void**)&pO16, g_O16);
    cudaGetSymbolAddress((void**)&pO16x, g_O16x);
    cudaGetSymbolAddress((void**)&pO16loc, g_O16loc);
    cudaGetSymbolAddress((void**)&pSb16, g_Sb16);
    cudaGetSymbolAddress((void**)&pSl16, g_Sl16);
    cudaGetSymbolAddress((void**)&pSs16, g_Ss16);
    cudaGetSymbolAddress((void**)&pF16, g_F16);
    cudaGetSymbolAddress((void**)&pT2b, g_T2b);
    cudaGetSymbolAddress((void**)&pWb,  g_Wb);

    static cudaStream_t s1 = nullptr, s2 = nullptr;
    static cudaEvent_t evFork, evCvt, evEmb, evBQ, evLn, evLoc, evXpv;
    if (!s1) {
        cudaStreamCreateWithFlags(&s1, cudaStreamNonBlocking);
        cudaStreamCreateWithFlags(&s2, cudaStreamNonBlocking);
        cudaEventCreateWithFlags(&evFork, cudaEventDisableTiming);
        cudaEventCreateWithFlags(&evCvt, cudaEventDisableTiming);
        cudaEventCreateWithFlags(&evEmb, cudaEventDisableTiming);
        cudaEventCreateWithFlags(&evBQ, cudaEventDisableTiming);
        cudaEventCreateWithFlags(&evLn, cudaEventDisableTiming);
        cudaEventCreateWithFlags(&evLoc, cudaEventDisableTiming);
        cudaEventCreateWithFlags(&evXpv, cudaEventDisableTiming);
        cudaFuncSetAttribute(linear_bf16_kernel,
                             cudaFuncAttributeMaxDynamicSharedMemorySize, L2_SMEM_BYTES);
    }

    WSrc ws;
    ws.p[0] = biw; ws.p[1] = biw + DD; ws.p[2] = biw + 2 * DD;
    ws.p[3] = liw; ws.p[4] = liw + DD; ws.p[5] = liw + 2 * DD;
    ws.p[6] = giw; ws.p[7] = giw + DD; ws.p[8] = giw + 2 * DD;
    ws.p[9] = ciw; ws.p[10] = ciw + DD; ws.p[11] = ciw + 2 * DD;
    ws.p[12] = bow; ws.p[13] = low; ws.p[14] = gow; ws.p[15] = cow;
    ws.p[16] = w1; ws.p[17] = w2;

    const int BIG = 1 << 30;
    auto lin = [&](cudaStream_t st, const bf16* A, const bf16* W, const float* bias,
                   float* C32, bf16* C16, int ldc16, int coloff, int vcol0, bf16* Vt,
                   const float* r1, const float* r2, const float* r3,
                   int Mrows, int Nout, int relu) {
        dim3 gdim(Nout / 128, Mrows / 128);
        linear_bf16_kernel<<<gdim, 256, L2_SMEM_BYTES, st>>>(A, W, bias, C32, C16, ldc16,
                                                             coloff, vcol0, Vt,
                                                             r1, r2, r3, Nout, relu);
    };

    // ---- fork ----
    cudaEventRecord(evFork, 0);
    cudaStreamWaitEvent(s1, evFork, 0);

    // s1: weight conversion    |  s0: embeddings
    cvt_weights_kernel<<<4608, 256, 0, s1>>>(ws);
    cudaEventRecord(evCvt, s1);
    embed_kernel<<<BN_ROWS, 128>>>(q, r, qry, M_emb, E_emb, Pmat);
    cudaEventRecord(evEmb, 0);

    // s1: base Q projection
    cudaStreamWaitEvent(s1, evEmb, 0);
    lin(s1, pEb, pWb + 0 * DD, bib, nullptr, pQK, 1024, 0, BIG, pVt,
        nullptr, nullptr, nullptr, BN_ROWS, 512, 0);
    cudaEventRecord(evBQ, s1);

    // s0: base K + Vt
    cudaStreamWaitEvent(0, evCvt, 0);
    lin(0, pMb, pWb + 1 * DD, bib + D, nullptr, pQK, 1024, 512, 512, pVt,
        nullptr, nullptr, nullptr, BN_ROWS, 1024, 0);
    cudaStreamWaitEvent(0, evBQ, 0);

    // s0: base attention + out-proj + LN1 (packs last LW rows -> T2b)
    scores_bf16_kernel<<<dim3(4, 4, 128), 256>>>(pQK, pS16, 1);
    softmax_base_warp<<<BN_ROWS, 256>>>(pS16, pP16, out + BN_ROWS);
    pv_bf16_kernel<<<dim3(1, 4, 128), 256>>>(pP16, pVt, pO16, 1);
    lin(0, pO16, pWb + 12 * DD, bob, pT1, nullptr, 0, 0, BIG, pVt,
        nullptr, nullptr, nullptr, BN_ROWS, 512, 0);
    ln_kernel<<<BN_ROWS, 128>>>(pT1, pM, pE, ln1g, ln1b, pSb, pSb16, pT2b);
    cudaEventRecord(evLn, 0);

    // s1: local MHA path (hidden under global path)
    cudaStreamWaitEvent(s1, evLn, 0);
    lin(s1, pT2b, pWb + 3 * DD, lib, nullptr, pQKloc, 1536, 0, BIG, pVt,
        nullptr, nullptr, nullptr, BLW_ROWS, 1536, 0);
    local_scores_kernel<<<dim3(1, 1, 128), 256, 0, s1>>>(pQKloc, pP32);
    softmax_f32_kernel<<<B * H * LW, 128, 0, s1>>>(pP32, LW, LW, 1);
    local_pv_kernel<<<dim3(1, 1, 128), 256, 0, s1>>>(pP32, pQKloc, pO16loc);
    lin(s1, pO16loc, pWb + 13 * DD, lob, pT1, nullptr, 0, 0, BIG, pVt,
        nullptr, nullptr, nullptr, BLW_ROWS, 512, 0);
    expand_local_kernel<<<(BN_ROWS * D) / 256, 256, 0, s1>>>(pT1);
    cudaEventRecord(evLoc, s1);

    // s2: full cross-attention chain (private buffers), ∥ with global on s0
    cudaStreamWaitEvent(s2, evLn, 0);
    lin(s2, pSb16, pWb + 9 * DD, cib, nullptr, pQKx, 1024, 0, BIG, pVtx,
        nullptr, nullptr, nullptr, BN_ROWS, 512, 0);
    cudaStreamWaitEvent(s2, evLoc, 0);
    lin(s2, pSl16, pWb + 10 * DD, cib + D, nullptr, pQKx, 1024, 512, 512, pVtx,
        nullptr, nullptr, nullptr, BN_ROWS, 1024, 0);
    scores_bf16_kernel<<<dim3(4, 4, 128), 256, 0, s2>>>(pQKx, pS16x, 0);
    softmax_warp_kernel<<<(B * H * N) / 8, 256, 0, s2>>>(pS16x, pP16x, 0);
    pv_bf16_kernel<<<dim3(1, 4, 128), 256, 0, s2>>>(pP16x, pVtx, pO16x, 0);
    cudaEventRecord(evXpv, s2);

    // s0: global MHA (fused QKV)
    lin(0, pSb16, pWb + 6 * DD, gib, nullptr, pQK, 1024, 0, 1024, pVt,
        nullptr, nullptr, nullptr, BN_ROWS, 1536, 0);
    scores_bf16_kernel<<<dim3(4, 4, 128), 256>>>(pQK, pS16, 1);
    softmax_warp_kernel<<<(B * H * N) / 8, 256>>>(pS16, pP16, 1);
    pv_bf16_kernel<<<dim3(1, 4, 128), 256>>>(pP16, pVt, pO16, 1);
    lin(0, pO16, pWb + 14 * DD, gob, pSg, nullptr, 0, 0, BIG, pVt,
        nullptr, nullptr, nullptr, BN_ROWS, 512, 0);

    // s0: join cross PV, then cross out-proj with fused 4-way sum
    cudaStreamWaitEvent(0, evXpv, 0);
    lin(0, pO16x, pWb + 15 * DD, cob, pSs, pSs16, 512, 0, BIG, pVt,
        pSb, pSl, pSg, BN_ROWS, 512, 0);

    // s0: FFN + LN2 + head
    lin(0, pSs16, pWb + 16 * DD, b1, nullptr, pF16, 512, 0, BIG, pVt,
        nullptr, nullptr, nullptr, BN_ROWS, 512, 1);
    lin(0, pF16, pWb + 17 * DD, b2, pT2, nullptr, 0, 0, BIG, pVt,
        nullptr, nullptr, nullptr, BN_ROWS, 512, 0);
    ln_kernel<<<BN_ROWS, 128>>>(pT2, pSs, nullptr, ln2g, ln2b, pT1, nullptr, nullptr);
    pred_kernel<<<BN_ROWS, 128>>>(pT1, pw, pb, out);
}

// round 16
// speedup vs baseline: 1.6034x; 1.1237x over previous
#include <cuda_runtime.h>
#include <cuda_bf16.h>
#include <math.h>
#include <stdint.h>

// ---------------------------------------------------------------------------
// Problem constants
// ---------------------------------------------------------------------------
static constexpr int B  = 16;
static constexpr int N  = 512;
static constexpr int D  = 512;
static constexpr int H  = 8;
static constexpr int HD = 64;
static constexpr int LW = 64;
static constexpr int NQ = 10000;
static constexpr int BN_ROWS  = B * N;    // 8192
static constexpr int BLW_ROWS = B * LW;   // 1024
static constexpr int DD = D * D;          // 262144 = 2^18

typedef __nv_bfloat16 bf16;
typedef __nv_bfloat162 bf162;

// ---------------------------------------------------------------------------
// Scratch (static device globals)
// ---------------------------------------------------------------------------
__device__ float g_M     [BN_ROWS * D];
__device__ float g_E     [BN_ROWS * D];
__device__ float g_T1    [BN_ROWS * D];
__device__ float g_T2    [BN_ROWS * D];
__device__ float g_Sbase [BN_ROWS * D];
__device__ float g_Slocal[BN_ROWS * D];
__device__ float g_Sglob [BN_ROWS * D];
__device__ float g_Ssum  [BN_ROWS * D];
__device__ float g_P32   [B * H * LW * LW];    // local probs scratch (f32)
__device__ bf16 g_Mb    [BN_ROWS * D];
__device__ bf16 g_Eb    [BN_ROWS * D];
__device__ bf16 g_QK    [BN_ROWS * 1024];      // base/glob packed Q|K
__device__ bf16 g_QKx   [BN_ROWS * 1024];      // cross packed Q|K
__device__ bf16 g_QKloc [BLW_ROWS * 1536];     // local packed QKV
__device__ bf16 g_Vt    [B * H * HD * N];      // V^T per (b,h) (base/glob)
__device__ bf16 g_Vtx   [B * H * HD * N];      // V^T per (b,h) (cross)
__device__ bf16 g_S16   [B * H * N * N];       // scores (base)
__device__ bf16 g_P16   [B * H * N * N];       // probs (base)
__device__ bf16 g_O16   [BN_ROWS * D];         // attn out (base/glob)
__device__ bf16 g_O16x  [BN_ROWS * D];         // attn out (cross)
__device__ bf16 g_O16loc[BLW_ROWS * D];
__device__ bf16 g_Sb16  [BN_ROWS * D];
__device__ bf16 g_Sl16  [BN_ROWS * D];
__device__ bf16 g_Ss16  [BN_ROWS * D];
__device__ bf16 g_F16   [BN_ROWS * D];
__device__ bf16 g_T2b   [BLW_ROWS * D];
__device__ bf16 g_Wb    [18 * DD];             // bf16 weights

// ---------------------------------------------------------------------------
// MMA / ldmatrix helpers
// ---------------------------------------------------------------------------
__device__ __forceinline__ void cp_async16(uint32_t dst, const void* src) {
    asm volatile("cp.async.cg.shared.global [%0], [%1], 16;" :: "r"(dst), "l"(src));
}
__device__ __forceinline__ void cp_commit() {
    asm volatile("cp.async.commit_group;");
}
__device__ __forceinline__ void mma_bf16(float c[4], uint32_t a0, uint32_t a1,
                                         uint32_t a2, uint32_t a3,
                                         uint32_t b0, uint32_t b1) {
    asm volatile(
        "mma.sync.aligned.m16n8k16.row.col.f32.bf16.bf16.f32 "
        "{%0,%1,%2,%3}, {%4,%5,%6,%7}, {%8,%9}, {%0,%1,%2,%3};"
        : "+f"(c[0]), "+f"(c[1]), "+f"(c[2]), "+f"(c[3])
        : "r"(a0), "r"(a1), "r"(a2), "r"(a3), "r"(b0), "r"(b1));
}
__device__ __forceinline__ void ldsm_x4(uint32_t& r0, uint32_t& r1,
                                        uint32_t& r2, uint32_t& r3, uint32_t addr) {
    asm volatile("ldmatrix.sync.aligned.m8n8.x4.shared.b16 {%0,%1,%2,%3}, [%4];"
                 : "=r"(r0), "=r"(r1), "=r"(r2), "=r"(r3) : "r"(addr));
}

static constexpr int L2STR = 36;
static constexpr int L2_STAGE_U32 = 256 * L2STR;
static constexpr int L2_SMEM_BYTES = 3 * L2_STAGE_U32 * 4;   // 110592
static constexpr int LSTR = 20;
static constexpr int PV_STAGE_U32 = 192 * LSTR;

// flash smem geometry
static constexpr int FQ_STR = 36;                 // u32 per 64-bf16 row
static constexpr int FV_STR = 68;                 // u32 per 128-bf16 row
static constexpr int F_Q_U32 = 128 * FQ_STR;      // 4608
static constexpr int F_K_U32 = 128 * FQ_STR;      // 4608 per buffer
static constexpr int F_V_U32 = 64 * FV_STR;       // 4352 per buffer
static constexpr int F_SMEM_BYTES = (F_Q_U32 + 2 * F_K_U32 + 2 * F_V_U32) * 4; // 90112

// ---------------------------------------------------------------------------
// Weight conversion
// ---------------------------------------------------------------------------
struct WSrc { const float* p[18]; };
__global__ void cvt_weights_kernel(WSrc ws) {
    for (int i = blockIdx.x * blockDim.x + threadIdx.x; i < 18 * DD;
         i += gridDim.x * blockDim.x) {
        int s = i >> 18;
        int off = i & (DD - 1);
        g_Wb[i] = __float2bfloat16(ws.p[s][off]);
    }
}

// ---------------------------------------------------------------------------
// Embedding gather
// ---------------------------------------------------------------------------
__global__ void embed_kernel(const int* __restrict__ q, const int* __restrict__ r,
                             const int* __restrict__ qry,
                             const float* __restrict__ M_emb,
                             const float* __restrict__ E_emb,
                             const float* __restrict__ P) {
    int row = blockIdx.x;
    int n = row & (N - 1);
    int x = q[row] + NQ * r[row];
    int e = qry[row];
    const float* msrc = M_emb + (size_t)x * D;
    const float* esrc = E_emb + (size_t)e * D;
    const float* psrc = P + (size_t)n * D;
    size_t base = (size_t)row * D;
    for (int d = threadIdx.x; d < D; d += blockDim.x) {
        float mv = msrc[d] + psrc[d];
        float ev = esrc[d];
        g_M[base + d] = mv;  g_Mb[base + d] = __float2bfloat16(mv);
        g_E[base + d] = ev;  g_Eb[base + d] = __float2bfloat16(ev);
    }
}

// ---------------------------------------------------------------------------
// BF16 tensor-core GEMM: ldmatrix fragments, BK=64, 3-stage pipeline.
// ---------------------------------------------------------------------------
__global__ __launch_bounds__(256, 2)
void linear_bf16_kernel(const bf16* __restrict__ A, const bf16* __restrict__ W,
                        const float* __restrict__ bias,
                        float* __restrict__ C32,
                        bf16* __restrict__ C16, int ldc16, int coloff,
                        int vcol0, bf16* __restrict__ Vt,
                        const float* __restrict__ res1,
                        const float* __restrict__ res2,
                        const float* __restrict__ res3,
                        int Nout, int relu) {
    extern __shared__ uint32_t sm[];
    const int tid  = threadIdx.x;
    const int lane = tid & 31;
    const int w    = tid >> 5;
    const int g    = lane >> 2;
    const int tg   = lane & 3;
    const int wm0  = (w >> 2) * 64;
    const int wn0  = (w & 3) * 32;
    const int m0   = blockIdx.y * 128;
    const int n0   = blockIdx.x * 128;
    const uint32_t sm_u32 = (uint32_t)__cvta_generic_to_shared(sm);

    const int qr = lane & 7, qm = (lane >> 3) & 1, qk = lane >> 4;
    const int q2 = lane >> 3, rB = lane & 7;
    uint32_t aoff[4], boff[2];
#pragma unroll
    for (int tm = 0; tm < 4; tm++)
        aoff[tm] = (uint32_t)(((wm0 + tm * 16 + qm * 8 + qr) * L2STR + qk * 4) * 4);
#pragma unroll
    for (int p = 0; p < 2; p++)
        boff[p] = (uint32_t)(((wn0 + (p * 2 + (q2 >> 1)) * 8 + rB) * L2STR + (q2 & 1) * 4) * 4);

    auto load_tile = [&](int t, int s) {
        const int k0 = t * 64;
        uint32_t base = sm_u32 + (uint32_t)(s * L2_STAGE_U32) * 4u;
#pragma unroll
        for (int i = 0; i < 4; i++) {
            int e = tid + i * 256;
            int row = e >> 3, ch = e & 7;
            cp_async16(base + (uint32_t)(row * L2STR + ch * 4) * 4u,
                       &A[(size_t)(m0 + row) * 512 + k0 + ch * 8]);
        }
        base += (uint32_t)(128 * L2STR) * 4u;
#pragma unroll
        for (int i = 0; i < 4; i++) {
            int e = tid + i * 256;
            int row = e >> 3, ch = e & 7;
            cp_async16(base + (uint32_t)(row * L2STR + ch * 4) * 4u,
                       &W[(size_t)(n0 + row) * 512 + k0 + ch * 8]);
        }
        cp_commit();
    };

    float acc[4][4][4] = {};
    const int NT = 8;
    load_tile(0, 0);
    load_tile(1, 1);
    for (int it = 0; it < NT; ++it) {
        if (it + 2 < NT) {
            load_tile(it + 2, (it + 2) % 3);
            asm volatile("cp.async.wait_group 2;");
        } else if (it + 1 < NT) {
            asm volatile("cp.async.wait_group 1;");
        } else {
            asm volatile("cp.async.wait_group 0;");
        }
        __syncthreads();
        const uint32_t baseA = sm_u32 + (uint32_t)((it % 3) * L2_STAGE_U32) * 4u;
        const uint32_t baseW = baseA + (uint32_t)(128 * L2STR) * 4u;
#pragma unroll
        for (int ks = 0; ks < 4; ks++) {
            const uint32_t kb = (uint32_t)(ks * 32);
            uint32_t a[4][4], bq[4][2];
#pragma unroll
            for (int tm = 0; tm < 4; tm++)
                ldsm_x4(a[tm][0], a[tm][1], a[tm][2], a[tm][3], baseA + aoff[tm] + kb);
#pragma unroll
            for (int p = 0; p < 2; p++)
                ldsm_x4(bq[p * 2][0], bq[p * 2][1], bq[p * 2 + 1][0], bq[p * 2 + 1][1],
                        baseW + boff[p] + kb);
#pragma unroll
            for (int tm = 0; tm < 4; tm++)
#pragma unroll
                for (int tn = 0; tn < 4; tn++)
                    mma_bf16(acc[tm][tn], a[tm][0], a[tm][1], a[tm][2], a[tm][3],
                             bq[tn][0], bq[tn][1]);
        }
        __syncthreads();
    }

#pragma unroll
    for (int tm = 0; tm < 4; tm++) {
        int r0 = m0 + wm0 + tm * 16 + g;
        int r1 = r0 + 8;
#pragma unroll
        for (int tn = 0; tn < 4; tn++) {
            int c = n0 + wn0 + tn * 8 + tg * 2;
            float b0 = bias[c], b1 = bias[c + 1];
            float v00 = acc[tm][tn][0] + b0;
            float v01 = acc[tm][tn][1] + b1;
            float v10 = acc[tm][tn][2] + b0;
            float v11 = acc[tm][tn][3] + b1;
            size_t o0 = (size_t)r0 * 512 + c;
            size_t o1 = (size_t)r1 * 512 + c;
            if (res1) { v00 += res1[o0]; v01 += res1[o0 + 1]; v10 += res1[o1]; v11 += res1[o1 + 1]; }
            if (res2) { v00 += res2[o0]; v01 += res2[o0 + 1]; v10 += res2[o1]; v11 += res2[o1 + 1]; }
            if (res3) { v00 += res3[o0]; v01 += res3[o0 + 1]; v10 += res3[o1]; v11 += res3[o1 + 1]; }
            if (relu) { v00 = fmaxf(v00, 0.f); v01 = fmaxf(v01, 0.f);
                        v10 = fmaxf(v10, 0.f); v11 = fmaxf(v11, 0.f); }
            if (C32) {
                *(float2*)&C32[o0] = make_float2(v00, v01);
                *(float2*)&C32[o1] = make_float2(v10, v11);
            }
            if (C16) {
                if (c >= vcol0) {
                    int ve = c - vcol0;
                    int h = ve >> 6, e0 = ve & 63;
                    int b_ = r0 >> 9;
                    int t0 = r0 & 511, t1 = r1 & 511;
                    bf16* vrow0 = Vt + ((size_t)((b_ * H + h) * HD + e0)) * N;
                    bf16* vrow1 = vrow0 + N;
                    vrow0[t0] = __float2bfloat16(v00);
                    vrow1[t0] = __float2bfloat16(v01);
                    vrow0[t1] = __float2bfloat16(v10);
                    vrow1[t1] = __float2bfloat16(v11);
                } else {
                    *(bf162*)&C16[(size_t)r0 * ldc16 + coloff + c] =
                        __floats2bfloat162_rn(v00, v01);
                    *(bf162*)&C16[(size_t)r1 * ldc16 + coloff + c] =
                        __floats2bfloat162_rn(v10, v11);
                }
            }
        }
    }
}

// ---------------------------------------------------------------------------
// Flash attention (fused scores+softmax+PV), HD=64, warp-per-16-rows.
// Q/K packed in QK (ld 1024, Q col 0, K col 512); V transposed in Vt.
// grid (1, N/128, B*H), 256 threads. Online softmax, P reinterpreted
// C-fragment -> A-fragment (thread-local, exact).
// ---------------------------------------------------------------------------
__global__ __launch_bounds__(256, 1)
void flash_bf16_kernel(const bf16* __restrict__ QK, const bf16* __restrict__ Vt,
                       bf16* __restrict__ O16, int causal) {
    extern __shared__ uint32_t sm[];
    const int z = blockIdx.z, b = z >> 3, h = z & 7;
    const int i0 = blockIdx.y * 128;
    const bf16* Qb  = QK + (size_t)(b * N) * 1024 + h * HD;
    const bf16* Kb  = Qb + 512;
    const bf16* Vtz = Vt + (size_t)z * HD * N;
    bf16* Ob = O16 + (size_t)(b * N) * 512 + h * HD;

    const int tid = threadIdx.x;
    const int lane = tid & 31;
    const int w = tid >> 5;
    const int g = lane >> 2, tg = lane & 3;
    const int row_base = w * 16;

    const uint32_t sm_u32 = (uint32_t)__cvta_generic_to_shared(sm);
    const uint32_t baseQ  = sm_u32;
    const uint32_t baseK0 = baseQ + (uint32_t)F_Q_U32 * 4u;
    const uint32_t baseV0 = baseK0 + (uint32_t)(2 * F_K_U32) * 4u;

    const int qr = lane & 7, qm = (lane >> 3) & 1, qk = lane >> 4;
    const uint32_t aoffQ = (uint32_t)(((row_base + qm * 8 + qr) * FQ_STR + qk * 4) * 4);
    const int q2 = lane >> 3, rB = lane & 7;
    uint32_t boffK[8], boffV[4];
#pragma unroll
    for (int p = 0; p < 8; p++)
        boffK[p] = (uint32_t)((((p * 2 + (q2 >> 1)) * 8 + rB) * FQ_STR + (q2 & 1) * 4) * 4);
#pragma unroll
    for (int p = 0; p < 4; p++)
        boffV[p] = (uint32_t)((((p * 2 + (q2 >> 1)) * 8 + rB) * FV_STR + (q2 & 1) * 4) * 4);

    // Q tile load (128 rows x 8 chunks)
#pragma unroll
    for (int i = 0; i < 4; i++) {
        int e = tid + i * 256;
        int row = e >> 3, ch = e & 7;
        cp_async16(baseQ + (uint32_t)(row * FQ_STR + ch * 4) * 4u,
                   &Qb[(size_t)(i0 + row) * 1024 + ch * 8]);
    }
    auto load_kv = [&](int jt, int s) {
        const int j0 = jt * 128;
        uint32_t bK = baseK0 + (uint32_t)(s * F_K_U32) * 4u;
        uint32_t bV = baseV0 + (uint32_t)(s * F_V_U32) * 4u;
#pragma unroll
        for (int i = 0; i < 4; i++) {
            int e = tid + i * 256;
            int row = e >> 3, ch = e & 7;
            cp_async16(bK + (uint32_t)(row * FQ_STR + ch * 4) * 4u,
                       &Kb[(size_t)(j0 + row) * 1024 + ch * 8]);
        }
#pragma unroll
        for (int i = 0; i < 4; i++) {
            int e = tid + i * 256;
            int row = e >> 4, ch = e & 15;      // 64 rows x 16 chunks
            cp_async16(bV + (uint32_t)(row * FV_STR + ch * 4) * 4u,
                       &Vtz[(size_t)row * N + j0 + ch * 8]);
        }
        cp_commit();
    };

    const int itile = i0 >> 7;
    const int ntiles = causal ? (itile + 1) : 4;
    load_kv(0, 0);    // commits group containing Q too

    float oacc[8][4] = {};
    float rmax0 = -1e30f, rmax1 = -1e30f;
    float rsum0 = 0.f, rsum1 = 0.f;
    const int r0 = i0 + row_base + g;
    const int r1 = r0 + 8;

    for (int jt = 0; jt < ntiles; ++jt) {
        if (jt + 1 < ntiles) { load_kv(jt + 1, (jt + 1) & 1);
                               asm volatile("cp.async.wait_group 1;"); }
        else                 { asm volatile("cp.async.wait_group 0;"); }
        __syncthreads();
        const uint32_t bK = baseK0 + (uint32_t)((jt & 1) * F_K_U32) * 4u;
        const uint32_t bV = baseV0 + (uint32_t)((jt & 1) * F_V_U32) * 4u;

        // S = Q K^T
        float sacc[16][4] = {};
#pragma unroll
        for (int ks = 0; ks < 4; ks++) {
            const uint32_t kb = (uint32_t)(ks * 32);
            uint32_t a0, a1, a2, a3;
            ldsm_x4(a0, a1, a2, a3, baseQ + aoffQ + kb);
            uint32_t bq[16][2];
#pragma unroll
            for (int p = 0; p < 8; p++)
                ldsm_x4(bq[p * 2][0], bq[p * 2][1], bq[p * 2 + 1][0], bq[p * 2 + 1][1],
                        bK + boffK[p] + kb);
#pragma unroll
            for (int tn = 0; tn < 16; tn++)
                mma_bf16(sacc[tn], a0, a1, a2, a3, bq[tn][0], bq[tn][1]);
        }
        const int j0 = jt * 128;
#pragma unroll
        for (int tn = 0; tn < 16; tn++) {
            sacc[tn][0] *= 0.125f; sacc[tn][1] *= 0.125f;
            sacc[tn][2] *= 0.125f; sacc[tn][3] *= 0.125f;
            if (causal && jt == itile) {
                int c0 = j0 + tn * 8 + tg * 2;
                if (c0 > r0)     sacc[tn][0] = -1e30f;
                if (c0 + 1 > r0) sacc[tn][1] = -1e30f;
                if (c0 > r1)     sacc[tn][2] = -1e30f;
                if (c0 + 1 > r1) sacc[tn][3] = -1e30f;
            }
        }
        // tile row max (warp-local: 4 lanes per row)
        float tm0 = -1e30f, tm1 = -1e30f;
#pragma unroll
        for (int tn = 0; tn < 16; tn++) {
            tm0 = fmaxf(tm0, fmaxf(sacc[tn][0], sacc[tn][1]));
            tm1 = fmaxf(tm1, fmaxf(sacc[tn][2], sacc[tn][3]));
        }
        tm0 = fmaxf(tm0, __shfl_xor_sync(~0u, tm0, 1));
        tm0 = fmaxf(tm0, __shfl_xor_sync(~0u, tm0, 2));
        tm1 = fmaxf(tm1, __shfl_xor_sync(~0u, tm1, 1));
        tm1 = fmaxf(tm1, __shfl_xor_sync(~0u, tm1, 2));
        float nm0 = fmaxf(rmax0, tm0), nm1 = fmaxf(rmax1, tm1);
        float sc0 = __expf(rmax0 - nm0), sc1 = __expf(rmax1 - nm1);
        rmax0 = nm0; rmax1 = nm1;

        // exp, tile sum, pack P fragments
        uint32_t pf[16], pf2[16];
        float ts0 = 0.f, ts1 = 0.f;
#pragma unroll
        for (int tn = 0; tn < 16; tn++) {
            float e0 = __expf(sacc[tn][0] - nm0);
            float e1 = __expf(sacc[tn][1] - nm0);
            float e2 = __expf(sacc[tn][2] - nm1);
            float e3 = __expf(sacc[tn][3] - nm1);
            ts0 += e0 + e1; ts1 += e2 + e3;
            bf162 p01 = __floats2bfloat162_rn(e0, e1);
            bf162 p23 = __floats2bfloat162_rn(e2, e3);
            pf[tn]  = *(uint32_t*)&p01;
            pf2[tn] = *(uint32_t*)&p23;
        }
        ts0 += __shfl_xor_sync(~0u, ts0, 1);
        ts0 += __shfl_xor_sync(~0u, ts0, 2);
        ts1 += __shfl_xor_sync(~0u, ts1, 1);
        ts1 += __shfl_xor_sync(~0u, ts1, 2);
        rsum0 = rsum0 * sc0 + ts0;
        rsum1 = rsum1 * sc1 + ts1;
        // rescale O
#pragma unroll
        for (int tn2 = 0; tn2 < 8; tn2++) {
            oacc[tn2][0] *= sc0; oacc[tn2][1] *= sc0;
            oacc[tn2][2] *= sc1; oacc[tn2][3] *= sc1;
        }
        // PV: P (C-frag reinterpreted as A-frag) x V
#pragma unroll
        for (int ks2 = 0; ks2 < 8; ks2++) {
            const uint32_t kb = (uint32_t)(ks2 * 32);
            uint32_t bv[8][2];
#pragma unroll
            for (int p = 0; p < 4; p++)
                ldsm_x4(bv[p * 2][0], bv[p * 2][1], bv[p * 2 + 1][0], bv[p * 2 + 1][1],
                        bV + boffV[p] + kb);
#pragma unroll
            for (int tn2 = 0; tn2 < 8; tn2++)
                mma_bf16(oacc[tn2], pf[2 * ks2], pf2[2 * ks2],
                         pf[2 * ks2 + 1], pf2[2 * ks2 + 1],
                         bv[tn2][0], bv[tn2][1]);
        }
        __syncthreads();
    }

    float inv0 = 1.f / rsum0, inv1 = 1.f / rsum1;
#pragma unroll
    for (int tn2 = 0; tn2 < 8; tn2++) {
        int c = tn2 * 8 + tg * 2;
        *(bf162*)&Ob[(size_t)r0 * 512 + c] =
            __floats2bfloat162_rn(oacc[tn2][0] * inv0, oacc[tn2][1] * inv0);
        *(bf162*)&Ob[(size_t)r1 * 512 + c] =
            __floats2bfloat162_rn(oacc[tn2][2] * inv1, oacc[tn2][3] * inv1);
    }
}

// ---------------------------------------------------------------------------
// BF16 attention scores (base only), single-stage K=64, ldmatrix fragments.
// ---------------------------------------------------------------------------
__global__ __launch_bounds__(256, 2)
void scores_bf16_kernel(const bf16* __restrict__ QK, bf16* __restrict__ S16,
                        int causal) {
    const int z = blockIdx.z, b = z >> 3, h = z & 7;
    const int i0 = blockIdx.y * 128, j0 = blockIdx.x * 128;
    if (causal && j0 > i0 + 127) return;
    const bf16* Qb = QK + (size_t)(b * N) * 1024 + h * HD;
    const bf16* Kb = Qb + 512;
    bf16* Sb = S16 + (size_t)z * N * N;

    __shared__ uint32_t sm[256 * L2STR];
    const int tid  = threadIdx.x;
    const int lane = tid & 31;
    const int w    = tid >> 5;
    const int g    = lane >> 2;
    const int tg   = lane & 3;
    const int wm0  = (w >> 2) * 64;
    const int wn0  = (w & 3) * 32;
    const uint32_t sm_u32 = (uint32_t)__cvta_generic_to_shared(sm);
    const uint32_t baseQ = sm_u32;
    const uint32_t baseK = sm_u32 + (uint32_t)(128 * L2STR) * 4u;

#pragma unroll
    for (int i = 0; i < 4; i++) {
        int e = tid + i * 256;
        int row = e >> 3, ch = e & 7;
        cp_async16(baseQ + (uint32_t)(row * L2STR + ch * 4) * 4u,
                   &Qb[(size_t)(i0 + row) * 1024 + ch * 8]);
    }
#pragma unroll
    for (int i = 0; i < 4; i++) {
        int e = tid + i * 256;
        int row = e >> 3, ch = e & 7;
        cp_async16(baseK + (uint32_t)(row * L2STR + ch * 4) * 4u,
                   &Kb[(size_t)(j0 + row) * 1024 + ch * 8]);
    }
    cp_commit();
    asm volatile("cp.async.wait_group 0;");
    __syncthreads();

    const int qr = lane & 7, qm = (lane >> 3) & 1, qk = lane >> 4;
    const int q2 = lane >> 3, rB = lane & 7;
    uint32_t aoff[4], boff[2];
#pragma unroll
    for (int tm = 0; tm < 4; tm++)
        aoff[tm] = (uint32_t)(((wm0 + tm * 16 + qm * 8 + qr) * L2STR + qk * 4) * 4);
#pragma unroll
    for (int p = 0; p < 2; p++)
        boff[p] = (uint32_t)(((wn0 + (p * 2 + (q2 >> 1)) * 8 + rB) * L2STR + (q2 & 1) * 4) * 4);

    float acc[4][4][4] = {};
#pragma unroll
    for (int ks = 0; ks < 4; ks++) {
        const uint32_t kb = (uint32_t)(ks * 32);
        uint32_t a[4][4], bq[4][2];
#pragma unroll
        for (int tm = 0; tm < 4; tm++)
            ldsm_x4(a[tm][0], a[tm][1], a[tm][2], a[tm][3], baseQ + aoff[tm] + kb);
#pragma unroll
        for (int p = 0; p < 2; p++)
            ldsm_x4(bq[p * 2][0], bq[p * 2][1], bq[p * 2 + 1][0], bq[p * 2 + 1][1],
                    baseK + boff[p] + kb);
#pragma unroll
        for (int tm = 0; tm < 4; tm++)
#pragma unroll
            for (int tn = 0; tn < 4; tn++)
                mma_bf16(acc[tm][tn], a[tm][0], a[tm][1], a[tm][2], a[tm][3],
                         bq[tn][0], bq[tn][1]);
    }

#pragma unroll
    for (int tm = 0; tm < 4; tm++) {
        int r0 = i0 + wm0 + tm * 16 + g;
        int r1 = r0 + 8;
#pragma unroll
        for (int tn = 0; tn < 4; tn++) {
            int c = j0 + wn0 + tn * 8 + tg * 2;
            *(bf162*)&Sb[(size_t)r0 * N + c] =
                __floats2bfloat162_rn(acc[tm][tn][0] * 0.125f, acc[tm][tn][1] * 0.125f);
            *(bf162*)&Sb[(size_t)r1 * N + c] =
                __floats2bfloat162_rn(acc[tm][tn][2] * 0.125f, acc[tm][tn][3] * 0.125f);
        }
    }
}

// ---------------------------------------------------------------------------
// BF16 PV (base only): O16 = P16 @ Vt^T, 128x64 tile, BK=32.
// ---------------------------------------------------------------------------
__global__ __launch_bounds__(256, 2)
void pv_bf16_kernel(const bf16* __restrict__ P16, const bf16* __restrict__ Vt,
                    bf16* __restrict__ O16, int causal) {
    const int z = blockIdx.z, b = z >> 3, h = z & 7;
    const int i0 = blockIdx.y * 128;
    const bf16* Pb  = P16 + (size_t)z * N * N;
    const bf16* Vtz = Vt + (size_t)z * HD * N;
    bf16* Ob = O16 + (size_t)(b * N) * 512 + h * HD;

    __shared__ uint32_t sm[2 * PV_STAGE_U32];
    const int tid  = threadIdx.x;
    const int lane = tid & 31;
    const int w    = tid >> 5;
    const int g    = lane >> 2;
    const int tg   = lane & 3;
    const int wm0  = (w >> 1) * 32;
    const int wn0  = (w & 1) * 32;
    const uint32_t sm_u32 = (uint32_t)__cvta_generic_to_shared(sm);

    const int qr = lane & 7, qm = (lane >> 3) & 1, qk = lane >> 4;
    const int q2 = lane >> 3, rB = lane & 7;
    uint32_t aoff[2], boff[2];
#pragma unroll
    for (int tm = 0; tm < 2; tm++)
        aoff[tm] = (uint32_t)(((wm0 + tm * 16 + qm * 8 + qr) * LSTR + qk * 4) * 4);
#pragma unroll
    for (int p = 0; p < 2; p++)
        boff[p] = (uint32_t)(((wn0 + (p * 2 + (q2 >> 1)) * 8 + rB) * LSTR + (q2 & 1) * 4) * 4);

    auto load_tile = [&](int t, int s) {
        const int k0 = t * 32;
        uint32_t base = sm_u32 + (uint32_t)(s * PV_STAGE_U32) * 4u;
#pragma unroll
        for (int i = 0; i < 2; i++) {
            int e = tid + i * 256;
            int row = e >> 2, ch = e & 3;
            cp_async16(base + (uint32_t)(row * LSTR + ch * 4) * 4u,
                       &Pb[(size_t)(i0 + row) * N + k0 + ch * 8]);
        }
        base += (uint32_t)(128 * LSTR) * 4u;
        {
            int row = tid >> 2, ch = tid & 3;
            cp_async16(base + (uint32_t)(row * LSTR + ch * 4) * 4u,
                       &Vtz[(size_t)row * N + k0 + ch * 8]);
        }
        cp_commit();
    };

    float acc[2][4][4] = {};
    const int kend = causal ? (i0 + 128) : N;
    const int NT = kend / 32;
    load_tile(0, 0);
    for (int it = 0; it < NT; ++it) {
        if (it + 1 < NT) { load_tile(it + 1, (it + 1) & 1);
                           asm volatile("cp.async.wait_group 1;"); }
        else             { asm volatile("cp.async.wait_group 0;"); }
        __syncthreads();
        const uint32_t baseP = sm_u32 + (uint32_t)((it & 1) * PV_STAGE_U32) * 4u;
        const uint32_t baseV = baseP + (uint32_t)(128 * LSTR) * 4u;
#pragma unroll
        for (int ks = 0; ks < 2; ks++) {
            const uint32_t kb = (uint32_t)(ks * 32);
            uint32_t a[2][4], bq[4][2];
#pragma unroll
            for (int tm = 0; tm < 2; tm++)
                ldsm_x4(a[tm][0], a[tm][1], a[tm][2], a[tm][3], baseP + aoff[tm] + kb);
#pragma unroll
            for (int p = 0; p < 2; p++)
                ldsm_x4(bq[p * 2][0], bq[p * 2][1], bq[p * 2 + 1][0], bq[p * 2 + 1][1],
                        baseV + boff[p] + kb);
#pragma unroll
            for (int tm = 0; tm < 2; tm++)
#pragma unroll
                for (int tn = 0; tn < 4; tn++)
                    mma_bf16(acc[tm][tn], a[tm][0], a[tm][1], a[tm][2], a[tm][3],
                             bq[tn][0], bq[tn][1]);
        }
        __syncthreads();
    }

#pragma unroll
    for (int tm = 0; tm < 2; tm++) {
        int r0 = i0 + wm0 + tm * 16 + g;
        int r1 = r0 + 8;
#pragma unroll
        for (int tn = 0; tn < 4; tn++) {
            int c = wn0 + tn * 8 + tg * 2;
            *(bf162*)&Ob[(size_t)r0 * 512 + c] =
                __floats2bfloat162_rn(acc[tm][tn][0], acc[tm][tn][1]);
            *(bf162*)&Ob[(size_t)r1 * 512 + c] =
                __floats2bfloat162_rn(acc[tm][tn][2], acc[tm][tn][3]);
        }
    }
}

// ---------------------------------------------------------------------------
// Fused BASE softmax + head-mean, warp-per-head. One block per (b,i).
// ---------------------------------------------------------------------------
__global__ void softmax_base_warp(const bf16* __restrict__ S16,
                                  bf16* __restrict__ P16,
                                  float* __restrict__ outw) {
    int row = blockIdx.x;
    int b = row >> 9, i = row & (N - 1);
    int wid = threadIdx.x >> 5, lane = threadIdx.x & 31;
    int lim = i + 1;
    __shared__ float pm[8][512];
    size_t off = ((size_t)((b * H + wid) * N) + i) * N;
    const bf16* Sr = S16 + off;
    bf16* Pr = P16 + off;
    float v[16];
    float mx = -1e30f;
#pragma unroll
    for (int c = 0; c < 16; c++) {
        int j = lane + c * 32;
        v[c] = (j < lim) ? __bfloat162float(Sr[j]) : -1e30f;
        mx = fmaxf(mx, v[c]);
    }
#pragma unroll
    for (int s = 16; s > 0; s >>= 1) mx = fmaxf(mx, __shfl_xor_sync(~0u, mx, s));
    float sum = 0.f;
#pragma unroll
    for (int c = 0; c < 16; c++) {
        int j = lane + c * 32;
        float e = (j < lim) ? __expf(v[c] - mx) : 0.f;
        v[c] = e; sum += e;
    }
#pragma unroll
    for (int s = 16; s > 0; s >>= 1) sum += __shfl_xor_sync(~0u, sum, s);
    float inv = 1.f / sum;
#pragma unroll
    for (int c = 0; c < 16; c++) {
        int j = lane + c * 32;
        float p = v[c] * inv;
        Pr[j] = __float2bfloat16(p);
        pm[wid][j] = p;
    }
    __syncthreads();
    size_t orow = (size_t)row * N;
    for (int t = threadIdx.x; t < N; t += 256) {
        float s = 0.f;
#pragma unroll
        for (int h = 0; h < H; h++) s += pm[h][t];
        outw[orow + t] = s * 0.125f;
    }
}

// f32 softmax (local path, Nk=64)
__global__ void softmax_f32_kernel(float* __restrict__ S, int Nq, int Nk, int causal) {
    int row = blockIdx.x;
    int i = row % Nq;
    float* Sr = S + (size_t)row * Nk;
    int lim = causal ? (i + 1) : Nk;
    int tid = threadIdx.x;
    float v[4];
    float mx = -1e30f;
#pragma unroll
    for (int c = 0; c < 4; c++) {
        int j = tid + c * 128;
        v[c] = (j < lim && j < Nk) ? Sr[j] : -1e30f;
        mx = fmaxf(mx, v[c]);
    }
    __shared__ float red[128];
    red[tid] = mx; __syncthreads();
    for (int s = 64; s > 0; s >>= 1) { if (tid < s) red[tid] = fmaxf(red[tid], red[tid + s]); __syncthreads(); }
    mx = red[0]; __syncthreads();
    float sum = 0.f;
#pragma unroll
    for (int c = 0; c < 4; c++) {
        int j = tid + c * 128;
        float e = (j < lim && j < Nk) ? __expf(v[c] - mx) : 0.f;
        v[c] = e; sum += e;
    }
    red[tid] = sum; __syncthreads();
    for (int s = 64; s > 0; s >>= 1) { if (tid < s) red[tid] += red[tid + s]; __syncthreads(); }
    float inv = 1.f / red[0];
#pragma unroll
    for (int c = 0; c < 4; c++) {
        int j = tid + c * 128;
        if (j < Nk) Sr[j] = v[c] * inv;
    }
}

// ---------------------------------------------------------------------------
// SIMT local attention (LW=64)
// ---------------------------------------------------------------------------
__global__ void local_scores_kernel(const bf16* __restrict__ QK, float* __restrict__ S) {
    int z = blockIdx.z, b = z >> 3, h = z & 7;
    const bf16* Qb = QK + (size_t)(b * LW) * 1536 + h * HD;
    const bf16* Kb = Qb + 512;
    float* Sb = S + (size_t)z * LW * LW;
    __shared__ float Qs[16][64];
    __shared__ float Ks[16][64];
    int tid = threadIdx.x, tx = tid & 15, ty = tid >> 4;
    float acc[4][4] = {};
    for (int k0 = 0; k0 < HD; k0 += 16) {
        for (int idx = tid; idx < 64 * 16; idx += 256) {
            int i = idx >> 4, j = idx & 15;
            Qs[j][i] = __bfloat162float(Qb[(size_t)i * 1536 + k0 + j]);
            Ks[j][i] = __bfloat162float(Kb[(size_t)i * 1536 + k0 + j]);
        }
        __syncthreads();
#pragma unroll
        for (int k = 0; k < 16; k++) {
            float a[4], wv[4];
#pragma unroll
            for (int i = 0; i < 4; i++) a[i] = Qs[k][ty * 4 + i];
#pragma unroll
            for (int j = 0; j < 4; j++) wv[j] = Ks[k][tx * 4 + j];
#pragma unroll
            for (int i = 0; i < 4; i++)
#pragma unroll
                for (int j = 0; j < 4; j++) acc[i][j] += a[i] * wv[j];
        }
        __syncthreads();
    }
#pragma unroll
    for (int i = 0; i < 4; i++)
#pragma unroll
        for (int j = 0; j < 4; j++)
            Sb[(size_t)(ty * 4 + i) * LW + tx * 4 + j] = acc[i][j] * 0.125f;
}

__global__ void local_pv_kernel(const float* __restrict__ Pm, const bf16* __restrict__ QK,
                                bf16* __restrict__ O16) {
    int z = blockIdx.z, b = z >> 3, h = z & 7;
    const float* Pb = Pm + (size_t)z * LW * LW;
    const bf16* Vb = QK + (size_t)(b * LW) * 1536 + 1024 + h * HD;
    bf16* Ob = O16 + (size_t)(b * LW) * 512 + h * HD;
    __shared__ float Ps[64][17];
    __shared__ float Vs[16][64];
    int tid = threadIdx.x, tx = tid & 15, ty = tid >> 4;
    float acc[4][4] = {};
    for (int k0 = 0; k0 < LW; k0 += 16) {
        for (int idx = tid; idx < 64 * 16; idx += 256) {
            int i = idx >> 4, j = idx & 15;
            Ps[i][j] = Pb[(size_t)i * LW + k0 + j];
        }
        for (int idx = tid; idx < 16 * 64; idx += 256) {
            int k = idx >> 6, e = idx & 63;
            Vs[k][e] = __bfloat162float(Vb[(size_t)(k0 + k) * 1536 + e]);
        }
        __syncthreads();
#pragma unroll
        for (int k = 0; k < 16; k++) {
            float a[4], wv[4];
#pragma unroll
            for (int i = 0; i < 4; i++) a[i] = Ps[ty * 4 + i][k];
#pragma unroll
            for (int j = 0; j < 4; j++) wv[j] = Vs[k][tx * 4 + j];
#pragma unroll
            for (int i = 0; i < 4; i++)
#pragma unroll
                for (int j = 0; j < 4; j++) acc[i][j] += a[i] * wv[j];
        }
        __syncthreads();
    }
#pragma unroll
    for (int i = 0; i < 4; i++)
#pragma unroll
        for (int j = 0; j < 4; j++)
            Ob[(size_t)(ty * 4 + i) * 512 + tx * 4 + j] = __float2bfloat16(acc[i][j]);
}

// ---------------------------------------------------------------------------
// LayerNorm: out = LN(X + r1? + r2?) * g + b ; optional bf16 out + packed copy
// ---------------------------------------------------------------------------
__global__ void ln_kernel(const float* __restrict__ X, const float* __restrict__ r1,
                          const float* __restrict__ r2, const float* __restrict__ g,
                          const float* __restrict__ bvec, float* __restrict__ out,
                          bf16* __restrict__ out16, bf16* __restrict__ pack16) {
    int row = blockIdx.x;
    size_t base = (size_t)row * D;
    int tid = threadIdx.x;
    int n = row & (N - 1);
    int b = row >> 9;
    float v[4];
    float s = 0.f;
#pragma unroll
    for (int c = 0; c < 4; c++) {
        int d = tid + c * 128;
        float t = X[base + d];
        if (r1) t += r1[base + d];
        if (r2) t += r2[base + d];
        v[c] = t; s += t;
    }
    __shared__ float red[128];
    red[tid] = s; __syncthreads();
    for (int st = 64; st > 0; st >>= 1) { if (tid < st) red[tid] += red[tid + st]; __syncthreads(); }
    float mean = red[0] * (1.f / D);
    __syncthreads();
    float vs = 0.f;
#pragma unroll
    for (int c = 0; c < 4; c++) { float dl = v[c] - mean; vs += dl * dl; }
    red[tid] = vs; __syncthreads();
    for (int st = 64; st > 0; st >>= 1) { if (tid < st) red[tid] += red[tid + st]; __syncthreads(); }
    float inv = rsqrtf(red[0] * (1.f / D) + 1e-5f);
    bf16* prow = (pack16 && n >= N - LW)
               ? pack16 + ((size_t)(b * LW + (n - (N - LW)))) * D : nullptr;
#pragma unroll
    for (int c = 0; c < 4; c++) {
        int d = tid + c * 128;
        float o = (v[c] - mean) * inv * g[d] + bvec[d];
        out[base + d] = o;
        bf16 ob = __float2bfloat16(o);
        if (out16) out16[base + d] = ob;
        if (prow) prow[d] = ob;
    }
}

// ---------------------------------------------------------------------------
// Misc elementwise kernels
// ---------------------------------------------------------------------------
__global__ void expand_local_kernel(const float* __restrict__ packed) {
    size_t idx = (size_t)blockIdx.x * blockDim.x + threadIdx.x;
    int d = (int)(idx & (D - 1));
    int row = (int)(idx >> 9);
    int b = row >> 9;
    int n = row & (N - 1);
    float v = 0.f;
    if (n >= N - LW)
        v = packed[(((size_t)b * LW + (n - (N - LW))) << 9) + d];
    g_Slocal[idx] = v;
    g_Sl16[idx] = __float2bfloat16(v);
}

__global__ void pred_kernel(const float* __restrict__ F, const float* __restrict__ pw,
                            const float* __restrict__ pb, float* __restrict__ out) {
    int row = blockIdx.x;
    int tid = threadIdx.x;
    const float* x = F + (size_t)row * D;
    float s = 0.f;
    for (int d = tid; d < D; d += 128) s += x[d] * pw[d];
    __shared__ float red[128];
    red[tid] = s; __syncthreads();
    for (int st = 64; st > 0; st >>= 1) { if (tid < st) red[tid] += red[tid + st]; __syncthreads(); }
    if (tid == 0) out[row] = 1.f / (1.f + __expf(-(red[0] + pb[0])));
}

// ---------------------------------------------------------------------------
// Launch
// ---------------------------------------------------------------------------
extern "C" void kernel_launch(void* const* d_in, const int* in_sizes, int n_in,
                              void* d_out, int out_size) {
    (void)in_sizes; (void)n_in; (void)out_size;
    const int*   q     = (const int*)d_in[0];
    const int*   r     = (const int*)d_in[1];
    const int*   qry   = (const int*)d_in[2];
    const float* M_emb = (const float*)d_in[3];
    const float* E_emb = (const float*)d_in[4];
    const float* Pmat  = (const float*)d_in[5];
    const float* biw = (const float*)d_in[6];  const float* bib = (const float*)d_in[7];
    const float* bow = (const float*)d_in[8];  const float* bob = (const float*)d_in[9];
    const float* liw = (const float*)d_in[10]; const float* lib = (const float*)d_in[11];
    const float* low = (const float*)d_in[12]; const float* lob = (const float*)d_in[13];
    const float* giw = (const float*)d_in[14]; const float* gib = (const float*)d_in[15];
    const float* gow = (const float*)d_in[16]; const float* gob = (const float*)d_in[17];
    const float* ciw = (const float*)d_in[18]; const float* cib = (const float*)d_in[19];
    const float* cow = (const float*)d_in[20]; const float* cob = (const float*)d_in[21];
    const float* ln1g = (const float*)d_in[22]; const float* ln1b = (const float*)d_in[23];
    const float* w1 = (const float*)d_in[24];  const float* b1 = (const float*)d_in[25];
    const float* w2 = (const float*)d_in[26];  const float* b2 = (const float*)d_in[27];
    const float* ln2g = (const float*)d_in[28]; const float* ln2b = (const float*)d_in[29];
    const float* pw = (const float*)d_in[30];  const float* pb = (const float*)d_in[31];
    float* out = (float*)d_out;

    float *pM, *pE, *pT1, *pT2, *pSb, *pSl, *pSg, *pSs, *pP32;
    bf16 *pMb, *pEb, *pQK, *pQKx, *pQKloc, *pVt, *pVtx, *pS16, *pP16;
    bf16 *pO16, *pO16x, *pO16loc, *pSb16, *pSl16, *pSs16, *pF16, *pT2b, *pWb;
    cudaGetSymbolAddress((void**)&pM,   g_M);
    cudaGetSymbolAddress((void**)&pE,   g_E);
    cudaGetSymbolAddress((void**)&pT1,  g_T1);
    cudaGetSymbolAddress((void**)&pT2,  g_T2);
    cudaGetSymbolAddress((void**)&pSb,  g_Sbase);
    cudaGetSymbolAddress((void**)&pSl,  g_Slocal);
    cudaGetSymbolAddress((void**)&pSg,  g_Sglob);
    cudaGetSymbolAddress((void**)&pSs,  g_Ssum);
    cudaGetSymbolAddress((void**)&pP32, g_P32);
    cudaGetSymbolAddress((void**)&pMb,  g_Mb);
    cudaGetSymbolAddress((void**)&pEb,  g_Eb);
    cudaGetSymbolAddress((void**)&pQK,  g_QK);
    cudaGetSymbolAddress((void**)&pQKx, g_QKx);
    cudaGetSymbolAddress((void**)&pQKloc, g_QKloc);
    cudaGetSymbolAddress((void**)&pVt,  g_Vt);
    cudaGetSymbolAddress((void**)&pVtx, g_Vtx);
    cudaGetSymbolAddress((void**)&pS16, g_S16);
    cudaGetSymbolAddress((void**)&pP16, g_P16);
    cudaGetSymbolAddress((void**)&pO16, g_O16);
    cudaGetSymbolAddress((void**)&pO16x, g_O16x);
    cudaGetSymbolAddress((void**)&pO16loc, g_O16loc);
    cudaGetSymbolAddress((void**)&pSb16, g_Sb16);
    cudaGetSymbolAddress((void**)&pSl16, g_Sl16);
    cudaGetSymbolAddress((void**)&pSs16, g_Ss16);
    cudaGetSymbolAddress((void**)&pF16, g_F16);
    cudaGetSymbolAddress((void**)&pT2b, g_T2b);
    cudaGetSymbolAddress((void**)&pWb,  g_Wb);

    static cudaStream_t s1 = nullptr, s2 = nullptr;
    static cudaEvent_t evFork, evCvt, evEmb, evBQ, evLn, evLoc, evXpv;
    if (!s1) {
        cudaStreamCreateWithFlags(&s1, cudaStreamNonBlocking);
        cudaStreamCreateWithFlags(&s2, cudaStreamNonBlocking);
        cudaEventCreateWithFlags(&evFork, cudaEventDisableTiming);
        cudaEventCreateWithFlags(&evCvt, cudaEventDisableTiming);
        cudaEventCreateWithFlags(&evEmb, cudaEventDisableTiming);
        cudaEventCreateWithFlags(&evBQ, cudaEventDisableTiming);
        cudaEventCreateWithFlags(&evLn, cudaEventDisableTiming);
        cudaEventCreateWithFlags(&evLoc, cudaEventDisableTiming);
        cudaEventCreateWithFlags(&evXpv, cudaEventDisableTiming);
        cudaFuncSetAttribute(linear_bf16_kernel,
                             cudaFuncAttributeMaxDynamicSharedMemorySize, L2_SMEM_BYTES);
        cudaFuncSetAttribute(flash_bf16_kernel,
                             cudaFuncAttributeMaxDynamicSharedMemorySize, F_SMEM_BYTES);
    }

    WSrc ws;
    ws.p[0] = biw; ws.p[1] = biw + DD; ws.p[2] = biw + 2 * DD;
    ws.p[3] = liw; ws.p[4] = liw + DD; ws.p[5] = liw + 2 * DD;
    ws.p[6] = giw; ws.p[7] = giw + DD; ws.p[8] = giw + 2 * DD;
    ws.p[9] = ciw; ws.p[10] = ciw + DD; ws.p[11] = ciw + 2 * DD;
    ws.p[12] = bow; ws.p[13] = low; ws.p[14] = gow; ws.p[15] = cow;
    ws.p[16] = w1; ws.p[17] = w2;

    const int BIG = 1 << 30;
    auto lin = [&](cudaStream_t st, const bf16* A, const bf16* W, const float* bias,
                   float* C32, bf16* C16, int ldc16, int coloff, int vcol0, bf16* Vt,
                   const float* r1, const float* r2, const float* r3,
                   int Mrows, int Nout, int relu) {
        dim3 gdim(Nout / 128, Mrows / 128);
        linear_bf16_kernel<<<gdim, 256, L2_SMEM_BYTES, st>>>(A, W, bias, C32, C16, ldc16,
                                                             coloff, vcol0, Vt,
                                                             r1, r2, r3, Nout, relu);
    };

    // ---- fork ----
    cudaEventRecord(evFork, 0);
    cudaStreamWaitEvent(s1, evFork, 0);

    // s1: weight conversion    |  s0: embeddings
    cvt_weights_kernel<<<4608, 256, 0, s1>>>(ws);
    cudaEventRecord(evCvt, s1);
    embed_kernel<<<BN_ROWS, 128>>>(q, r, qry, M_emb, E_emb, Pmat);
    cudaEventRecord(evEmb, 0);

    // s1: base Q projection
    cudaStreamWaitEvent(s1, evEmb, 0);
    lin(s1, pEb, pWb + 0 * DD, bib, nullptr, pQK, 1024, 0, BIG, pVt,
        nullptr, nullptr, nullptr, BN_ROWS, 512, 0);
    cudaEventRecord(evBQ, s1);

    // s0: base K + Vt
    cudaStreamWaitEvent(0, evCvt, 0);
    lin(0, pMb, pWb + 1 * DD, bib + D, nullptr, pQK, 1024, 512, 512, pVt,
        nullptr, nullptr, nullptr, BN_ROWS, 1024, 0);
    cudaStreamWaitEvent(0, evBQ, 0);

    // s0: base attention (probs materialized for attn_w) + out-proj + LN1
    scores_bf16_kernel<<<dim3(4, 4, 128), 256>>>(pQK, pS16, 1);
    softmax_base_warp<<<BN_ROWS, 256>>>(pS16, pP16, out + BN_ROWS);
    pv_bf16_kernel<<<dim3(1, 4, 128), 256>>>(pP16, pVt, pO16, 1);
    lin(0, pO16, pWb + 12 * DD, bob, pT1, nullptr, 0, 0, BIG, pVt,
        nullptr, nullptr, nullptr, BN_ROWS, 512, 0);
    ln_kernel<<<BN_ROWS, 128>>>(pT1, pM, pE, ln1g, ln1b, pSb, pSb16, pT2b);
    cudaEventRecord(evLn, 0);

    // s1: local MHA path (hidden under global path)
    cudaStreamWaitEvent(s1, evLn, 0);
    lin(s1, pT2b, pWb + 3 * DD, lib, nullptr, pQKloc, 1536, 0, BIG, pVt,
        nullptr, nullptr, nullptr, BLW_ROWS, 1536, 0);
    local_scores_kernel<<<dim3(1, 1, 128), 256, 0, s1>>>(pQKloc, pP32);
    softmax_f32_kernel<<<B * H * LW, 128, 0, s1>>>(pP32, LW, LW, 1);
    local_pv_kernel<<<dim3(1, 1, 128), 256, 0, s1>>>(pP32, pQKloc, pO16loc);
    lin(s1, pO16loc, pWb + 13 * DD, lob, pT1, nullptr, 0, 0, BIG, pVt,
        nullptr, nullptr, nullptr, BLW_ROWS, 512, 0);
    expand_local_kernel<<<(BN_ROWS * D) / 256, 256, 0, s1>>>(pT1);
    cudaEventRecord(evLoc, s1);

    // s2: cross-attention chain (private buffers, flash), ∥ with global on s0
    cudaStreamWaitEvent(s2, evLn, 0);
    lin(s2, pSb16, pWb + 9 * DD, cib, nullptr, pQKx, 1024, 0, BIG, pVtx,
        nullptr, nullptr, nullptr, BN_ROWS, 512, 0);
    cudaStreamWaitEvent(s2, evLoc, 0);
    lin(s2, pSl16, pWb + 10 * DD, cib + D, nullptr, pQKx, 1024, 512, 512, pVtx,
        nullptr, nullptr, nullptr, BN_ROWS, 1024, 0);
    flash_bf16_kernel<<<dim3(1, 4, 128), 256, F_SMEM_BYTES, s2>>>(pQKx, pVtx, pO16x, 0);
    cudaEventRecord(evXpv, s2);

    // s0: global MHA (fused QKV + flash attention)
    lin(0, pSb16, pWb + 6 * DD, gib, nullptr, pQK, 1024, 0, 1024, pVt,
        nullptr, nullptr, nullptr, BN_ROWS, 1536, 0);
    flash_bf16_kernel<<<dim3(1, 4, 128), 256, F_SMEM_BYTES, 0>>>(pQK, pVt, pO16, 1);
    lin(0, pO16, pWb + 14 * DD, gob, pSg, nullptr, 0, 0, BIG, pVt,
        nullptr, nullptr, nullptr, BN_ROWS, 512, 0);

    // s0: join cross PV, then cross out-proj with fused 4-way sum
    cudaStreamWaitEvent(0, evXpv, 0);
    lin(0, pO16x, pWb + 15 * DD, cob, pSs, pSs16, 512, 0, BIG, pVt,
        pSb, pSl, pSg, BN_ROWS, 512, 0);

    // s0: FFN + LN2 + head
    lin(0, pSs16, pWb + 16 * DD, b1, nullptr, pF16, 512, 0, BIG, pVt,
        nullptr, nullptr, nullptr, BN_ROWS, 512, 1);
    lin(0, pF16, pWb + 17 * DD, b2, pT2, nullptr, 0, 0, BIG, pVt,
        nullptr, nullptr, nullptr, BN_ROWS, 512, 0);
    ln_kernel<<<BN_ROWS, 128>>>(pT2, pSs, nullptr, ln2g, ln2b, pT1, nullptr, nullptr);
    pred_kernel<<<BN_ROWS, 128>>>(pT1, pw, pb, out);
}

// round 17
// speedup vs baseline: 1.6372x; 1.0210x over previous
#include <cuda_runtime.h>
#include <cuda_bf16.h>
#include <math.h>
#include <stdint.h>

// ---------------------------------------------------------------------------
// Problem constants
// ---------------------------------------------------------------------------
static constexpr int B  = 16;
static constexpr int N  = 512;
static constexpr int D  = 512;
static constexpr int H  = 8;
static constexpr int HD = 64;
static constexpr int LW = 64;
static constexpr int NQ = 10000;
static constexpr int BN_ROWS  = B * N;    // 8192
static constexpr int BLW_ROWS = B * LW;   // 1024
static constexpr int DD = D * D;          // 262144 = 2^18

typedef __nv_bfloat16 bf16;
typedef __nv_bfloat162 bf162;

// ---------------------------------------------------------------------------
// Scratch (static device globals)
// ---------------------------------------------------------------------------
__device__ float g_M     [BN_ROWS * D];
__device__ float g_E     [BN_ROWS * D];
__device__ float g_T1    [BN_ROWS * D];
__device__ float g_T2    [BN_ROWS * D];
__device__ float g_Sbase [BN_ROWS * D];
__device__ float g_Slocal[BN_ROWS * D];
__device__ float g_Sglob [BN_ROWS * D];
__device__ float g_Ssum  [BN_ROWS * D];
__device__ float g_P32   [B * H * LW * LW];    // local probs scratch (f32)
__device__ bf16 g_Mb    [BN_ROWS * D];
__device__ bf16 g_Eb    [BN_ROWS * D];
__device__ bf16 g_QK    [BN_ROWS * 1024];      // base/glob packed Q|K
__device__ bf16 g_QKx   [BN_ROWS * 1024];      // cross packed Q|K
__device__ bf16 g_QKloc [BLW_ROWS * 1536];     // local packed QKV
__device__ bf16 g_Vt    [B * H * HD * N];      // V^T per (b,h) (base/glob)
__device__ bf16 g_Vtx   [B * H * HD * N];      // V^T per (b,h) (cross)
__device__ bf16 g_S16   [B * H * N * N];       // scores (base, for attn_w)
__device__ bf16 g_O16   [BN_ROWS * D];         // attn out (base/glob)
__device__ bf16 g_O16x  [BN_ROWS * D];         // attn out (cross)
__device__ bf16 g_O16loc[BLW_ROWS * D];
__device__ bf16 g_Sb16  [BN_ROWS * D];
__device__ bf16 g_Sl16  [BN_ROWS * D];
__device__ bf16 g_Ss16  [BN_ROWS * D];
__device__ bf16 g_F16   [BN_ROWS * D];
__device__ bf16 g_T2b   [BLW_ROWS * D];
__device__ bf16 g_Wb    [18 * DD];             // bf16 weights

// ---------------------------------------------------------------------------
// MMA / ldmatrix helpers
// ---------------------------------------------------------------------------
__device__ __forceinline__ void cp_async16(uint32_t dst, const void* src) {
    asm volatile("cp.async.cg.shared.global [%0], [%1], 16;" :: "r"(dst), "l"(src));
}
__device__ __forceinline__ void cp_commit() {
    asm volatile("cp.async.commit_group;");
}
__device__ __forceinline__ void mma_bf16(float c[4], uint32_t a0, uint32_t a1,
                                         uint32_t a2, uint32_t a3,
                                         uint32_t b0, uint32_t b1) {
    asm volatile(
        "mma.sync.aligned.m16n8k16.row.col.f32.bf16.bf16.f32 "
        "{%0,%1,%2,%3}, {%4,%5,%6,%7}, {%8,%9}, {%0,%1,%2,%3};"
        : "+f"(c[0]), "+f"(c[1]), "+f"(c[2]), "+f"(c[3])
        : "r"(a0), "r"(a1), "r"(a2), "r"(a3), "r"(b0), "r"(b1));
}
__device__ __forceinline__ void ldsm_x4(uint32_t& r0, uint32_t& r1,
                                        uint32_t& r2, uint32_t& r3, uint32_t addr) {
    asm volatile("ldmatrix.sync.aligned.m8n8.x4.shared.b16 {%0,%1,%2,%3}, [%4];"
                 : "=r"(r0), "=r"(r1), "=r"(r2), "=r"(r3) : "r"(addr));
}

static constexpr int L2STR = 36;
static constexpr int L2_STAGE_U32 = 256 * L2STR;
static constexpr int L2_SMEM_BYTES = 3 * L2_STAGE_U32 * 4;   // 110592

// flash smem geometry
static constexpr int FQ_STR = 36;                 // u32 per 64-bf16 row
static constexpr int FV_STR = 68;                 // u32 per 128-bf16 row
static constexpr int F_Q_U32 = 128 * FQ_STR;      // 4608
static constexpr int F_K_U32 = 128 * FQ_STR;      // 4608 per buffer
static constexpr int F_V_U32 = 64 * FV_STR;       // 4352 per buffer
static constexpr int F_SMEM_BYTES = (F_Q_U32 + 2 * F_K_U32 + 2 * F_V_U32) * 4; // 90112

// ---------------------------------------------------------------------------
// Weight conversion
// ---------------------------------------------------------------------------
struct WSrc { const float* p[18]; };
__global__ void cvt_weights_kernel(WSrc ws) {
    for (int i = blockIdx.x * blockDim.x + threadIdx.x; i < 18 * DD;
         i += gridDim.x * blockDim.x) {
        int s = i >> 18;
        int off = i & (DD - 1);
        g_Wb[i] = __float2bfloat16(ws.p[s][off]);
    }
}

// ---------------------------------------------------------------------------
// Embedding gather
// ---------------------------------------------------------------------------
__global__ void embed_kernel(const int* __restrict__ q, const int* __restrict__ r,
                             const int* __restrict__ qry,
                             const float* __restrict__ M_emb,
                             const float* __restrict__ E_emb,
                             const float* __restrict__ P) {
    int row = blockIdx.x;
    int n = row & (N - 1);
    int x = q[row] + NQ * r[row];
    int e = qry[row];
    const float* msrc = M_emb + (size_t)x * D;
    const float* esrc = E_emb + (size_t)e * D;
    const float* psrc = P + (size_t)n * D;
    size_t base = (size_t)row * D;
    for (int d = threadIdx.x; d < D; d += blockDim.x) {
        float mv = msrc[d] + psrc[d];
        float ev = esrc[d];
        g_M[base + d] = mv;  g_Mb[base + d] = __float2bfloat16(mv);
        g_E[base + d] = ev;  g_Eb[base + d] = __float2bfloat16(ev);
    }
}

// ---------------------------------------------------------------------------
// BF16 tensor-core GEMM: ldmatrix fragments, BK=64, 3-stage pipeline.
// ---------------------------------------------------------------------------
__global__ __launch_bounds__(256, 2)
void linear_bf16_kernel(const bf16* __restrict__ A, const bf16* __restrict__ W,
                        const float* __restrict__ bias,
                        float* __restrict__ C32,
                        bf16* __restrict__ C16, int ldc16, int coloff,
                        int vcol0, bf16* __restrict__ Vt,
                        const float* __restrict__ res1,
                        const float* __restrict__ res2,
                        const float* __restrict__ res3,
                        int Nout, int relu) {
    extern __shared__ uint32_t sm[];
    const int tid  = threadIdx.x;
    const int lane = tid & 31;
    const int w    = tid >> 5;
    const int g    = lane >> 2;
    const int tg   = lane & 3;
    const int wm0  = (w >> 2) * 64;
    const int wn0  = (w & 3) * 32;
    const int m0   = blockIdx.y * 128;
    const int n0   = blockIdx.x * 128;
    const uint32_t sm_u32 = (uint32_t)__cvta_generic_to_shared(sm);

    const int qr = lane & 7, qm = (lane >> 3) & 1, qk = lane >> 4;
    const int q2 = lane >> 3, rB = lane & 7;
    uint32_t aoff[4], boff[2];
#pragma unroll
    for (int tm = 0; tm < 4; tm++)
        aoff[tm] = (uint32_t)(((wm0 + tm * 16 + qm * 8 + qr) * L2STR + qk * 4) * 4);
#pragma unroll
    for (int p = 0; p < 2; p++)
        boff[p] = (uint32_t)(((wn0 + (p * 2 + (q2 >> 1)) * 8 + rB) * L2STR + (q2 & 1) * 4) * 4);

    auto load_tile = [&](int t, int s) {
        const int k0 = t * 64;
        uint32_t base = sm_u32 + (uint32_t)(s * L2_STAGE_U32) * 4u;
#pragma unroll
        for (int i = 0; i < 4; i++) {
            int e = tid + i * 256;
            int row = e >> 3, ch = e & 7;
            cp_async16(base + (uint32_t)(row * L2STR + ch * 4) * 4u,
                       &A[(size_t)(m0 + row) * 512 + k0 + ch * 8]);
        }
        base += (uint32_t)(128 * L2STR) * 4u;
#pragma unroll
        for (int i = 0; i < 4; i++) {
            int e = tid + i * 256;
            int row = e >> 3, ch = e & 7;
            cp_async16(base + (uint32_t)(row * L2STR + ch * 4) * 4u,
                       &W[(size_t)(n0 + row) * 512 + k0 + ch * 8]);
        }
        cp_commit();
    };

    float acc[4][4][4] = {};
    const int NT = 8;
    load_tile(0, 0);
    load_tile(1, 1);
    for (int it = 0; it < NT; ++it) {
        if (it + 2 < NT) {
            load_tile(it + 2, (it + 2) % 3);
            asm volatile("cp.async.wait_group 2;");
        } else if (it + 1 < NT) {
            asm volatile("cp.async.wait_group 1;");
        } else {
            asm volatile("cp.async.wait_group 0;");
        }
        __syncthreads();
        const uint32_t baseA = sm_u32 + (uint32_t)((it % 3) * L2_STAGE_U32) * 4u;
        const uint32_t baseW = baseA + (uint32_t)(128 * L2STR) * 4u;
#pragma unroll
        for (int ks = 0; ks < 4; ks++) {
            const uint32_t kb = (uint32_t)(ks * 32);
            uint32_t a[4][4], bq[4][2];
#pragma unroll
            for (int tm = 0; tm < 4; tm++)
                ldsm_x4(a[tm][0], a[tm][1], a[tm][2], a[tm][3], baseA + aoff[tm] + kb);
#pragma unroll
            for (int p = 0; p < 2; p++)
                ldsm_x4(bq[p * 2][0], bq[p * 2][1], bq[p * 2 + 1][0], bq[p * 2 + 1][1],
                        baseW + boff[p] + kb);
#pragma unroll
            for (int tm = 0; tm < 4; tm++)
#pragma unroll
                for (int tn = 0; tn < 4; tn++)
                    mma_bf16(acc[tm][tn], a[tm][0], a[tm][1], a[tm][2], a[tm][3],
                             bq[tn][0], bq[tn][1]);
        }
        __syncthreads();
    }

#pragma unroll
    for (int tm = 0; tm < 4; tm++) {
        int r0 = m0 + wm0 + tm * 16 + g;
        int r1 = r0 + 8;
#pragma unroll
        for (int tn = 0; tn < 4; tn++) {
            int c = n0 + wn0 + tn * 8 + tg * 2;
            float b0 = bias[c], b1 = bias[c + 1];
            float v00 = acc[tm][tn][0] + b0;
            float v01 = acc[tm][tn][1] + b1;
            float v10 = acc[tm][tn][2] + b0;
            float v11 = acc[tm][tn][3] + b1;
            size_t o0 = (size_t)r0 * 512 + c;
            size_t o1 = (size_t)r1 * 512 + c;
            if (res1) { v00 += res1[o0]; v01 += res1[o0 + 1]; v10 += res1[o1]; v11 += res1[o1 + 1]; }
            if (res2) { v00 += res2[o0]; v01 += res2[o0 + 1]; v10 += res2[o1]; v11 += res2[o1 + 1]; }
            if (res3) { v00 += res3[o0]; v01 += res3[o0 + 1]; v10 += res3[o1]; v11 += res3[o1 + 1]; }
            if (relu) { v00 = fmaxf(v00, 0.f); v01 = fmaxf(v01, 0.f);
                        v10 = fmaxf(v10, 0.f); v11 = fmaxf(v11, 0.f); }
            if (C32) {
                *(float2*)&C32[o0] = make_float2(v00, v01);
                *(float2*)&C32[o1] = make_float2(v10, v11);
            }
            if (C16) {
                if (c >= vcol0) {
                    int ve = c - vcol0;
                    int h = ve >> 6, e0 = ve & 63;
                    int b_ = r0 >> 9;
                    int t0 = r0 & 511, t1 = r1 & 511;
                    bf16* vrow0 = Vt + ((size_t)((b_ * H + h) * HD + e0)) * N;
                    bf16* vrow1 = vrow0 + N;
                    vrow0[t0] = __float2bfloat16(v00);
                    vrow1[t0] = __float2bfloat16(v01);
                    vrow0[t1] = __float2bfloat16(v10);
                    vrow1[t1] = __float2bfloat16(v11);
                } else {
                    *(bf162*)&C16[(size_t)r0 * ldc16 + coloff + c] =
                        __floats2bfloat162_rn(v00, v01);
                    *(bf162*)&C16[(size_t)r1 * ldc16 + coloff + c] =
                        __floats2bfloat162_rn(v10, v11);
                }
            }
        }
    }
}

// ---------------------------------------------------------------------------
// Flash attention (fused scores+softmax+PV), HD=64, warp-per-16-rows.
// Q/K packed in QK (ld 1024, Q col 0, K col 512); V transposed in Vt.
// Optional S16out: raw scaled scores written as byproduct (for base attn_w).
// grid (1, N/128, B*H), 256 threads.
// ---------------------------------------------------------------------------
__global__ __launch_bounds__(256, 1)
void flash_bf16_kernel(const bf16* __restrict__ QK, const bf16* __restrict__ Vt,
                       bf16* __restrict__ O16, bf16* __restrict__ S16out,
                       int causal) {
    extern __shared__ uint32_t sm[];
    const int z = blockIdx.z, b = z >> 3, h = z & 7;
    const int i0 = blockIdx.y * 128;
    const bf16* Qb  = QK + (size_t)(b * N) * 1024 + h * HD;
    const bf16* Kb  = Qb + 512;
    const bf16* Vtz = Vt + (size_t)z * HD * N;
    bf16* Ob = O16 + (size_t)(b * N) * 512 + h * HD;
    bf16* Sb = S16out ? S16out + (size_t)z * N * N : nullptr;

    const int tid = threadIdx.x;
    const int lane = tid & 31;
    const int w = tid >> 5;
    const int g = lane >> 2, tg = lane & 3;
    const int row_base = w * 16;

    const uint32_t sm_u32 = (uint32_t)__cvta_generic_to_shared(sm);
    const uint32_t baseQ  = sm_u32;
    const uint32_t baseK0 = baseQ + (uint32_t)F_Q_U32 * 4u;
    const uint32_t baseV0 = baseK0 + (uint32_t)(2 * F_K_U32) * 4u;

    const int qr = lane & 7, qm = (lane >> 3) & 1, qk = lane >> 4;
    const uint32_t aoffQ = (uint32_t)(((row_base + qm * 8 + qr) * FQ_STR + qk * 4) * 4);
    const int q2 = lane >> 3, rB = lane & 7;
    uint32_t boffK[8], boffV[4];
#pragma unroll
    for (int p = 0; p < 8; p++)
        boffK[p] = (uint32_t)((((p * 2 + (q2 >> 1)) * 8 + rB) * FQ_STR + (q2 & 1) * 4) * 4);
#pragma unroll
    for (int p = 0; p < 4; p++)
        boffV[p] = (uint32_t)((((p * 2 + (q2 >> 1)) * 8 + rB) * FV_STR + (q2 & 1) * 4) * 4);

    // Q tile load (128 rows x 8 chunks)
#pragma unroll
    for (int i = 0; i < 4; i++) {
        int e = tid + i * 256;
        int row = e >> 3, ch = e & 7;
        cp_async16(baseQ + (uint32_t)(row * FQ_STR + ch * 4) * 4u,
                   &Qb[(size_t)(i0 + row) * 1024 + ch * 8]);
    }
    auto load_kv = [&](int jt, int s) {
        const int j0 = jt * 128;
        uint32_t bK = baseK0 + (uint32_t)(s * F_K_U32) * 4u;
        uint32_t bV = baseV0 + (uint32_t)(s * F_V_U32) * 4u;
#pragma unroll
        for (int i = 0; i < 4; i++) {
            int e = tid + i * 256;
            int row = e >> 3, ch = e & 7;
            cp_async16(bK + (uint32_t)(row * FQ_STR + ch * 4) * 4u,
                       &Kb[(size_t)(j0 + row) * 1024 + ch * 8]);
        }
#pragma unroll
        for (int i = 0; i < 4; i++) {
            int e = tid + i * 256;
            int row = e >> 4, ch = e & 15;      // 64 rows x 16 chunks
            cp_async16(bV + (uint32_t)(row * FV_STR + ch * 4) * 4u,
                       &Vtz[(size_t)row * N + j0 + ch * 8]);
        }
        cp_commit();
    };

    const int itile = i0 >> 7;
    const int ntiles = causal ? (itile + 1) : 4;
    load_kv(0, 0);    // commits group containing Q too

    float oacc[8][4] = {};
    float rmax0 = -1e30f, rmax1 = -1e30f;
    float rsum0 = 0.f, rsum1 = 0.f;
    const int r0 = i0 + row_base + g;
    const int r1 = r0 + 8;

    for (int jt = 0; jt < ntiles; ++jt) {
        if (jt + 1 < ntiles) { load_kv(jt + 1, (jt + 1) & 1);
                               asm volatile("cp.async.wait_group 1;"); }
        else                 { asm volatile("cp.async.wait_group 0;"); }
        __syncthreads();
        const uint32_t bK = baseK0 + (uint32_t)((jt & 1) * F_K_U32) * 4u;
        const uint32_t bV = baseV0 + (uint32_t)((jt & 1) * F_V_U32) * 4u;

        // S = Q K^T
        float sacc[16][4] = {};
#pragma unroll
        for (int ks = 0; ks < 4; ks++) {
            const uint32_t kb = (uint32_t)(ks * 32);
            uint32_t a0, a1, a2, a3;
            ldsm_x4(a0, a1, a2, a3, baseQ + aoffQ + kb);
            uint32_t bq[16][2];
#pragma unroll
            for (int p = 0; p < 8; p++)
                ldsm_x4(bq[p * 2][0], bq[p * 2][1], bq[p * 2 + 1][0], bq[p * 2 + 1][1],
                        bK + boffK[p] + kb);
#pragma unroll
            for (int tn = 0; tn < 16; tn++)
                mma_bf16(sacc[tn], a0, a1, a2, a3, bq[tn][0], bq[tn][1]);
        }
        const int j0 = jt * 128;
#pragma unroll
        for (int tn = 0; tn < 16; tn++) {
            sacc[tn][0] *= 0.125f; sacc[tn][1] *= 0.125f;
            sacc[tn][2] *= 0.125f; sacc[tn][3] *= 0.125f;
            if (causal && jt == itile) {
                int c0 = j0 + tn * 8 + tg * 2;
                if (c0 > r0)     sacc[tn][0] = -1e30f;
                if (c0 + 1 > r0) sacc[tn][1] = -1e30f;
                if (c0 > r1)     sacc[tn][2] = -1e30f;
                if (c0 + 1 > r1) sacc[tn][3] = -1e30f;
            }
        }
        // byproduct: write scaled (masked) score tiles for attn_w softmax
        if (Sb) {
#pragma unroll
            for (int tn = 0; tn < 16; tn++) {
                int c = j0 + tn * 8 + tg * 2;
                *(bf162*)&Sb[(size_t)r0 * N + c] =
                    __floats2bfloat162_rn(sacc[tn][0], sacc[tn][1]);
                *(bf162*)&Sb[(size_t)r1 * N + c] =
                    __floats2bfloat162_rn(sacc[tn][2], sacc[tn][3]);
            }
        }
        // tile row max (warp-local: 4 lanes per row)
        float tm0 = -1e30f, tm1 = -1e30f;
#pragma unroll
        for (int tn = 0; tn < 16; tn++) {
            tm0 = fmaxf(tm0, fmaxf(sacc[tn][0], sacc[tn][1]));
            tm1 = fmaxf(tm1, fmaxf(sacc[tn][2], sacc[tn][3]));
        }
        tm0 = fmaxf(tm0, __shfl_xor_sync(~0u, tm0, 1));
        tm0 = fmaxf(tm0, __shfl_xor_sync(~0u, tm0, 2));
        tm1 = fmaxf(tm1, __shfl_xor_sync(~0u, tm1, 1));
        tm1 = fmaxf(tm1, __shfl_xor_sync(~0u, tm1, 2));
        float nm0 = fmaxf(rmax0, tm0), nm1 = fmaxf(rmax1, tm1);
        float sc0 = __expf(rmax0 - nm0), sc1 = __expf(rmax1 - nm1);
        rmax0 = nm0; rmax1 = nm1;

        // exp, tile sum, pack P fragments
        uint32_t pf[16], pf2[16];
        float ts0 = 0.f, ts1 = 0.f;
#pragma unroll
        for (int tn = 0; tn < 16; tn++) {
            float e0 = __expf(sacc[tn][0] - nm0);
            float e1 = __expf(sacc[tn][1] - nm0);
            float e2 = __expf(sacc[tn][2] - nm1);
            float e3 = __expf(sacc[tn][3] - nm1);
            ts0 += e0 + e1; ts1 += e2 + e3;
            bf162 p01 = __floats2bfloat162_rn(e0, e1);
            bf162 p23 = __floats2bfloat162_rn(e2, e3);
            pf[tn]  = *(uint32_t*)&p01;
            pf2[tn] = *(uint32_t*)&p23;
        }
        ts0 += __shfl_xor_sync(~0u, ts0, 1);
        ts0 += __shfl_xor_sync(~0u, ts0, 2);
        ts1 += __shfl_xor_sync(~0u, ts1, 1);
        ts1 += __shfl_xor_sync(~0u, ts1, 2);
        rsum0 = rsum0 * sc0 + ts0;
        rsum1 = rsum1 * sc1 + ts1;
        // rescale O
#pragma unroll
        for (int tn2 = 0; tn2 < 8; tn2++) {
            oacc[tn2][0] *= sc0; oacc[tn2][1] *= sc0;
            oacc[tn2][2] *= sc1; oacc[tn2][3] *= sc1;
        }
        // PV: P (C-frag reinterpreted as A-frag) x V
#pragma unroll
        for (int ks2 = 0; ks2 < 8; ks2++) {
            const uint32_t kb = (uint32_t)(ks2 * 32);
            uint32_t bv[8][2];
#pragma unroll
            for (int p = 0; p < 4; p++)
                ldsm_x4(bv[p * 2][0], bv[p * 2][1], bv[p * 2 + 1][0], bv[p * 2 + 1][1],
                        bV + boffV[p] + kb);
#pragma unroll
            for (int tn2 = 0; tn2 < 8; tn2++)
                mma_bf16(oacc[tn2], pf[2 * ks2], pf2[2 * ks2],
                         pf[2 * ks2 + 1], pf2[2 * ks2 + 1],
                         bv[tn2][0], bv[tn2][1]);
        }
        __syncthreads();
    }

    float inv0 = 1.f / rsum0, inv1 = 1.f / rsum1;
#pragma unroll
    for (int tn2 = 0; tn2 < 8; tn2++) {
        int c = tn2 * 8 + tg * 2;
        *(bf162*)&Ob[(size_t)r0 * 512 + c] =
            __floats2bfloat162_rn(oacc[tn2][0] * inv0, oacc[tn2][1] * inv0);
        *(bf162*)&Ob[(size_t)r1 * 512 + c] =
            __floats2bfloat162_rn(oacc[tn2][2] * inv1, oacc[tn2][3] * inv1);
    }
}

// ---------------------------------------------------------------------------
// Base attn_w reduction: softmax over S16 rows per head, mean across heads.
// One block per (b,i), warp per head. Writes ONLY attn_w (off critical path).
// ---------------------------------------------------------------------------
__global__ void softmax_base_warp(const bf16* __restrict__ S16,
                                  float* __restrict__ outw) {
    int row = blockIdx.x;
    int b = row >> 9, i = row & (N - 1);
    int wid = threadIdx.x >> 5, lane = threadIdx.x & 31;
    int lim = i + 1;
    __shared__ float pm[8][512];
    size_t off = ((size_t)((b * H + wid) * N) + i) * N;
    const bf16* Sr = S16 + off;
    float v[16];
    float mx = -1e30f;
#pragma unroll
    for (int c = 0; c < 16; c++) {
        int j = lane + c * 32;
        v[c] = (j < lim) ? __bfloat162float(Sr[j]) : -1e30f;
        mx = fmaxf(mx, v[c]);
    }
#pragma unroll
    for (int s = 16; s > 0; s >>= 1) mx = fmaxf(mx, __shfl_xor_sync(~0u, mx, s));
    float sum = 0.f;
#pragma unroll
    for (int c = 0; c < 16; c++) {
        int j = lane + c * 32;
        float e = (j < lim) ? __expf(v[c] - mx) : 0.f;
        v[c] = e; sum += e;
    }
#pragma unroll
    for (int s = 16; s > 0; s >>= 1) sum += __shfl_xor_sync(~0u, sum, s);
    float inv = 1.f / sum;
#pragma unroll
    for (int c = 0; c < 16; c++) {
        int j = lane + c * 32;
        pm[wid][j] = v[c] * inv;
    }
    __syncthreads();
    size_t orow = (size_t)row * N;
    for (int t = threadIdx.x; t < N; t += 256) {
        float s = 0.f;
#pragma unroll
        for (int h = 0; h < H; h++) s += pm[h][t];
        outw[orow + t] = s * 0.125f;
    }
}

// f32 softmax (local path, Nk=64)
__global__ void softmax_f32_kernel(float* __restrict__ S, int Nq, int Nk, int causal) {
    int row = blockIdx.x;
    int i = row % Nq;
    float* Sr = S + (size_t)row * Nk;
    int lim = causal ? (i + 1) : Nk;
    int tid = threadIdx.x;
    float v[4];
    float mx = -1e30f;
#pragma unroll
    for (int c = 0; c < 4; c++) {
        int j = tid + c * 128;
        v[c] = (j < lim && j < Nk) ? Sr[j] : -1e30f;
        mx = fmaxf(mx, v[c]);
    }
    __shared__ float red[128];
    red[tid] = mx; __syncthreads();
    for (int s = 64; s > 0; s >>= 1) { if (tid < s) red[tid] = fmaxf(red[tid], red[tid + s]); __syncthreads(); }
    mx = red[0]; __syncthreads();
    float sum = 0.f;
#pragma unroll
    for (int c = 0; c < 4; c++) {
        int j = tid + c * 128;
        float e = (j < lim && j < Nk) ? __expf(v[c] - mx) : 0.f;
        v[c] = e; sum += e;
    }
    red[tid] = sum; __syncthreads();
    for (int s = 64; s > 0; s >>= 1) { if (tid < s) red[tid] += red[tid + s]; __syncthreads(); }
    float inv = 1.f / red[0];
#pragma unroll
    for (int c = 0; c < 4; c++) {
        int j = tid + c * 128;
        if (j < Nk) Sr[j] = v[c] * inv;
    }
}

// ---------------------------------------------------------------------------
// SIMT local attention (LW=64)
// ---------------------------------------------------------------------------
__global__ void local_scores_kernel(const bf16* __restrict__ QK, float* __restrict__ S) {
    int z = blockIdx.z, b = z >> 3, h = z & 7;
    const bf16* Qb = QK + (size_t)(b * LW) * 1536 + h * HD;
    const bf16* Kb = Qb + 512;
    float* Sb = S + (size_t)z * LW * LW;
    __shared__ float Qs[16][64];
    __shared__ float Ks[16][64];
    int tid = threadIdx.x, tx = tid & 15, ty = tid >> 4;
    float acc[4][4] = {};
    for (int k0 = 0; k0 < HD; k0 += 16) {
        for (int idx = tid; idx < 64 * 16; idx += 256) {
            int i = idx >> 4, j = idx & 15;
            Qs[j][i] = __bfloat162float(Qb[(size_t)i * 1536 + k0 + j]);
            Ks[j][i] = __bfloat162float(Kb[(size_t)i * 1536 + k0 + j]);
        }
        __syncthreads();
#pragma unroll
        for (int k = 0; k < 16; k++) {
            float a[4], wv[4];
#pragma unroll
            for (int i = 0; i < 4; i++) a[i] = Qs[k][ty * 4 + i];
#pragma unroll
            for (int j = 0; j < 4; j++) wv[j] = Ks[k][tx * 4 + j];
#pragma unroll
            for (int i = 0; i < 4; i++)
#pragma unroll
                for (int j = 0; j < 4; j++) acc[i][j] += a[i] * wv[j];
        }
        __syncthreads();
    }
#pragma unroll
    for (int i = 0; i < 4; i++)
#pragma unroll
        for (int j = 0; j < 4; j++)
            Sb[(size_t)(ty * 4 + i) * LW + tx * 4 + j] = acc[i][j] * 0.125f;
}

__global__ void local_pv_kernel(const float* __restrict__ Pm, const bf16* __restrict__ QK,
                                bf16* __restrict__ O16) {
    int z = blockIdx.z, b = z >> 3, h = z & 7;
    const float* Pb = Pm + (size_t)z * LW * LW;
    const bf16* Vb = QK + (size_t)(b * LW) * 1536 + 1024 + h * HD;
    bf16* Ob = O16 + (size_t)(b * LW) * 512 + h * HD;
    __shared__ float Ps[64][17];
    __shared__ float Vs[16][64];
    int tid = threadIdx.x, tx = tid & 15, ty = tid >> 4;
    float acc[4][4] = {};
    for (int k0 = 0; k0 < LW; k0 += 16) {
        for (int idx = tid; idx < 64 * 16; idx += 256) {
            int i = idx >> 4, j = idx & 15;
            Ps[i][j] = Pb[(size_t)i * LW + k0 + j];
        }
        for (int idx = tid; idx < 16 * 64; idx += 256) {
            int k = idx >> 6, e = idx & 63;
            Vs[k][e] = __bfloat162float(Vb[(size_t)(k0 + k) * 1536 + e]);
        }
        __syncthreads();
#pragma unroll
        for (int k = 0; k < 16; k++) {
            float a[4], wv[4];
#pragma unroll
            for (int i = 0; i < 4; i++) a[i] = Ps[ty * 4 + i][k];
#pragma unroll
            for (int j = 0; j < 4; j++) wv[j] = Vs[k][tx * 4 + j];
#pragma unroll
            for (int i = 0; i < 4; i++)
#pragma unroll
                for (int j = 0; j < 4; j++) acc[i][j] += a[i] * wv[j];
        }
        __syncthreads();
    }
#pragma unroll
    for (int i = 0; i < 4; i++)
#pragma unroll
        for (int j = 0; j < 4; j++)
            Ob[(size_t)(ty * 4 + i) * 512 + tx * 4 + j] = __float2bfloat16(acc[i][j]);
}

// ---------------------------------------------------------------------------
// LayerNorm: out = LN(X + r1? + r2?) * g + b ; optional bf16 out + packed copy
// ---------------------------------------------------------------------------
__global__ void ln_kernel(const float* __restrict__ X, const float* __restrict__ r1,
                          const float* __restrict__ r2, const float* __restrict__ g,
                          const float* __restrict__ bvec, float* __restrict__ out,
                          bf16* __restrict__ out16, bf16* __restrict__ pack16) {
    int row = blockIdx.x;
    size_t base = (size_t)row * D;
    int tid = threadIdx.x;
    int n = row & (N - 1);
    int b = row >> 9;
    float v[4];
    float s = 0.f;
#pragma unroll
    for (int c = 0; c < 4; c++) {
        int d = tid + c * 128;
        float t = X[base + d];
        if (r1) t += r1[base + d];
        if (r2) t += r2[base + d];
        v[c] = t; s += t;
    }
    __shared__ float red[128];
    red[tid] = s; __syncthreads();
    for (int st = 64; st > 0; st >>= 1) { if (tid < st) red[tid] += red[tid + st]; __syncthreads(); }
    float mean = red[0] * (1.f / D);
    __syncthreads();
    float vs = 0.f;
#pragma unroll
    for (int c = 0; c < 4; c++) { float dl = v[c] - mean; vs += dl * dl; }
    red[tid] = vs; __syncthreads();
    for (int st = 64; st > 0; st >>= 1) { if (tid < st) red[tid] += red[tid + st]; __syncthreads(); }
    float inv = rsqrtf(red[0] * (1.f / D) + 1e-5f);
    bf16* prow = (pack16 && n >= N - LW)
               ? pack16 + ((size_t)(b * LW + (n - (N - LW)))) * D : nullptr;
#pragma unroll
    for (int c = 0; c < 4; c++) {
        int d = tid + c * 128;
        float o = (v[c] - mean) * inv * g[d] + bvec[d];
        out[base + d] = o;
        bf16 ob = __float2bfloat16(o);
        if (out16) out16[base + d] = ob;
        if (prow) prow[d] = ob;
    }
}

// ---------------------------------------------------------------------------
// Misc elementwise kernels
// ---------------------------------------------------------------------------
__global__ void expand_local_kernel(const float* __restrict__ packed) {
    size_t idx = (size_t)blockIdx.x * blockDim.x + threadIdx.x;
    int d = (int)(idx & (D - 1));
    int row = (int)(idx >> 9);
    int b = row >> 9;
    int n = row & (N - 1);
    float v = 0.f;
    if (n >= N - LW)
        v = packed[(((size_t)b * LW + (n - (N - LW))) << 9) + d];
    g_Slocal[idx] = v;
    g_Sl16[idx] = __float2bfloat16(v);
}

__global__ void pred_kernel(const float* __restrict__ F, const float* __restrict__ pw,
                            const float* __restrict__ pb, float* __restrict__ out) {
    int row = blockIdx.x;
    int tid = threadIdx.x;
    const float* x = F + (size_t)row * D;
    float s = 0.f;
    for (int d = tid; d < D; d += 128) s += x[d] * pw[d];
    __shared__ float red[128];
    red[tid] = s; __syncthreads();
    for (int st = 64; st > 0; st >>= 1) { if (tid < st) red[tid] += red[tid + st]; __syncthreads(); }
    if (tid == 0) out[row] = 1.f / (1.f + __expf(-(red[0] + pb[0])));
}

// ---------------------------------------------------------------------------
// Launch
// ---------------------------------------------------------------------------
extern "C" void kernel_launch(void* const* d_in, const int* in_sizes, int n_in,
                              void* d_out, int out_size) {
    (void)in_sizes; (void)n_in; (void)out_size;
    const int*   q     = (const int*)d_in[0];
    const int*   r     = (const int*)d_in[1];
    const int*   qry   = (const int*)d_in[2];
    const float* M_emb = (const float*)d_in[3];
    const float* E_emb = (const float*)d_in[4];
    const float* Pmat  = (const float*)d_in[5];
    const float* biw = (const float*)d_in[6];  const float* bib = (const float*)d_in[7];
    const float* bow = (const float*)d_in[8];  const float* bob = (const float*)d_in[9];
    const float* liw = (const float*)d_in[10]; const float* lib = (const float*)d_in[11];
    const float* low = (const float*)d_in[12]; const float* lob = (const float*)d_in[13];
    const float* giw = (const float*)d_in[14]; const float* gib = (const float*)d_in[15];
    const float* gow = (const float*)d_in[16]; const float* gob = (const float*)d_in[17];
    const float* ciw = (const float*)d_in[18]; const float* cib = (const float*)d_in[19];
    const float* cow = (const float*)d_in[20]; const float* cob = (const float*)d_in[21];
    const float* ln1g = (const float*)d_in[22]; const float* ln1b = (const float*)d_in[23];
    const float* w1 = (const float*)d_in[24];  const float* b1 = (const float*)d_in[25];
    const float* w2 = (const float*)d_in[26];  const float* b2 = (const float*)d_in[27];
    const float* ln2g = (const float*)d_in[28]; const float* ln2b = (const float*)d_in[29];
    const float* pw = (const float*)d_in[30];  const float* pb = (const float*)d_in[31];
    float* out = (float*)d_out;

    float *pM, *pE, *pT1, *pT2, *pSb, *pSl, *pSg, *pSs, *pP32;
    bf16 *pMb, *pEb, *pQK, *pQKx, *pQKloc, *pVt, *pVtx, *pS16;
    bf16 *pO16, *pO16x, *pO16loc, *pSb16, *pSl16, *pSs16, *pF16, *pT2b, *pWb;
    cudaGetSymbolAddress((void**)&pM,   g_M);
    cudaGetSymbolAddress((void**)&pE,   g_E);
    cudaGetSymbolAddress((void**)&pT1,  g_T1);
    cudaGetSymbolAddress((void**)&pT2,  g_T2);
    cudaGetSymbolAddress((void**)&pSb,  g_Sbase);
    cudaGetSymbolAddress((void**)&pSl,  g_Slocal);
    cudaGetSymbolAddress((void**)&pSg,  g_Sglob);
    cudaGetSymbolAddress((void**)&pSs,  g_Ssum);
    cudaGetSymbolAddress((void**)&pP32, g_P32);
    cudaGetSymbolAddress((void**)&pMb,  g_Mb);
    cudaGetSymbolAddress((void**)&pEb,  g_Eb);
    cudaGetSymbolAddress((void**)&pQK,  g_QK);
    cudaGetSymbolAddress((void**)&pQKx, g_QKx);
    cudaGetSymbolAddress((void**)&pQKloc, g_QKloc);
    cudaGetSymbolAddress((void**)&pVt,  g_Vt);
    cudaGetSymbolAddress((void**)&pVtx, g_Vtx);
    cudaGetSymbolAddress((void**)&pS16, g_S16);
    cudaGetSymbolAddress((void**)&pO16, g_O16);
    cudaGetSymbolAddress((void**)&pO16x, g_O16x);
    cudaGetSymbolAddress((void**)&pO16loc, g_O16loc);
    cudaGetSymbolAddress((void**)&pSb16, g_Sb16);
    cudaGetSymbolAddress((void**)&pSl16, g_Sl16);
    cudaGetSymbolAddress((void**)&pSs16, g_Ss16);
    cudaGetSymbolAddress((void**)&pF16, g_F16);
    cudaGetSymbolAddress((void**)&pT2b, g_T2b);
    cudaGetSymbolAddress((void**)&pWb,  g_Wb);

    static cudaStream_t s1 = nullptr, s2 = nullptr;
    static cudaEvent_t evFork, evCvt, evEmb, evBQ, evFB, evLn, evLoc, evXpv;
    if (!s1) {
        cudaStreamCreateWithFlags(&s1, cudaStreamNonBlocking);
        cudaStreamCreateWithFlags(&s2, cudaStreamNonBlocking);
        cudaEventCreateWithFlags(&evFork, cudaEventDisableTiming);
        cudaEventCreateWithFlags(&evCvt, cudaEventDisableTiming);
        cudaEventCreateWithFlags(&evEmb, cudaEventDisableTiming);
        cudaEventCreateWithFlags(&evBQ, cudaEventDisableTiming);
        cudaEventCreateWithFlags(&evFB, cudaEventDisableTiming);
        cudaEventCreateWithFlags(&evLn, cudaEventDisableTiming);
        cudaEventCreateWithFlags(&evLoc, cudaEventDisableTiming);
        cudaEventCreateWithFlags(&evXpv, cudaEventDisableTiming);
        cudaFuncSetAttribute(linear_bf16_kernel,
                             cudaFuncAttributeMaxDynamicSharedMemorySize, L2_SMEM_BYTES);
        cudaFuncSetAttribute(flash_bf16_kernel,
                             cudaFuncAttributeMaxDynamicSharedMemorySize, F_SMEM_BYTES);
    }

    WSrc ws;
    ws.p[0] = biw; ws.p[1] = biw + DD; ws.p[2] = biw + 2 * DD;
    ws.p[3] = liw; ws.p[4] = liw + DD; ws.p[5] = liw + 2 * DD;
    ws.p[6] = giw; ws.p[7] = giw + DD; ws.p[8] = giw + 2 * DD;
    ws.p[9] = ciw; ws.p[10] = ciw + DD; ws.p[11] = ciw + 2 * DD;
    ws.p[12] = bow; ws.p[13] = low; ws.p[14] = gow; ws.p[15] = cow;
    ws.p[16] = w1; ws.p[17] = w2;

    const int BIG = 1 << 30;
    auto lin = [&](cudaStream_t st, const bf16* A, const bf16* W, const float* bias,
                   float* C32, bf16* C16, int ldc16, int coloff, int vcol0, bf16* Vt,
                   const float* r1, const float* r2, const float* r3,
                   int Mrows, int Nout, int relu) {
        dim3 gdim(Nout / 128, Mrows / 128);
        linear_bf16_kernel<<<gdim, 256, L2_SMEM_BYTES, st>>>(A, W, bias, C32, C16, ldc16,
                                                             coloff, vcol0, Vt,
                                                             r1, r2, r3, Nout, relu);
    };

    // ---- fork ----
    cudaEventRecord(evFork, 0);
    cudaStreamWaitEvent(s1, evFork, 0);

    // s1: weight conversion    |  s0: embeddings
    cvt_weights_kernel<<<4608, 256, 0, s1>>>(ws);
    cudaEventRecord(evCvt, s1);
    embed_kernel<<<BN_ROWS, 128>>>(q, r, qry, M_emb, E_emb, Pmat);
    cudaEventRecord(evEmb, 0);

    // s1: base Q projection
    cudaStreamWaitEvent(s1, evEmb, 0);
    lin(s1, pEb, pWb + 0 * DD, bib, nullptr, pQK, 1024, 0, BIG, pVt,
        nullptr, nullptr, nullptr, BN_ROWS, 512, 0);
    cudaEventRecord(evBQ, s1);

    // s0: base K + Vt
    cudaStreamWaitEvent(0, evCvt, 0);
    lin(0, pMb, pWb + 1 * DD, bib + D, nullptr, pQK, 1024, 512, 512, pVt,
        nullptr, nullptr, nullptr, BN_ROWS, 1024, 0);
    cudaStreamWaitEvent(0, evBQ, 0);

    // s0: base flash attention (emits S16 for attn_w) + out-proj + LN1
    flash_bf16_kernel<<<dim3(1, 4, 128), 256, F_SMEM_BYTES, 0>>>(pQK, pVt, pO16, pS16, 1);
    cudaEventRecord(evFB, 0);
    lin(0, pO16, pWb + 12 * DD, bob, pT1, nullptr, 0, 0, BIG, pVt,
        nullptr, nullptr, nullptr, BN_ROWS, 512, 0);
    ln_kernel<<<BN_ROWS, 128>>>(pT1, pM, pE, ln1g, ln1b, pSb, pSb16, pT2b);
    cudaEventRecord(evLn, 0);

    // s2: attn_w head-mean softmax (off critical path, hidden under s0)
    cudaStreamWaitEvent(s2, evFB, 0);
    softmax_base_warp<<<BN_ROWS, 256, 0, s2>>>(pS16, out + BN_ROWS);

    // s1: local MHA path (hidden under global path)
    cudaStreamWaitEvent(s1, evLn, 0);
    lin(s1, pT2b, pWb + 3 * DD, lib, nullptr, pQKloc, 1536, 0, BIG, pVt,
        nullptr, nullptr, nullptr, BLW_ROWS, 1536, 0);
    local_scores_kernel<<<dim3(1, 1, 128), 256, 0, s1>>>(pQKloc, pP32);
    softmax_f32_kernel<<<B * H * LW, 128, 0, s1>>>(pP32, LW, LW, 1);
    local_pv_kernel<<<dim3(1, 1, 128), 256, 0, s1>>>(pP32, pQKloc, pO16loc);
    lin(s1, pO16loc, pWb + 13 * DD, lob, pT1, nullptr, 0, 0, BIG, pVt,
        nullptr, nullptr, nullptr, BLW_ROWS, 512, 0);
    expand_local_kernel<<<(BN_ROWS * D) / 256, 256, 0, s1>>>(pT1);
    cudaEventRecord(evLoc, s1);

    // s2: cross-attention chain (private buffers, flash), ∥ with global on s0
    cudaStreamWaitEvent(s2, evLn, 0);
    lin(s2, pSb16, pWb + 9 * DD, cib, nullptr, pQKx, 1024, 0, BIG, pVtx,
        nullptr, nullptr, nullptr, BN_ROWS, 512, 0);
    cudaStreamWaitEvent(s2, evLoc, 0);
    lin(s2, pSl16, pWb + 10 * DD, cib + D, nullptr, pQKx, 1024, 512, 512, pVtx,
        nullptr, nullptr, nullptr, BN_ROWS, 1024, 0);
    flash_bf16_kernel<<<dim3(1, 4, 128), 256, F_SMEM_BYTES, s2>>>(pQKx, pVtx, pO16x, nullptr, 0);
    cudaEventRecord(evXpv, s2);

    // s0: global MHA (fused QKV + flash attention)
    lin(0, pSb16, pWb + 6 * DD, gib, nullptr, pQK, 1024, 0, 1024, pVt,
        nullptr, nullptr, nullptr, BN_ROWS, 1536, 0);
    flash_bf16_kernel<<<dim3(1, 4, 128), 256, F_SMEM_BYTES, 0>>>(pQK, pVt, pO16, nullptr, 1);
    lin(0, pO16, pWb + 14 * DD, gob, pSg, nullptr, 0, 0, BIG, pVt,
        nullptr, nullptr, nullptr, BN_ROWS, 512, 0);

    // s0: join cross PV, then cross out-proj with fused 4-way sum
    cudaStreamWaitEvent(0, evXpv, 0);
    lin(0, pO16x, pWb + 15 * DD, cob, pSs, pSs16, 512, 0, BIG, pVt,
        pSb, pSl, pSg, BN_ROWS, 512, 0);

    // s0: FFN + LN2 + head
    lin(0, pSs16, pWb + 16 * DD, b1, nullptr, pF16, 512, 0, BIG, pVt,
        nullptr, nullptr, nullptr, BN_ROWS, 512, 1);
    lin(0, pF16, pWb + 17 * DD, b2, pT2, nullptr, 0, 0, BIG, pVt,
        nullptr, nullptr, nullptr, BN_ROWS, 512, 0);
    ln_kernel<<<BN_ROWS, 128>>>(pT2, pSs, nullptr, ln2g, ln2b, pT1, nullptr, nullptr);
    pred_kernel<<<BN_ROWS, 128>>>(pT1, pw, pb, out);
}